// round 1
// baseline (speedup 1.0000x reference)
#include <cuda_runtime.h>
#include <math.h>

#define EMB_DIM 448
#define FEAT_DIM 64
#define DMODEL 512
#define NBATCH 8
#define SEQ 2048
#define MTOT (NBATCH * SEQ)

// -------- scratch (device globals; no allocations allowed) --------
static __device__ float g_x[MTOT * DMODEL];      // 32 MB
static __device__ float g_q[MTOT * DMODEL];
static __device__ float g_k[MTOT * DMODEL];
static __device__ float g_v[MTOT * DMODEL];
static __device__ float g_h[MTOT * DMODEL];
static __device__ float g_t[MTOT * DMODEL];
static __device__ float g_sc[(size_t)NBATCH * SEQ * SEQ];  // 128 MB
static __device__ float g_mean[NBATCH * DMODEL];
static __device__ float g_rstd[NBATCH * DMODEL];
static __device__ float g_last[64 * DMODEL];     // padded last-row tile (rows 8..63 unused)
static __device__ float g_lt[64 * DMODEL];
static __device__ float g_lo[64 * DMODEL];

// -------- gather: x = concat(emb_table[ids], feats) --------
__global__ __launch_bounds__(256) void gather_kernel(const int* __restrict__ seq,
                                                     const float* __restrict__ feats,
                                                     const float* __restrict__ emb) {
    int i = blockIdx.x * 256 + threadIdx.x;           // over MTOT * (DMODEL/4)
    int row = i >> 7;                                  // DMODEL/4 = 128
    int d = (i & 127) << 2;
    float4 val;
    if (d < EMB_DIM) {
        int item = seq[row];
        val = *(const float4*)(emb + (size_t)item * EMB_DIM + d);
    } else {
        val = *(const float4*)(feats + (size_t)row * FEAT_DIM + (d - EMB_DIM));
    }
    *(float4*)(g_x + ((size_t)row << 9) + d) = val;
}

// -------- C[M,512] = A[M,512] @ W[512,512]^T + bias, optional ReLU --------
// 64x64 tile, 256 threads, 4x4 micro-tile, BK=16
template <bool RELU>
__global__ __launch_bounds__(256) void gemm_wt_kernel(const float* __restrict__ A,
                                                      const float* __restrict__ W,
                                                      const float* __restrict__ bias,
                                                      float* __restrict__ C) {
    __shared__ float As[16][64];
    __shared__ float Bs[16][64];
    const int bm = blockIdx.x, bn = blockIdx.y;
    const int tid = threadIdx.x;
    const int lrow = tid >> 2;
    const int lc = (tid & 3) << 2;
    const int tm = (tid >> 4) << 2;
    const int tn = (tid & 15) << 2;
    const float* Ap = A + (size_t)(bm * 64 + lrow) * DMODEL + lc;
    const float* Wp = W + (size_t)(bn * 64 + lrow) * DMODEL + lc;
    float acc[4][4] = {};
    for (int kt = 0; kt < DMODEL; kt += 16) {
        float4 a4 = *(const float4*)(Ap + kt);
        float4 w4 = *(const float4*)(Wp + kt);
        As[lc + 0][lrow] = a4.x; As[lc + 1][lrow] = a4.y;
        As[lc + 2][lrow] = a4.z; As[lc + 3][lrow] = a4.w;
        Bs[lc + 0][lrow] = w4.x; Bs[lc + 1][lrow] = w4.y;
        Bs[lc + 2][lrow] = w4.z; Bs[lc + 3][lrow] = w4.w;
        __syncthreads();
#pragma unroll
        for (int kk = 0; kk < 16; kk++) {
            float4 av = *(const float4*)&As[kk][tm];
            float4 bv = *(const float4*)&Bs[kk][tn];
            acc[0][0] += av.x * bv.x; acc[0][1] += av.x * bv.y; acc[0][2] += av.x * bv.z; acc[0][3] += av.x * bv.w;
            acc[1][0] += av.y * bv.x; acc[1][1] += av.y * bv.y; acc[1][2] += av.y * bv.z; acc[1][3] += av.y * bv.w;
            acc[2][0] += av.z * bv.x; acc[2][1] += av.z * bv.y; acc[2][2] += av.z * bv.z; acc[2][3] += av.z * bv.w;
            acc[3][0] += av.w * bv.x; acc[3][1] += av.w * bv.y; acc[3][2] += av.w * bv.z; acc[3][3] += av.w * bv.w;
        }
        __syncthreads();
    }
#pragma unroll
    for (int i = 0; i < 4; i++) {
        int m = bm * 64 + tm + i;
#pragma unroll
        for (int j = 0; j < 4; j++) {
            int n = bn * 64 + tn + j;
            float vv = acc[i][j] + bias[n];
            if (RELU) vv = fmaxf(vv, 0.0f);
            C[(size_t)m * DMODEL + n] = vv;
        }
    }
}

// -------- scores = tril(Q @ K^T) * scale  (per batch) --------
__global__ __launch_bounds__(256) void scores_kernel(const float* __restrict__ Q,
                                                     const float* __restrict__ K) {
    const int b = blockIdx.z;
    const int bm = blockIdx.x, bn = blockIdx.y;
    const int tid = threadIdx.x;
    const int tm = (tid >> 4) << 2;
    const int tn = (tid & 15) << 2;
    float* Sc = g_sc + (size_t)b * SEQ * SEQ;
    if (bn > bm) {  // fully masked tile: write zeros
#pragma unroll
        for (int i = 0; i < 4; i++)
#pragma unroll
            for (int j = 0; j < 4; j++)
                Sc[(size_t)(bm * 64 + tm + i) * SEQ + bn * 64 + tn + j] = 0.0f;
        return;
    }
    __shared__ float As[16][64];
    __shared__ float Bs[16][64];
    const int lrow = tid >> 2;
    const int lc = (tid & 3) << 2;
    const float* Qb = Q + (size_t)b * SEQ * DMODEL;
    const float* Kb = K + (size_t)b * SEQ * DMODEL;
    const float* Ap = Qb + (size_t)(bm * 64 + lrow) * DMODEL + lc;
    const float* Wp = Kb + (size_t)(bn * 64 + lrow) * DMODEL + lc;
    float acc[4][4] = {};
    for (int kt = 0; kt < DMODEL; kt += 16) {
        float4 a4 = *(const float4*)(Ap + kt);
        float4 w4 = *(const float4*)(Wp + kt);
        As[lc + 0][lrow] = a4.x; As[lc + 1][lrow] = a4.y;
        As[lc + 2][lrow] = a4.z; As[lc + 3][lrow] = a4.w;
        Bs[lc + 0][lrow] = w4.x; Bs[lc + 1][lrow] = w4.y;
        Bs[lc + 2][lrow] = w4.z; Bs[lc + 3][lrow] = w4.w;
        __syncthreads();
#pragma unroll
        for (int kk = 0; kk < 16; kk++) {
            float4 av = *(const float4*)&As[kk][tm];
            float4 bv = *(const float4*)&Bs[kk][tn];
            acc[0][0] += av.x * bv.x; acc[0][1] += av.x * bv.y; acc[0][2] += av.x * bv.z; acc[0][3] += av.x * bv.w;
            acc[1][0] += av.y * bv.x; acc[1][1] += av.y * bv.y; acc[1][2] += av.y * bv.z; acc[1][3] += av.y * bv.w;
            acc[2][0] += av.z * bv.x; acc[2][1] += av.z * bv.y; acc[2][2] += av.z * bv.z; acc[2][3] += av.z * bv.w;
            acc[3][0] += av.w * bv.x; acc[3][1] += av.w * bv.y; acc[3][2] += av.w * bv.z; acc[3][3] += av.w * bv.w;
        }
        __syncthreads();
    }
    const float scale = 0.044194173824159216f;  // 1/sqrt(512)
#pragma unroll
    for (int i = 0; i < 4; i++) {
        int m = bm * 64 + tm + i;
#pragma unroll
        for (int j = 0; j < 4; j++) {
            int n = bn * 64 + tn + j;
            Sc[(size_t)m * SEQ + n] = (n <= m) ? acc[i][j] * scale : 0.0f;
        }
    }
}

// -------- h = scores @ V  (per batch; K-loop bounded by causal diagonal) --------
__global__ __launch_bounds__(256) void gemm_av_kernel() {
    const int b = blockIdx.z;
    const float* A = g_sc + (size_t)b * SEQ * SEQ;
    const float* Bv = g_v + (size_t)b * SEQ * DMODEL;
    float* C = g_h + (size_t)b * SEQ * DMODEL;
    __shared__ float As[16][64];
    __shared__ float Bs[16][64];
    const int bm = blockIdx.x, bn = blockIdx.y;
    const int tid = threadIdx.x;
    const int lrow = tid >> 2;
    const int lc = (tid & 3) << 2;
    const int brow = tid >> 4;          // 0..15 (k within tile)
    const int bcol = (tid & 15) << 2;   // 0..60 (n within tile)
    const int tm = (tid >> 4) << 2;
    const int tn = (tid & 15) << 2;
    const float* Ap = A + (size_t)(bm * 64 + lrow) * SEQ + lc;
    float acc[4][4] = {};
    const int kmax = (bm + 1) * 64;  // scores zero beyond diagonal
    for (int kt = 0; kt < kmax; kt += 16) {
        float4 a4 = *(const float4*)(Ap + kt);
        As[lc + 0][lrow] = a4.x; As[lc + 1][lrow] = a4.y;
        As[lc + 2][lrow] = a4.z; As[lc + 3][lrow] = a4.w;
        *(float4*)&Bs[brow][bcol] =
            *(const float4*)(Bv + (size_t)(kt + brow) * DMODEL + bn * 64 + bcol);
        __syncthreads();
#pragma unroll
        for (int kk = 0; kk < 16; kk++) {
            float4 av = *(const float4*)&As[kk][tm];
            float4 bv = *(const float4*)&Bs[kk][tn];
            acc[0][0] += av.x * bv.x; acc[0][1] += av.x * bv.y; acc[0][2] += av.x * bv.z; acc[0][3] += av.x * bv.w;
            acc[1][0] += av.y * bv.x; acc[1][1] += av.y * bv.y; acc[1][2] += av.y * bv.z; acc[1][3] += av.y * bv.w;
            acc[2][0] += av.z * bv.x; acc[2][1] += av.z * bv.y; acc[2][2] += av.z * bv.z; acc[2][3] += av.z * bv.w;
            acc[3][0] += av.w * bv.x; acc[3][1] += av.w * bv.y; acc[3][2] += av.w * bv.z; acc[3][3] += av.w * bv.w;
        }
        __syncthreads();
    }
#pragma unroll
    for (int i = 0; i < 4; i++) {
        int m = bm * 64 + tm + i;
#pragma unroll
        for (int j = 0; j < 4; j++)
            C[(size_t)m * DMODEL + (bn * 64 + tn + j)] = acc[i][j];
    }
}

// -------- seq-norm stats over axis=1 (S), ddof=1; denom = std + 1e-5 + 1e-5 --------
__global__ void stats_kernel(const float* __restrict__ H) {
    const int b = blockIdx.x;
    const int d = blockIdx.y * 32 + threadIdx.x;
    const int ty = threadIdx.y;
    float sum = 0.f, sq = 0.f;
    for (int s = ty; s < SEQ; s += 8) {
        float v = H[(size_t)(b * SEQ + s) * DMODEL + d];
        sum += v; sq += v * v;
    }
    __shared__ float ss[8][32];
    __shared__ float s2[8][32];
    ss[ty][threadIdx.x] = sum;
    s2[ty][threadIdx.x] = sq;
    __syncthreads();
    if (ty == 0) {
#pragma unroll
        for (int r = 1; r < 8; r++) { sum += ss[r][threadIdx.x]; sq += s2[r][threadIdx.x]; }
        float mean = sum * (1.0f / SEQ);
        float var = (sq - sum * mean) * (1.0f / (SEQ - 1));
        var = fmaxf(var, 0.0f);
        g_mean[b * DMODEL + d] = mean;
        g_rstd[b * DMODEL + d] = 1.0f / (sqrtf(var) + 2e-5f);
    }
}

__global__ __launch_bounds__(256) void norm_kernel(float* __restrict__ H) {
    int i = blockIdx.x * 256 + threadIdx.x;  // over MTOT * 128
    int row = i >> 7;
    int c4 = (i & 127) << 2;
    int b = row >> 11;  // SEQ = 2048
    float4 v = *(float4*)(H + ((size_t)row << 9) + c4);
    float4 m = *(const float4*)(g_mean + b * DMODEL + c4);
    float4 r = *(const float4*)(g_rstd + b * DMODEL + c4);
    v.x = (v.x - m.x) * r.x; v.y = (v.y - m.y) * r.y;
    v.z = (v.z - m.z) * r.z; v.w = (v.w - m.w) * r.w;
    *(float4*)(H + ((size_t)row << 9) + c4) = v;
}

// -------- last-row extraction for block-2 MLP (positionwise ⇒ only last row needed) --------
__global__ void last_gather_kernel(const float* __restrict__ H) {
    int i = blockIdx.x * 256 + threadIdx.x;  // 4096
    int b = i >> 9, d = i & 511;
    g_last[i] = H[(size_t)(b * SEQ + SEQ - 1) * DMODEL + d];
}

__global__ void out_copy_kernel(float* __restrict__ out) {
    int i = blockIdx.x * 256 + threadIdx.x;  // 4096
    out[i] = g_lo[i];
}

extern "C" void kernel_launch(void* const* d_in, const int* in_sizes, int n_in,
                              void* d_out, int out_size) {
    const int* seq = (const int*)d_in[0];
    const float* feats = (const float*)d_in[1];
    const float* emb = (const float*)d_in[2];
    const float* Wq = (const float*)d_in[3];
    const float* bq = (const float*)d_in[4];
    const float* Wk = (const float*)d_in[5];
    const float* bk = (const float*)d_in[6];
    const float* Wv = (const float*)d_in[7];
    const float* bv = (const float*)d_in[8];
    const float* W1 = (const float*)d_in[9];
    const float* b1 = (const float*)d_in[10];
    const float* W2 = (const float*)d_in[11];
    const float* b2 = (const float*)d_in[12];
    float* out = (float*)d_out;

    void *px, *pq, *pk, *pv, *ph, *pt, *plast, *plt, *plo;
    cudaGetSymbolAddress(&px, g_x);
    cudaGetSymbolAddress(&pq, g_q);
    cudaGetSymbolAddress(&pk, g_k);
    cudaGetSymbolAddress(&pv, g_v);
    cudaGetSymbolAddress(&ph, g_h);
    cudaGetSymbolAddress(&pt, g_t);
    cudaGetSymbolAddress(&plast, g_last);
    cudaGetSymbolAddress(&plt, g_lt);
    cudaGetSymbolAddress(&plo, g_lo);
    float* x = (float*)px;  float* q = (float*)pq;  float* k = (float*)pk;
    float* v = (float*)pv;  float* h = (float*)ph;  float* t = (float*)pt;
    float* last = (float*)plast; float* lt = (float*)plt; float* lo = (float*)plo;

    gather_kernel<<<MTOT * 128 / 256, 256>>>(seq, feats, emb);

    const dim3 gemm_grid(MTOT / 64, DMODEL / 64);
    for (int l = 0; l < 2; l++) {
        const float* Wq_l = Wq + (size_t)l * DMODEL * DMODEL;
        const float* Wk_l = Wk + (size_t)l * DMODEL * DMODEL;
        const float* Wv_l = Wv + (size_t)l * DMODEL * DMODEL;
        const float* W1_l = W1 + (size_t)l * DMODEL * DMODEL;
        const float* W2_l = W2 + (size_t)l * DMODEL * DMODEL;
        const float* bq_l = bq + l * DMODEL;
        const float* bk_l = bk + l * DMODEL;
        const float* bv_l = bv + l * DMODEL;
        const float* b1_l = b1 + l * DMODEL;
        const float* b2_l = b2 + l * DMODEL;

        gemm_wt_kernel<false><<<gemm_grid, 256>>>(x, Wq_l, bq_l, q);
        gemm_wt_kernel<false><<<gemm_grid, 256>>>(x, Wk_l, bk_l, k);
        gemm_wt_kernel<false><<<gemm_grid, 256>>>(x, Wv_l, bv_l, v);

        scores_kernel<<<dim3(SEQ / 64, SEQ / 64, NBATCH), 256>>>(q, k);
        gemm_av_kernel<<<dim3(SEQ / 64, DMODEL / 64, NBATCH), 256>>>();

        stats_kernel<<<dim3(NBATCH, DMODEL / 32), dim3(32, 8)>>>(h);
        norm_kernel<<<MTOT * 128 / 256, 256>>>(h);

        if (l == 0) {
            gemm_wt_kernel<true><<<gemm_grid, 256>>>(h, W1_l, b1_l, t);
            gemm_wt_kernel<false><<<gemm_grid, 256>>>(t, W2_l, b2_l, x);
        } else {
            // output only needs the last position; MLP is positionwise
            last_gather_kernel<<<16, 256>>>(h);
            gemm_wt_kernel<true><<<dim3(1, DMODEL / 64), 256>>>(last, W1_l, b1_l, lt);
            gemm_wt_kernel<false><<<dim3(1, DMODEL / 64), 256>>>(lt, W2_l, b2_l, lo);
            out_copy_kernel<<<16, 256>>>(out);
        }
    }
}

// round 2
// speedup vs baseline: 1.0005x; 1.0005x over previous
#include <cuda_runtime.h>
#include <math.h>

#define EMB_DIM 448
#define FEAT_DIM 64
#define DMODEL 512
#define NBATCH 8
#define SEQ 2048
#define MTOT (NBATCH * SEQ)

// -------- scratch (device globals; no allocations allowed) --------
static __device__ float g_x[MTOT * DMODEL];      // 32 MB
static __device__ float g_q[MTOT * DMODEL];
static __device__ float g_k[MTOT * DMODEL];
static __device__ float g_v[MTOT * DMODEL];
static __device__ float g_h[MTOT * DMODEL];
static __device__ float g_t[MTOT * DMODEL];
static __device__ float g_sc[(size_t)NBATCH * SEQ * SEQ];  // 128 MB
static __device__ float g_mean[NBATCH * DMODEL];
static __device__ float g_rstd[NBATCH * DMODEL];
static __device__ float g_last[64 * DMODEL];     // padded last-row tile (rows 8..63 unused)
static __device__ float g_lt[64 * DMODEL];
static __device__ float g_lo[64 * DMODEL];

// -------- gather: x = concat(emb_table[ids], feats) --------
__global__ __launch_bounds__(256) void gather_kernel(const int* __restrict__ seq,
                                                     const float* __restrict__ feats,
                                                     const float* __restrict__ emb) {
    int i = blockIdx.x * 256 + threadIdx.x;           // over MTOT * (DMODEL/4)
    int row = i >> 7;                                  // DMODEL/4 = 128
    int d = (i & 127) << 2;
    float4 val;
    if (d < EMB_DIM) {
        int item = seq[row];
        val = *(const float4*)(emb + (size_t)item * EMB_DIM + d);
    } else {
        val = *(const float4*)(feats + (size_t)row * FEAT_DIM + (d - EMB_DIM));
    }
    *(float4*)(g_x + ((size_t)row << 9) + d) = val;
}

// -------- C[M,512] = A[M,512] @ W[512,512]^T + bias, optional ReLU --------
// 64x64 tile, 256 threads, 4x4 micro-tile, BK=16
template <bool RELU>
__global__ __launch_bounds__(256) void gemm_wt_kernel(const float* __restrict__ A,
                                                      const float* __restrict__ W,
                                                      const float* __restrict__ bias,
                                                      float* __restrict__ C) {
    __shared__ float As[16][64];
    __shared__ float Bs[16][64];
    const int bm = blockIdx.x, bn = blockIdx.y;
    const int tid = threadIdx.x;
    const int lrow = tid >> 2;
    const int lc = (tid & 3) << 2;
    const int tm = (tid >> 4) << 2;
    const int tn = (tid & 15) << 2;
    const float* Ap = A + (size_t)(bm * 64 + lrow) * DMODEL + lc;
    const float* Wp = W + (size_t)(bn * 64 + lrow) * DMODEL + lc;
    float acc[4][4] = {};
    for (int kt = 0; kt < DMODEL; kt += 16) {
        float4 a4 = *(const float4*)(Ap + kt);
        float4 w4 = *(const float4*)(Wp + kt);
        As[lc + 0][lrow] = a4.x; As[lc + 1][lrow] = a4.y;
        As[lc + 2][lrow] = a4.z; As[lc + 3][lrow] = a4.w;
        Bs[lc + 0][lrow] = w4.x; Bs[lc + 1][lrow] = w4.y;
        Bs[lc + 2][lrow] = w4.z; Bs[lc + 3][lrow] = w4.w;
        __syncthreads();
#pragma unroll
        for (int kk = 0; kk < 16; kk++) {
            float4 av = *(const float4*)&As[kk][tm];
            float4 bv = *(const float4*)&Bs[kk][tn];
            acc[0][0] += av.x * bv.x; acc[0][1] += av.x * bv.y; acc[0][2] += av.x * bv.z; acc[0][3] += av.x * bv.w;
            acc[1][0] += av.y * bv.x; acc[1][1] += av.y * bv.y; acc[1][2] += av.y * bv.z; acc[1][3] += av.y * bv.w;
            acc[2][0] += av.z * bv.x; acc[2][1] += av.z * bv.y; acc[2][2] += av.z * bv.z; acc[2][3] += av.z * bv.w;
            acc[3][0] += av.w * bv.x; acc[3][1] += av.w * bv.y; acc[3][2] += av.w * bv.z; acc[3][3] += av.w * bv.w;
        }
        __syncthreads();
    }
#pragma unroll
    for (int i = 0; i < 4; i++) {
        int m = bm * 64 + tm + i;
#pragma unroll
        for (int j = 0; j < 4; j++) {
            int n = bn * 64 + tn + j;
            float vv = acc[i][j] + bias[n];
            if (RELU) vv = fmaxf(vv, 0.0f);
            C[(size_t)m * DMODEL + n] = vv;
        }
    }
}

// -------- scores = tril(Q @ K^T) * scale  (per batch) --------
__global__ __launch_bounds__(256) void scores_kernel(const float* __restrict__ Q,
                                                     const float* __restrict__ K) {
    const int b = blockIdx.z;
    const int bm = blockIdx.x, bn = blockIdx.y;
    const int tid = threadIdx.x;
    const int tm = (tid >> 4) << 2;
    const int tn = (tid & 15) << 2;
    float* Sc = g_sc + (size_t)b * SEQ * SEQ;
    if (bn > bm) {  // fully masked tile: write zeros
#pragma unroll
        for (int i = 0; i < 4; i++)
#pragma unroll
            for (int j = 0; j < 4; j++)
                Sc[(size_t)(bm * 64 + tm + i) * SEQ + bn * 64 + tn + j] = 0.0f;
        return;
    }
    __shared__ float As[16][64];
    __shared__ float Bs[16][64];
    const int lrow = tid >> 2;
    const int lc = (tid & 3) << 2;
    const float* Qb = Q + (size_t)b * SEQ * DMODEL;
    const float* Kb = K + (size_t)b * SEQ * DMODEL;
    const float* Ap = Qb + (size_t)(bm * 64 + lrow) * DMODEL + lc;
    const float* Wp = Kb + (size_t)(bn * 64 + lrow) * DMODEL + lc;
    float acc[4][4] = {};
    for (int kt = 0; kt < DMODEL; kt += 16) {
        float4 a4 = *(const float4*)(Ap + kt);
        float4 w4 = *(const float4*)(Wp + kt);
        As[lc + 0][lrow] = a4.x; As[lc + 1][lrow] = a4.y;
        As[lc + 2][lrow] = a4.z; As[lc + 3][lrow] = a4.w;
        Bs[lc + 0][lrow] = w4.x; Bs[lc + 1][lrow] = w4.y;
        Bs[lc + 2][lrow] = w4.z; Bs[lc + 3][lrow] = w4.w;
        __syncthreads();
#pragma unroll
        for (int kk = 0; kk < 16; kk++) {
            float4 av = *(const float4*)&As[kk][tm];
            float4 bv = *(const float4*)&Bs[kk][tn];
            acc[0][0] += av.x * bv.x; acc[0][1] += av.x * bv.y; acc[0][2] += av.x * bv.z; acc[0][3] += av.x * bv.w;
            acc[1][0] += av.y * bv.x; acc[1][1] += av.y * bv.y; acc[1][2] += av.y * bv.z; acc[1][3] += av.y * bv.w;
            acc[2][0] += av.z * bv.x; acc[2][1] += av.z * bv.y; acc[2][2] += av.z * bv.z; acc[2][3] += av.z * bv.w;
            acc[3][0] += av.w * bv.x; acc[3][1] += av.w * bv.y; acc[3][2] += av.w * bv.z; acc[3][3] += av.w * bv.w;
        }
        __syncthreads();
    }
    const float scale = 0.044194173824159216f;  // 1/sqrt(512)
#pragma unroll
    for (int i = 0; i < 4; i++) {
        int m = bm * 64 + tm + i;
#pragma unroll
        for (int j = 0; j < 4; j++) {
            int n = bn * 64 + tn + j;
            Sc[(size_t)m * SEQ + n] = (n <= m) ? acc[i][j] * scale : 0.0f;
        }
    }
}

// -------- h = scores @ V  (per batch; K-loop bounded by causal diagonal) --------
__global__ __launch_bounds__(256) void gemm_av_kernel() {
    const int b = blockIdx.z;
    const float* A = g_sc + (size_t)b * SEQ * SEQ;
    const float* Bv = g_v + (size_t)b * SEQ * DMODEL;
    float* C = g_h + (size_t)b * SEQ * DMODEL;
    __shared__ float As[16][64];
    __shared__ float Bs[16][64];
    const int bm = blockIdx.x, bn = blockIdx.y;
    const int tid = threadIdx.x;
    const int lrow = tid >> 2;
    const int lc = (tid & 3) << 2;
    const int brow = tid >> 4;          // 0..15 (k within tile)
    const int bcol = (tid & 15) << 2;   // 0..60 (n within tile)
    const int tm = (tid >> 4) << 2;
    const int tn = (tid & 15) << 2;
    const float* Ap = A + (size_t)(bm * 64 + lrow) * SEQ + lc;
    float acc[4][4] = {};
    const int kmax = (bm + 1) * 64;  // scores zero beyond diagonal
    for (int kt = 0; kt < kmax; kt += 16) {
        float4 a4 = *(const float4*)(Ap + kt);
        As[lc + 0][lrow] = a4.x; As[lc + 1][lrow] = a4.y;
        As[lc + 2][lrow] = a4.z; As[lc + 3][lrow] = a4.w;
        *(float4*)&Bs[brow][bcol] =
            *(const float4*)(Bv + (size_t)(kt + brow) * DMODEL + bn * 64 + bcol);
        __syncthreads();
#pragma unroll
        for (int kk = 0; kk < 16; kk++) {
            float4 av = *(const float4*)&As[kk][tm];
            float4 bv = *(const float4*)&Bs[kk][tn];
            acc[0][0] += av.x * bv.x; acc[0][1] += av.x * bv.y; acc[0][2] += av.x * bv.z; acc[0][3] += av.x * bv.w;
            acc[1][0] += av.y * bv.x; acc[1][1] += av.y * bv.y; acc[1][2] += av.y * bv.z; acc[1][3] += av.y * bv.w;
            acc[2][0] += av.z * bv.x; acc[2][1] += av.z * bv.y; acc[2][2] += av.z * bv.z; acc[2][3] += av.z * bv.w;
            acc[3][0] += av.w * bv.x; acc[3][1] += av.w * bv.y; acc[3][2] += av.w * bv.z; acc[3][3] += av.w * bv.w;
        }
        __syncthreads();
    }
#pragma unroll
    for (int i = 0; i < 4; i++) {
        int m = bm * 64 + tm + i;
#pragma unroll
        for (int j = 0; j < 4; j++)
            C[(size_t)m * DMODEL + (bn * 64 + tn + j)] = acc[i][j];
    }
}

// -------- seq-norm stats over axis=1 (S), ddof=1; denom = std + 1e-5 + 1e-5 --------
__global__ void stats_kernel(const float* __restrict__ H) {
    const int b = blockIdx.x;
    const int d = blockIdx.y * 32 + threadIdx.x;
    const int ty = threadIdx.y;
    float sum = 0.f, sq = 0.f;
    for (int s = ty; s < SEQ; s += 8) {
        float v = H[(size_t)(b * SEQ + s) * DMODEL + d];
        sum += v; sq += v * v;
    }
    __shared__ float ss[8][32];
    __shared__ float s2[8][32];
    ss[ty][threadIdx.x] = sum;
    s2[ty][threadIdx.x] = sq;
    __syncthreads();
    if (ty == 0) {
#pragma unroll
        for (int r = 1; r < 8; r++) { sum += ss[r][threadIdx.x]; sq += s2[r][threadIdx.x]; }
        float mean = sum * (1.0f / SEQ);
        float var = (sq - sum * mean) * (1.0f / (SEQ - 1));
        var = fmaxf(var, 0.0f);
        g_mean[b * DMODEL + d] = mean;
        g_rstd[b * DMODEL + d] = 1.0f / (sqrtf(var) + 2e-5f);
    }
}

__global__ __launch_bounds__(256) void norm_kernel(float* __restrict__ H) {
    int i = blockIdx.x * 256 + threadIdx.x;  // over MTOT * 128
    int row = i >> 7;
    int c4 = (i & 127) << 2;
    int b = row >> 11;  // SEQ = 2048
    float4 v = *(float4*)(H + ((size_t)row << 9) + c4);
    float4 m = *(const float4*)(g_mean + b * DMODEL + c4);
    float4 r = *(const float4*)(g_rstd + b * DMODEL + c4);
    v.x = (v.x - m.x) * r.x; v.y = (v.y - m.y) * r.y;
    v.z = (v.z - m.z) * r.z; v.w = (v.w - m.w) * r.w;
    *(float4*)(H + ((size_t)row << 9) + c4) = v;
}

// -------- last-row extraction for block-2 MLP (positionwise ⇒ only last row needed) --------
__global__ void last_gather_kernel(const float* __restrict__ H) {
    int i = blockIdx.x * 256 + threadIdx.x;  // 4096
    int b = i >> 9, d = i & 511;
    g_last[i] = H[(size_t)(b * SEQ + SEQ - 1) * DMODEL + d];
}

__global__ void out_copy_kernel(float* __restrict__ out) {
    int i = blockIdx.x * 256 + threadIdx.x;  // 4096
    out[i] = g_lo[i];
}

extern "C" void kernel_launch(void* const* d_in, const int* in_sizes, int n_in,
                              void* d_out, int out_size) {
    const int* seq = (const int*)d_in[0];
    const float* feats = (const float*)d_in[1];
    const float* emb = (const float*)d_in[2];
    const float* Wq = (const float*)d_in[3];
    const float* bq = (const float*)d_in[4];
    const float* Wk = (const float*)d_in[5];
    const float* bk = (const float*)d_in[6];
    const float* Wv = (const float*)d_in[7];
    const float* bv = (const float*)d_in[8];
    const float* W1 = (const float*)d_in[9];
    const float* b1 = (const float*)d_in[10];
    const float* W2 = (const float*)d_in[11];
    const float* b2 = (const float*)d_in[12];
    float* out = (float*)d_out;

    void *px, *pq, *pk, *pv, *ph, *pt, *plast, *plt, *plo;
    cudaGetSymbolAddress(&px, g_x);
    cudaGetSymbolAddress(&pq, g_q);
    cudaGetSymbolAddress(&pk, g_k);
    cudaGetSymbolAddress(&pv, g_v);
    cudaGetSymbolAddress(&ph, g_h);
    cudaGetSymbolAddress(&pt, g_t);
    cudaGetSymbolAddress(&plast, g_last);
    cudaGetSymbolAddress(&plt, g_lt);
    cudaGetSymbolAddress(&plo, g_lo);
    float* x = (float*)px;  float* q = (float*)pq;  float* k = (float*)pk;
    float* v = (float*)pv;  float* h = (float*)ph;  float* t = (float*)pt;
    float* last = (float*)plast; float* lt = (float*)plt; float* lo = (float*)plo;

    gather_kernel<<<MTOT * 128 / 256, 256>>>(seq, feats, emb);

    const dim3 gemm_grid(MTOT / 64, DMODEL / 64);
    for (int l = 0; l < 2; l++) {
        const float* Wq_l = Wq + (size_t)l * DMODEL * DMODEL;
        const float* Wk_l = Wk + (size_t)l * DMODEL * DMODEL;
        const float* Wv_l = Wv + (size_t)l * DMODEL * DMODEL;
        const float* W1_l = W1 + (size_t)l * DMODEL * DMODEL;
        const float* W2_l = W2 + (size_t)l * DMODEL * DMODEL;
        const float* bq_l = bq + l * DMODEL;
        const float* bk_l = bk + l * DMODEL;
        const float* bv_l = bv + l * DMODEL;
        const float* b1_l = b1 + l * DMODEL;
        const float* b2_l = b2 + l * DMODEL;

        gemm_wt_kernel<false><<<gemm_grid, 256>>>(x, Wq_l, bq_l, q);
        gemm_wt_kernel<false><<<gemm_grid, 256>>>(x, Wk_l, bk_l, k);
        gemm_wt_kernel<false><<<gemm_grid, 256>>>(x, Wv_l, bv_l, v);

        scores_kernel<<<dim3(SEQ / 64, SEQ / 64, NBATCH), 256>>>(q, k);
        gemm_av_kernel<<<dim3(SEQ / 64, DMODEL / 64, NBATCH), 256>>>();

        stats_kernel<<<dim3(NBATCH, DMODEL / 32), dim3(32, 8)>>>(h);
        norm_kernel<<<MTOT * 128 / 256, 256>>>(h);

        if (l == 0) {
            gemm_wt_kernel<true><<<gemm_grid, 256>>>(h, W1_l, b1_l, t);
            gemm_wt_kernel<false><<<gemm_grid, 256>>>(t, W2_l, b2_l, x);
        } else {
            // output only needs the last position; MLP is positionwise
            last_gather_kernel<<<16, 256>>>(h);
            gemm_wt_kernel<true><<<dim3(1, DMODEL / 64), 256>>>(last, W1_l, b1_l, lt);
            gemm_wt_kernel<false><<<dim3(1, DMODEL / 64), 256>>>(lt, W2_l, b2_l, lo);
            out_copy_kernel<<<16, 256>>>(out);
        }
    }
}

// round 4
// speedup vs baseline: 2.0834x; 2.0825x over previous
#include <cuda_runtime.h>
#include <cuda_bf16.h>
#include <math.h>
#include <stdint.h>

#define EMB_DIM 448
#define FEAT_DIM 64
#define DMODEL 512
#define NBATCH 8
#define SEQ 2048
#define MTOT (NBATCH * SEQ)

static __device__ float g_x[MTOT * DMODEL];
static __device__ float g_q[MTOT * DMODEL];
static __device__ float g_k[MTOT * DMODEL];
static __device__ float g_v[MTOT * DMODEL];
static __device__ float g_vt[MTOT * DMODEL];
static __device__ float g_h[MTOT * DMODEL];
static __device__ float g_t[MTOT * DMODEL];
static __device__ float g_sc[(size_t)NBATCH * SEQ * SEQ];
static __device__ float g_mean[NBATCH * DMODEL];
static __device__ float g_rstd[NBATCH * DMODEL];
static __device__ float g_last[NBATCH * DMODEL];
static __device__ float g_lt[NBATCH * DMODEL];

__device__ __forceinline__ uint32_t smem_u32(const void* p) {
    uint32_t a;
    asm("{ .reg .u64 t; cvta.to.shared.u64 t, %1; cvt.u32.u64 %0, t; }" : "=r"(a) : "l"(p));
    return a;
}

#define SWZ(o) ((o) ^ ((((uint32_t)(o)) >> 3) & 0x70))
// per-stage SMEM: Ahi | Alo | Bhi | Blo, each 128 rows x 128B (SW128)
#define ST(s) ((s) * 65536u)
#define OFF_AHI 0u
#define OFF_ALO 16384u
#define OFF_BHI 32768u
#define OFF_BLO 49152u
#define SMEM_TC 131072

__device__ __forceinline__ void ldm_x4(uint32_t* r, uint32_t addr) {
    asm volatile("ldmatrix.sync.aligned.m8n8.x4.shared.b16 {%0,%1,%2,%3}, [%4];"
                 : "=r"(r[0]), "=r"(r[1]), "=r"(r[2]), "=r"(r[3]) : "r"(addr));
}
__device__ __forceinline__ void mma16816(float* c, const uint32_t* a, const uint32_t* b) {
    asm volatile(
        "mma.sync.aligned.m16n8k16.row.col.f32.bf16.bf16.f32 "
        "{%0,%1,%2,%3}, {%4,%5,%6,%7}, {%8,%9}, {%0,%1,%2,%3};"
        : "+f"(c[0]), "+f"(c[1]), "+f"(c[2]), "+f"(c[3])
        : "r"(a[0]), "r"(a[1]), "r"(a[2]), "r"(a[3]), "r"(b[0]), "r"(b[1]));
}

__device__ __forceinline__ void cvt8(float4 a, float4 b, uint4& hi, uint4& lo) {
    __nv_bfloat162 h0 = __floats2bfloat162_rn(a.x, a.y), h1 = __floats2bfloat162_rn(a.z, a.w);
    __nv_bfloat162 h2 = __floats2bfloat162_rn(b.x, b.y), h3 = __floats2bfloat162_rn(b.z, b.w);
    __nv_bfloat162 l0 = __floats2bfloat162_rn(a.x - __bfloat162float(h0.x), a.y - __bfloat162float(h0.y));
    __nv_bfloat162 l1 = __floats2bfloat162_rn(a.z - __bfloat162float(h1.x), a.w - __bfloat162float(h1.y));
    __nv_bfloat162 l2 = __floats2bfloat162_rn(b.x - __bfloat162float(h2.x), b.y - __bfloat162float(h2.y));
    __nv_bfloat162 l3 = __floats2bfloat162_rn(b.z - __bfloat162float(h3.x), b.w - __bfloat162float(h3.y));
    hi.x = *(uint32_t*)&h0; hi.y = *(uint32_t*)&h1; hi.z = *(uint32_t*)&h2; hi.w = *(uint32_t*)&h3;
    lo.x = *(uint32_t*)&l0; lo.y = *(uint32_t*)&l1; lo.z = *(uint32_t*)&l2; lo.w = *(uint32_t*)&l3;
}

// 128x64 fp32 -> hi/lo bf16 SW128 tiles (128B rows); 256 threads
__device__ __forceinline__ void load_hl(const float* __restrict__ src, int ld,
                                        char* hb, char* lb, int tid) {
#pragma unroll
    for (int i = 0; i < 2; i++) {
        int r = i * 64 + (tid >> 2);
        int cg = tid & 3;
        const float* p = src + (size_t)r * ld + cg * 16;
        float4 f0 = *(const float4*)(p + 0), f1 = *(const float4*)(p + 4);
        float4 f2 = *(const float4*)(p + 8), f3 = *(const float4*)(p + 12);
        uint4 h0, l0, h1, l1;
        cvt8(f0, f1, h0, l0);
        cvt8(f2, f3, h1, l1);
        uint32_t off = (uint32_t)r * 128u + (uint32_t)cg * 32u;
        *(uint4*)(hb + SWZ(off)) = h0;  *(uint4*)(hb + SWZ(off + 16)) = h1;
        *(uint4*)(lb + SWZ(off)) = l0;  *(uint4*)(lb + SWZ(off + 16)) = l1;
    }
}

// MODE: 0=bias, 1=bias+relu, 2=scores(scale+causal mask), 3=plain with causal K bound
// C[128m x 128n] = A[128, K] * B(rows)[128, K]^T ; 256 thr, warp tile 64x32
template <int MODE>
__global__ void __launch_bounds__(256) mma_gemm(const float* __restrict__ A,
                                                const float* __restrict__ B,
                                                const float* __restrict__ bias,
                                                float* __restrict__ C,
                                                int lda, int ldb, int ldc, int Kfix,
                                                size_t sA, size_t sB, size_t sC, float scale) {
    extern __shared__ char smem[];
    const int tid = threadIdx.x, wid = tid >> 5, lane = tid & 31;
    const int bm = blockIdx.x, bn = blockIdx.y, bz = blockIdx.z;
    if (MODE == 2 && bn > bm) return;  // fully-masked score tile
    A += sA * bz + (size_t)bm * 128 * lda;
    B += sB * bz + (size_t)bn * 128 * ldb;
    C += sC * bz;
    const int K = (MODE == 3) ? (bm + 1) * 128 : Kfix;
    const int NC = K >> 6;

    const uint32_t sb = smem_u32(smem);
    const int wm = wid >> 2, wn = wid & 3;           // warp grid 2x4
    const int lr = lane & 15, lc16 = (lane >> 4) * 16;

    float acc[4][4][4];
#pragma unroll
    for (int i = 0; i < 4; i++)
#pragma unroll
        for (int j = 0; j < 4; j++)
#pragma unroll
            for (int r = 0; r < 4; r++) acc[i][j][r] = 0.f;

    load_hl(A, lda, smem + ST(0) + OFF_AHI, smem + ST(0) + OFF_ALO, tid);
    load_hl(B, ldb, smem + ST(0) + OFF_BHI, smem + ST(0) + OFF_BLO, tid);
    __syncthreads();

    for (int c = 0; c < NC; c++) {
        const uint32_t base = sb + ST(c & 1);
#pragma unroll
        for (int ks = 0; ks < 4; ks++) {
            const uint32_t kb = ks * 32 + lc16;
            uint32_t ah[4][4], al[4][4];
#pragma unroll
            for (int mb = 0; mb < 4; mb++) {
                uint32_t ro = (uint32_t)(wm * 64 + mb * 16 + lr) * 128u + kb;
                ldm_x4(ah[mb], base + OFF_AHI + SWZ(ro));
                ldm_x4(al[mb], base + OFF_ALO + SWZ(ro));
            }
            uint32_t bh[4][2], bl[4][2];
#pragma unroll
            for (int n2 = 0; n2 < 2; n2++) {
                uint32_t ro = (uint32_t)(wn * 32 + n2 * 16 + lr) * 128u + kb;
                uint32_t t[4];
                ldm_x4(t, base + OFF_BHI + SWZ(ro));
                bh[n2 * 2][0] = t[0]; bh[n2 * 2][1] = t[2];
                bh[n2 * 2 + 1][0] = t[1]; bh[n2 * 2 + 1][1] = t[3];
                ldm_x4(t, base + OFF_BLO + SWZ(ro));
                bl[n2 * 2][0] = t[0]; bl[n2 * 2][1] = t[2];
                bl[n2 * 2 + 1][0] = t[1]; bl[n2 * 2 + 1][1] = t[3];
            }
#pragma unroll
            for (int mb = 0; mb < 4; mb++)
#pragma unroll
                for (int nb = 0; nb < 4; nb++) {
                    mma16816(acc[mb][nb], ah[mb], bh[nb]);
                    mma16816(acc[mb][nb], ah[mb], bl[nb]);
                    mma16816(acc[mb][nb], al[mb], bh[nb]);
                }
        }
        if (c + 1 < NC) {
            char* s2 = smem + ST((c + 1) & 1);
            load_hl(A + (c + 1) * 64, lda, s2 + OFF_AHI, s2 + OFF_ALO, tid);
            load_hl(B + (c + 1) * 64, ldb, s2 + OFF_BHI, s2 + OFF_BLO, tid);
        }
        __syncthreads();
    }

    const int g = lane >> 2, t4 = lane & 3;
#pragma unroll
    for (int mb = 0; mb < 4; mb++) {
        const int mbase = bm * 128 + wm * 64 + mb * 16 + g;
#pragma unroll
        for (int nb = 0; nb < 4; nb++) {
            const int n0 = bn * 128 + wn * 32 + nb * 8 + t4 * 2;
#pragma unroll
            for (int rr = 0; rr < 2; rr++) {
                const int m = mbase + rr * 8;
                float v0 = acc[mb][nb][rr * 2], v1 = acc[mb][nb][rr * 2 + 1];
                if (MODE == 0) { v0 += bias[n0]; v1 += bias[n0 + 1]; }
                if (MODE == 1) { v0 = fmaxf(v0 + bias[n0], 0.f); v1 = fmaxf(v1 + bias[n0 + 1], 0.f); }
                if (MODE == 2) {
                    v0 = (n0 <= m) ? v0 * scale : 0.f;
                    v1 = (n0 + 1 <= m) ? v1 * scale : 0.f;
                }
                *(float2*)(C + (size_t)m * ldc + n0) = make_float2(v0, v1);
            }
        }
    }
}

// ---------------- elementwise / small kernels ----------------
__global__ __launch_bounds__(256) void gather_kernel(const int* __restrict__ seq,
                                                     const float* __restrict__ feats,
                                                     const float* __restrict__ emb) {
    int i = blockIdx.x * 256 + threadIdx.x;
    int row = i >> 7, d = (i & 127) << 2;
    float4 val;
    if (d < EMB_DIM) val = *(const float4*)(emb + (size_t)seq[row] * EMB_DIM + d);
    else val = *(const float4*)(feats + (size_t)row * FEAT_DIM + (d - EMB_DIM));
    *(float4*)(g_x + ((size_t)row << 9) + d) = val;
}

__global__ void transpose_kernel(const float* __restrict__ V, float* __restrict__ Vt) {
    __shared__ float tile[32][33];
    int b = blockIdx.z, s0 = blockIdx.x * 32, d0 = blockIdx.y * 32;
    const float* Vb = V + (size_t)b * SEQ * DMODEL;
    float* Vtb = Vt + (size_t)b * DMODEL * SEQ;
    int tx = threadIdx.x, ty = threadIdx.y;
#pragma unroll
    for (int i = 0; i < 32; i += 8)
        tile[ty + i][tx] = Vb[(size_t)(s0 + ty + i) * DMODEL + d0 + tx];
    __syncthreads();
#pragma unroll
    for (int i = 0; i < 32; i += 8)
        Vtb[(size_t)(d0 + ty + i) * SEQ + s0 + tx] = tile[tx][ty + i];
}

__global__ void stats_kernel(const float* __restrict__ H) {
    const int b = blockIdx.x, d = blockIdx.y * 32 + threadIdx.x, ty = threadIdx.y;
    float sum = 0.f, sq = 0.f;
    for (int s = ty; s < SEQ; s += 8) {
        float v = H[(size_t)(b * SEQ + s) * DMODEL + d];
        sum += v; sq += v * v;
    }
    __shared__ float ss[8][32], s2[8][32];
    ss[ty][threadIdx.x] = sum; s2[ty][threadIdx.x] = sq;
    __syncthreads();
    if (ty == 0) {
#pragma unroll
        for (int r = 1; r < 8; r++) { sum += ss[r][threadIdx.x]; sq += s2[r][threadIdx.x]; }
        float mean = sum * (1.0f / SEQ);
        float var = fmaxf((sq - sum * mean) * (1.0f / (SEQ - 1)), 0.0f);
        g_mean[b * DMODEL + d] = mean;
        g_rstd[b * DMODEL + d] = 1.0f / (sqrtf(var) + 2e-5f);
    }
}

__global__ __launch_bounds__(256) void norm_kernel(float* __restrict__ H) {
    int i = blockIdx.x * 256 + threadIdx.x;
    int row = i >> 7, c4 = (i & 127) << 2, b = row >> 11;
    float4 v = *(float4*)(H + ((size_t)row << 9) + c4);
    float4 m = *(const float4*)(g_mean + b * DMODEL + c4);
    float4 r = *(const float4*)(g_rstd + b * DMODEL + c4);
    v.x = (v.x - m.x) * r.x; v.y = (v.y - m.y) * r.y;
    v.z = (v.z - m.z) * r.z; v.w = (v.w - m.w) * r.w;
    *(float4*)(H + ((size_t)row << 9) + c4) = v;
}

__global__ void last_gather_kernel(const float* __restrict__ H) {
    int i = blockIdx.x * 256 + threadIdx.x;  // 4096
    int b = i >> 9, d = i & 511;
    g_last[i] = H[(size_t)(b * SEQ + SEQ - 1) * DMODEL + d];
}

template <bool RELU>
__global__ void small_gemm(const float* __restrict__ A, const float* __restrict__ W,
                           const float* __restrict__ bias, float* __restrict__ C) {
    int i = blockIdx.x * 256 + threadIdx.x;  // 4096
    int m = i >> 9, n = i & 511;
    const float* a = A + (size_t)m * DMODEL;
    const float* w = W + (size_t)n * DMODEL;
    float s = 0.f;
#pragma unroll 8
    for (int k2 = 0; k2 < DMODEL; k2 += 4) {
        float4 av = *(const float4*)(a + k2), wv = *(const float4*)(w + k2);
        s += av.x * wv.x + av.y * wv.y + av.z * wv.z + av.w * wv.w;
    }
    s += bias[n];
    if (RELU) s = fmaxf(s, 0.0f);
    C[i] = s;
}

extern "C" void kernel_launch(void* const* d_in, const int* in_sizes, int n_in,
                              void* d_out, int out_size) {
    const int* seq = (const int*)d_in[0];
    const float* feats = (const float*)d_in[1];
    const float* emb = (const float*)d_in[2];
    const float* Wq = (const float*)d_in[3];  const float* bq = (const float*)d_in[4];
    const float* Wk = (const float*)d_in[5];  const float* bk = (const float*)d_in[6];
    const float* Wv = (const float*)d_in[7];  const float* bv = (const float*)d_in[8];
    const float* W1 = (const float*)d_in[9];  const float* b1 = (const float*)d_in[10];
    const float* W2 = (const float*)d_in[11]; const float* b2 = (const float*)d_in[12];
    float* out = (float*)d_out;

    cudaFuncSetAttribute(mma_gemm<0>, cudaFuncAttributeMaxDynamicSharedMemorySize, SMEM_TC);
    cudaFuncSetAttribute(mma_gemm<1>, cudaFuncAttributeMaxDynamicSharedMemorySize, SMEM_TC);
    cudaFuncSetAttribute(mma_gemm<2>, cudaFuncAttributeMaxDynamicSharedMemorySize, SMEM_TC);
    cudaFuncSetAttribute(mma_gemm<3>, cudaFuncAttributeMaxDynamicSharedMemorySize, SMEM_TC);

    void *px, *pq, *pk, *pv, *pvt, *ph, *pt, *psc, *plast, *plt;
    cudaGetSymbolAddress(&px, g_x);   cudaGetSymbolAddress(&pq, g_q);
    cudaGetSymbolAddress(&pk, g_k);   cudaGetSymbolAddress(&pv, g_v);
    cudaGetSymbolAddress(&pvt, g_vt); cudaGetSymbolAddress(&ph, g_h);
    cudaGetSymbolAddress(&pt, g_t);   cudaGetSymbolAddress(&psc, g_sc);
    cudaGetSymbolAddress(&plast, g_last); cudaGetSymbolAddress(&plt, g_lt);
    float* x = (float*)px;  float* q = (float*)pq;  float* k = (float*)pk;
    float* v = (float*)pv;  float* vt = (float*)pvt; float* h = (float*)ph;
    float* t = (float*)pt;  float* sc = (float*)psc;
    float* last = (float*)plast; float* lt = (float*)plt;

    const float scale = 0.044194173824159216f;  // 1/sqrt(512)

    gather_kernel<<<MTOT * 128 / 256, 256>>>(seq, feats, emb);

    const dim3 gw(MTOT / 128, DMODEL / 128);         // 128 x 4
    const dim3 gs(SEQ / 128, SEQ / 128, NBATCH);     // 16 x 16 x 8
    const dim3 ga(SEQ / 128, DMODEL / 128, NBATCH);  // 16 x 4 x 8

    for (int l = 0; l < 2; l++) {
        const size_t wo = (size_t)l * DMODEL * DMODEL;
        const int bo = l * DMODEL;
        mma_gemm<0><<<gw, 256, SMEM_TC>>>(x, Wq + wo, bq + bo, q, DMODEL, DMODEL, DMODEL, DMODEL, 0, 0, 0, 0.f);
        mma_gemm<0><<<gw, 256, SMEM_TC>>>(x, Wk + wo, bk + bo, k, DMODEL, DMODEL, DMODEL, DMODEL, 0, 0, 0, 0.f);
        mma_gemm<0><<<gw, 256, SMEM_TC>>>(x, Wv + wo, bv + bo, v, DMODEL, DMODEL, DMODEL, DMODEL, 0, 0, 0, 0.f);

        transpose_kernel<<<dim3(SEQ / 32, DMODEL / 32, NBATCH), dim3(32, 8)>>>(v, vt);

        mma_gemm<2><<<gs, 256, SMEM_TC>>>(q, k, nullptr, sc, DMODEL, DMODEL, SEQ, DMODEL,
                                          (size_t)SEQ * DMODEL, (size_t)SEQ * DMODEL, (size_t)SEQ * SEQ, scale);
        mma_gemm<3><<<ga, 256, SMEM_TC>>>(sc, vt, nullptr, h, SEQ, SEQ, DMODEL, 0,
                                          (size_t)SEQ * SEQ, (size_t)DMODEL * SEQ, (size_t)SEQ * DMODEL, 0.f);

        stats_kernel<<<dim3(NBATCH, DMODEL / 32), dim3(32, 8)>>>(h);
        norm_kernel<<<MTOT * 128 / 256, 256>>>(h);

        if (l == 0) {
            mma_gemm<1><<<gw, 256, SMEM_TC>>>(h, W1 + wo, b1 + bo, t, DMODEL, DMODEL, DMODEL, DMODEL, 0, 0, 0, 0.f);
            mma_gemm<0><<<gw, 256, SMEM_TC>>>(t, W2 + wo, b2 + bo, x, DMODEL, DMODEL, DMODEL, DMODEL, 0, 0, 0, 0.f);
        } else {
            last_gather_kernel<<<16, 256>>>(h);
            small_gemm<true><<<16, 256>>>(last, W1 + wo, b1 + bo, lt);
            small_gemm<false><<<16, 256>>>(lt, W2 + wo, b2 + bo, out);
        }
    }
}

// round 5
// speedup vs baseline: 2.1842x; 1.0483x over previous
#include <cuda_runtime.h>
#include <cuda_bf16.h>
#include <math.h>
#include <stdint.h>

#define EMB_DIM 448
#define FEAT_DIM 64
#define DMODEL 512
#define NBATCH 8
#define SEQ 2048
#define MTOT (NBATCH * SEQ)

static __device__ float g_x[MTOT * DMODEL];
static __device__ float g_q[MTOT * DMODEL];
static __device__ float g_k[MTOT * DMODEL];
static __device__ float g_v[MTOT * DMODEL];
static __device__ float g_vt[MTOT * DMODEL];
static __device__ float g_h[MTOT * DMODEL];
static __device__ float g_t[MTOT * DMODEL];
static __device__ float g_sc[(size_t)NBATCH * SEQ * SEQ];
static __device__ float g_mean[NBATCH * DMODEL];
static __device__ float g_rstd[NBATCH * DMODEL];
static __device__ float g_last[NBATCH * DMODEL];
static __device__ float g_lt[NBATCH * DMODEL];

__device__ __forceinline__ uint32_t smem_u32(const void* p) {
    uint32_t a;
    asm("{ .reg .u64 t; cvta.to.shared.u64 t, %1; cvt.u32.u64 %0, t; }" : "=r"(a) : "l"(p));
    return a;
}

#define SWZ(o) ((o) ^ ((((uint32_t)(o)) >> 3) & 0x70))
// per-stage SMEM: Ahi | Alo | Bhi | Blo, each 128 rows x 128B (SW128)
#define ST(s) ((s) * 65536u)
#define OFF_AHI 0u
#define OFF_ALO 16384u
#define OFF_BHI 32768u
#define OFF_BLO 49152u
#define SMEM_TC 131072

__device__ __forceinline__ void ldm_x4(uint32_t* r, uint32_t addr) {
    asm volatile("ldmatrix.sync.aligned.m8n8.x4.shared.b16 {%0,%1,%2,%3}, [%4];"
                 : "=r"(r[0]), "=r"(r[1]), "=r"(r[2]), "=r"(r[3]) : "r"(addr));
}
__device__ __forceinline__ void mma16816(float* c, const uint32_t* a, const uint32_t* b) {
    asm volatile(
        "mma.sync.aligned.m16n8k16.row.col.f32.bf16.bf16.f32 "
        "{%0,%1,%2,%3}, {%4,%5,%6,%7}, {%8,%9}, {%0,%1,%2,%3};"
        : "+f"(c[0]), "+f"(c[1]), "+f"(c[2]), "+f"(c[3])
        : "r"(a[0]), "r"(a[1]), "r"(a[2]), "r"(a[3]), "r"(b[0]), "r"(b[1]));
}

__device__ __forceinline__ void cvt8(float4 a, float4 b, uint4& hi, uint4& lo) {
    __nv_bfloat162 h0 = __floats2bfloat162_rn(a.x, a.y), h1 = __floats2bfloat162_rn(a.z, a.w);
    __nv_bfloat162 h2 = __floats2bfloat162_rn(b.x, b.y), h3 = __floats2bfloat162_rn(b.z, b.w);
    __nv_bfloat162 l0 = __floats2bfloat162_rn(a.x - __bfloat162float(h0.x), a.y - __bfloat162float(h0.y));
    __nv_bfloat162 l1 = __floats2bfloat162_rn(a.z - __bfloat162float(h1.x), a.w - __bfloat162float(h1.y));
    __nv_bfloat162 l2 = __floats2bfloat162_rn(b.x - __bfloat162float(h2.x), b.y - __bfloat162float(h2.y));
    __nv_bfloat162 l3 = __floats2bfloat162_rn(b.z - __bfloat162float(h3.x), b.w - __bfloat162float(h3.y));
    hi.x = *(uint32_t*)&h0; hi.y = *(uint32_t*)&h1; hi.z = *(uint32_t*)&h2; hi.w = *(uint32_t*)&h3;
    lo.x = *(uint32_t*)&l0; lo.y = *(uint32_t*)&l1; lo.z = *(uint32_t*)&l2; lo.w = *(uint32_t*)&l3;
}

// 128x64 fp32 -> hi/lo bf16 SW128 tiles; 512 threads: one 64B quarter-row each
__device__ __forceinline__ void load_hl(const float* __restrict__ src, int ld,
                                        char* hb, char* lb, int tid) {
    int r = tid >> 2;
    int cg = tid & 3;
    const float* p = src + (size_t)r * ld + cg * 16;
    float4 f0 = *(const float4*)(p + 0), f1 = *(const float4*)(p + 4);
    float4 f2 = *(const float4*)(p + 8), f3 = *(const float4*)(p + 12);
    uint4 h0, l0, h1, l1;
    cvt8(f0, f1, h0, l0);
    cvt8(f2, f3, h1, l1);
    uint32_t off = (uint32_t)r * 128u + (uint32_t)cg * 32u;
    *(uint4*)(hb + SWZ(off)) = h0;  *(uint4*)(hb + SWZ(off + 16)) = h1;
    *(uint4*)(lb + SWZ(off)) = l0;  *(uint4*)(lb + SWZ(off + 16)) = l1;
}

// MODE: 0=bias, 1=bias+relu, 2=scores(scale+causal mask), 3=plain with causal K bound
// C[128m x 128n] = A[128, K] * B(rows)[128, K]^T ; 512 thr, warp grid 4x4, warp tile 32x32
template <int MODE>
__global__ void __launch_bounds__(512) mma_gemm(const float* __restrict__ A,
                                                const float* __restrict__ B,
                                                const float* __restrict__ bias,
                                                float* __restrict__ C,
                                                int lda, int ldb, int ldc, int Kfix,
                                                size_t sA, size_t sB, size_t sC, float scale) {
    extern __shared__ char smem[];
    const int tid = threadIdx.x, wid = tid >> 5, lane = tid & 31;
    const int bm = blockIdx.x, bn = blockIdx.y, bz = blockIdx.z;
    if (MODE == 2 && bn > bm) return;  // fully-masked score tile
    A += sA * bz + (size_t)bm * 128 * lda;
    B += sB * bz + (size_t)bn * 128 * ldb;
    C += sC * bz;
    const int K = (MODE == 3) ? (bm + 1) * 128 : Kfix;
    const int NC = K >> 6;

    const uint32_t sb = smem_u32(smem);
    const int wm = wid >> 2, wn = wid & 3;           // warp grid 4x4
    const int lr = lane & 15, lc16 = (lane >> 4) * 16;

    float acc[2][4][4];
#pragma unroll
    for (int i = 0; i < 2; i++)
#pragma unroll
        for (int j = 0; j < 4; j++)
#pragma unroll
            for (int r = 0; r < 4; r++) acc[i][j][r] = 0.f;

    load_hl(A, lda, smem + ST(0) + OFF_AHI, smem + ST(0) + OFF_ALO, tid);
    load_hl(B, ldb, smem + ST(0) + OFF_BHI, smem + ST(0) + OFF_BLO, tid);
    __syncthreads();

    for (int c = 0; c < NC; c++) {
        const uint32_t base = sb + ST(c & 1);
#pragma unroll
        for (int ks = 0; ks < 4; ks++) {
            const uint32_t kb = ks * 32 + lc16;
            uint32_t ah[2][4], al[2][4];
#pragma unroll
            for (int mb = 0; mb < 2; mb++) {
                uint32_t ro = (uint32_t)(wm * 32 + mb * 16 + lr) * 128u + kb;
                ldm_x4(ah[mb], base + OFF_AHI + SWZ(ro));
                ldm_x4(al[mb], base + OFF_ALO + SWZ(ro));
            }
            uint32_t bh[4][2], bl[4][2];
#pragma unroll
            for (int n2 = 0; n2 < 2; n2++) {
                uint32_t ro = (uint32_t)(wn * 32 + n2 * 16 + lr) * 128u + kb;
                uint32_t t[4];
                ldm_x4(t, base + OFF_BHI + SWZ(ro));
                bh[n2 * 2][0] = t[0]; bh[n2 * 2][1] = t[2];
                bh[n2 * 2 + 1][0] = t[1]; bh[n2 * 2 + 1][1] = t[3];
                ldm_x4(t, base + OFF_BLO + SWZ(ro));
                bl[n2 * 2][0] = t[0]; bl[n2 * 2][1] = t[2];
                bl[n2 * 2 + 1][0] = t[1]; bl[n2 * 2 + 1][1] = t[3];
            }
#pragma unroll
            for (int mb = 0; mb < 2; mb++)
#pragma unroll
                for (int nb = 0; nb < 4; nb++) {
                    mma16816(acc[mb][nb], ah[mb], bh[nb]);
                    mma16816(acc[mb][nb], ah[mb], bl[nb]);
                    mma16816(acc[mb][nb], al[mb], bh[nb]);
                }
        }
        if (c + 1 < NC) {
            char* s2 = smem + ST((c + 1) & 1);
            load_hl(A + (c + 1) * 64, lda, s2 + OFF_AHI, s2 + OFF_ALO, tid);
            load_hl(B + (c + 1) * 64, ldb, s2 + OFF_BHI, s2 + OFF_BLO, tid);
        }
        __syncthreads();
    }

    const int g = lane >> 2, t4 = lane & 3;
#pragma unroll
    for (int mb = 0; mb < 2; mb++) {
        const int mbase = bm * 128 + wm * 32 + mb * 16 + g;
#pragma unroll
        for (int nb = 0; nb < 4; nb++) {
            const int n0 = bn * 128 + wn * 32 + nb * 8 + t4 * 2;
#pragma unroll
            for (int rr = 0; rr < 2; rr++) {
                const int m = mbase + rr * 8;
                float v0 = acc[mb][nb][rr * 2], v1 = acc[mb][nb][rr * 2 + 1];
                if (MODE == 0) { v0 += bias[n0]; v1 += bias[n0 + 1]; }
                if (MODE == 1) { v0 = fmaxf(v0 + bias[n0], 0.f); v1 = fmaxf(v1 + bias[n0 + 1], 0.f); }
                if (MODE == 2) {
                    v0 = (n0 <= m) ? v0 * scale : 0.f;
                    v1 = (n0 + 1 <= m) ? v1 * scale : 0.f;
                }
                *(float2*)(C + (size_t)m * ldc + n0) = make_float2(v0, v1);
            }
        }
    }
}

// ---------------- elementwise / small kernels ----------------
__global__ __launch_bounds__(256) void gather_kernel(const int* __restrict__ seq,
                                                     const float* __restrict__ feats,
                                                     const float* __restrict__ emb) {
    int i = blockIdx.x * 256 + threadIdx.x;
    int row = i >> 7, d = (i & 127) << 2;
    float4 val;
    if (d < EMB_DIM) val = *(const float4*)(emb + (size_t)seq[row] * EMB_DIM + d);
    else val = *(const float4*)(feats + (size_t)row * FEAT_DIM + (d - EMB_DIM));
    *(float4*)(g_x + ((size_t)row << 9) + d) = val;
}

__global__ void transpose_kernel(const float* __restrict__ V, float* __restrict__ Vt) {
    __shared__ float tile[32][33];
    int b = blockIdx.z, s0 = blockIdx.x * 32, d0 = blockIdx.y * 32;
    const float* Vb = V + (size_t)b * SEQ * DMODEL;
    float* Vtb = Vt + (size_t)b * DMODEL * SEQ;
    int tx = threadIdx.x, ty = threadIdx.y;
#pragma unroll
    for (int i = 0; i < 32; i += 8)
        tile[ty + i][tx] = Vb[(size_t)(s0 + ty + i) * DMODEL + d0 + tx];
    __syncthreads();
#pragma unroll
    for (int i = 0; i < 32; i += 8)
        Vtb[(size_t)(d0 + ty + i) * SEQ + s0 + tx] = tile[tx][ty + i];
}

__global__ void stats_kernel(const float* __restrict__ H) {
    const int b = blockIdx.x, d = blockIdx.y * 32 + threadIdx.x, ty = threadIdx.y;
    float sum = 0.f, sq = 0.f;
    for (int s = ty; s < SEQ; s += 8) {
        float v = H[(size_t)(b * SEQ + s) * DMODEL + d];
        sum += v; sq += v * v;
    }
    __shared__ float ss[8][32], s2[8][32];
    ss[ty][threadIdx.x] = sum; s2[ty][threadIdx.x] = sq;
    __syncthreads();
    if (ty == 0) {
#pragma unroll
        for (int r = 1; r < 8; r++) { sum += ss[r][threadIdx.x]; sq += s2[r][threadIdx.x]; }
        float mean = sum * (1.0f / SEQ);
        float var = fmaxf((sq - sum * mean) * (1.0f / (SEQ - 1)), 0.0f);
        g_mean[b * DMODEL + d] = mean;
        g_rstd[b * DMODEL + d] = 1.0f / (sqrtf(var) + 2e-5f);
    }
}

__global__ __launch_bounds__(256) void norm_kernel(float* __restrict__ H) {
    int i = blockIdx.x * 256 + threadIdx.x;
    int row = i >> 7, c4 = (i & 127) << 2, b = row >> 11;
    float4 v = *(float4*)(H + ((size_t)row << 9) + c4);
    float4 m = *(const float4*)(g_mean + b * DMODEL + c4);
    float4 r = *(const float4*)(g_rstd + b * DMODEL + c4);
    v.x = (v.x - m.x) * r.x; v.y = (v.y - m.y) * r.y;
    v.z = (v.z - m.z) * r.z; v.w = (v.w - m.w) * r.w;
    *(float4*)(H + ((size_t)row << 9) + c4) = v;
}

__global__ void last_gather_kernel(const float* __restrict__ H) {
    int i = blockIdx.x * 256 + threadIdx.x;  // 4096
    int b = i >> 9, d = i & 511;
    g_last[i] = H[(size_t)(b * SEQ + SEQ - 1) * DMODEL + d];
}

template <bool RELU>
__global__ void small_gemm(const float* __restrict__ A, const float* __restrict__ W,
                           const float* __restrict__ bias, float* __restrict__ C) {
    int i = blockIdx.x * 256 + threadIdx.x;  // 4096
    int m = i >> 9, n = i & 511;
    const float* a = A + (size_t)m * DMODEL;
    const float* w = W + (size_t)n * DMODEL;
    float s = 0.f;
#pragma unroll 8
    for (int k2 = 0; k2 < DMODEL; k2 += 4) {
        float4 av = *(const float4*)(a + k2), wv = *(const float4*)(w + k2);
        s += av.x * wv.x + av.y * wv.y + av.z * wv.z + av.w * wv.w;
    }
    s += bias[n];
    if (RELU) s = fmaxf(s, 0.0f);
    C[i] = s;
}

extern "C" void kernel_launch(void* const* d_in, const int* in_sizes, int n_in,
                              void* d_out, int out_size) {
    const int* seq = (const int*)d_in[0];
    const float* feats = (const float*)d_in[1];
    const float* emb = (const float*)d_in[2];
    const float* Wq = (const float*)d_in[3];  const float* bq = (const float*)d_in[4];
    const float* Wk = (const float*)d_in[5];  const float* bk = (const float*)d_in[6];
    const float* Wv = (const float*)d_in[7];  const float* bv = (const float*)d_in[8];
    const float* W1 = (const float*)d_in[9];  const float* b1 = (const float*)d_in[10];
    const float* W2 = (const float*)d_in[11]; const float* b2 = (const float*)d_in[12];
    float* out = (float*)d_out;

    cudaFuncSetAttribute(mma_gemm<0>, cudaFuncAttributeMaxDynamicSharedMemorySize, SMEM_TC);
    cudaFuncSetAttribute(mma_gemm<1>, cudaFuncAttributeMaxDynamicSharedMemorySize, SMEM_TC);
    cudaFuncSetAttribute(mma_gemm<2>, cudaFuncAttributeMaxDynamicSharedMemorySize, SMEM_TC);
    cudaFuncSetAttribute(mma_gemm<3>, cudaFuncAttributeMaxDynamicSharedMemorySize, SMEM_TC);

    void *px, *pq, *pk, *pv, *pvt, *ph, *pt, *psc, *plast, *plt;
    cudaGetSymbolAddress(&px, g_x);   cudaGetSymbolAddress(&pq, g_q);
    cudaGetSymbolAddress(&pk, g_k);   cudaGetSymbolAddress(&pv, g_v);
    cudaGetSymbolAddress(&pvt, g_vt); cudaGetSymbolAddress(&ph, g_h);
    cudaGetSymbolAddress(&pt, g_t);   cudaGetSymbolAddress(&psc, g_sc);
    cudaGetSymbolAddress(&plast, g_last); cudaGetSymbolAddress(&plt, g_lt);
    float* x = (float*)px;  float* q = (float*)pq;  float* k = (float*)pk;
    float* v = (float*)pv;  float* vt = (float*)pvt; float* h = (float*)ph;
    float* t = (float*)pt;  float* sc = (float*)psc;
    float* last = (float*)plast; float* lt = (float*)plt;

    const float scale = 0.044194173824159216f;  // 1/sqrt(512)

    gather_kernel<<<MTOT * 128 / 256, 256>>>(seq, feats, emb);

    const dim3 gw(MTOT / 128, DMODEL / 128);         // 128 x 4
    const dim3 gs(SEQ / 128, SEQ / 128, NBATCH);     // 16 x 16 x 8
    const dim3 ga(SEQ / 128, DMODEL / 128, NBATCH);  // 16 x 4 x 8

    for (int l = 0; l < 2; l++) {
        const size_t wo = (size_t)l * DMODEL * DMODEL;
        const int bo = l * DMODEL;
        mma_gemm<0><<<gw, 512, SMEM_TC>>>(x, Wq + wo, bq + bo, q, DMODEL, DMODEL, DMODEL, DMODEL, 0, 0, 0, 0.f);
        mma_gemm<0><<<gw, 512, SMEM_TC>>>(x, Wk + wo, bk + bo, k, DMODEL, DMODEL, DMODEL, DMODEL, 0, 0, 0, 0.f);
        mma_gemm<0><<<gw, 512, SMEM_TC>>>(x, Wv + wo, bv + bo, v, DMODEL, DMODEL, DMODEL, DMODEL, 0, 0, 0, 0.f);

        transpose_kernel<<<dim3(SEQ / 32, DMODEL / 32, NBATCH), dim3(32, 8)>>>(v, vt);

        mma_gemm<2><<<gs, 512, SMEM_TC>>>(q, k, nullptr, sc, DMODEL, DMODEL, SEQ, DMODEL,
                                          (size_t)SEQ * DMODEL, (size_t)SEQ * DMODEL, (size_t)SEQ * SEQ, scale);
        mma_gemm<3><<<ga, 512, SMEM_TC>>>(sc, vt, nullptr, h, SEQ, SEQ, DMODEL, 0,
                                          (size_t)SEQ * SEQ, (size_t)DMODEL * SEQ, (size_t)SEQ * DMODEL, 0.f);

        stats_kernel<<<dim3(NBATCH, DMODEL / 32), dim3(32, 8)>>>(h);
        norm_kernel<<<MTOT * 128 / 256, 256>>>(h);

        if (l == 0) {
            mma_gemm<1><<<gw, 512, SMEM_TC>>>(h, W1 + wo, b1 + bo, t, DMODEL, DMODEL, DMODEL, DMODEL, 0, 0, 0, 0.f);
            mma_gemm<0><<<gw, 512, SMEM_TC>>>(t, W2 + wo, b2 + bo, x, DMODEL, DMODEL, DMODEL, DMODEL, 0, 0, 0, 0.f);
        } else {
            last_gather_kernel<<<16, 256>>>(h);
            small_gemm<true><<<16, 256>>>(last, W1 + wo, b1 + bo, lt);
            small_gemm<false><<<16, 256>>>(lt, W2 + wo, b2 + bo, out);
        }
    }
}

// round 6
// speedup vs baseline: 2.8339x; 1.2975x over previous
#include <cuda_runtime.h>
#include <cuda_bf16.h>
#include <math.h>
#include <stdint.h>

#define EMB_DIM 448
#define FEAT_DIM 64
#define DMODEL 512
#define NBATCH 8
#define SEQ 2048
#define MTOT (NBATCH * SEQ)
typedef __nv_bfloat16 bf16;

// -------- scratch (device globals) --------
static __device__ bf16 g_xh[MTOT * DMODEL], g_xl[MTOT * DMODEL];
static __device__ bf16 g_qh[MTOT * DMODEL], g_ql[MTOT * DMODEL];
static __device__ bf16 g_kh[MTOT * DMODEL], g_kl[MTOT * DMODEL];
static __device__ bf16 g_vth[MTOT * DMODEL], g_vtl[MTOT * DMODEL];
static __device__ bf16 g_hnh[MTOT * DMODEL], g_hnl[MTOT * DMODEL];
static __device__ bf16 g_th[MTOT * DMODEL], g_tl[MTOT * DMODEL];
static __device__ bf16 g_sch[(size_t)NBATCH * SEQ * SEQ], g_scl[(size_t)NBATCH * SEQ * SEQ];
static __device__ bf16 g_wbh[DMODEL * DMODEL], g_wbl[DMODEL * DMODEL];
static __device__ float g_v[MTOT * DMODEL], g_h[MTOT * DMODEL];
static __device__ float g_mean[NBATCH * DMODEL], g_rstd[NBATCH * DMODEL];
static __device__ float g_last[NBATCH * DMODEL], g_lt[NBATCH * DMODEL];

__device__ __forceinline__ uint32_t smem_u32(const void* p) {
    uint32_t a;
    asm("{ .reg .u64 t; cvta.to.shared.u64 t, %1; cvt.u32.u64 %0, t; }" : "=r"(a) : "l"(p));
    return a;
}
#define SWZ(o) ((o) ^ ((((uint32_t)(o)) >> 3) & 0x70))
#define OFF_AHI 0u
#define OFF_ALO 16384u
#define OFF_BHI 32768u
#define OFF_BLO 49152u
#define STAGE_B 65536u
#define SMEM_TC 196608

__device__ __forceinline__ void ldm_x4(uint32_t* r, uint32_t addr) {
    asm volatile("ldmatrix.sync.aligned.m8n8.x4.shared.b16 {%0,%1,%2,%3}, [%4];"
                 : "=r"(r[0]), "=r"(r[1]), "=r"(r[2]), "=r"(r[3]) : "r"(addr));
}
__device__ __forceinline__ void mma16816(float* c, const uint32_t* a, const uint32_t* b) {
    asm volatile(
        "mma.sync.aligned.m16n8k16.row.col.f32.bf16.bf16.f32 "
        "{%0,%1,%2,%3}, {%4,%5,%6,%7}, {%8,%9}, {%0,%1,%2,%3};"
        : "+f"(c[0]), "+f"(c[1]), "+f"(c[2]), "+f"(c[3])
        : "r"(a[0]), "r"(a[1]), "r"(a[2]), "r"(a[3]), "r"(b[0]), "r"(b[1]));
}
__device__ __forceinline__ void cpa16(uint32_t dst, const void* src) {
    asm volatile("cp.async.cg.shared.global [%0], [%1], 16;" :: "r"(dst), "l"(src));
}
#define CPA_COMMIT() asm volatile("cp.async.commit_group;" ::: "memory")

__device__ __forceinline__ void split4(float4 f, uint2& h, uint2& l) {
    bf16 h0 = __float2bfloat16(f.x), h1 = __float2bfloat16(f.y);
    bf16 h2 = __float2bfloat16(f.z), h3 = __float2bfloat16(f.w);
    bf16 l0 = __float2bfloat16(f.x - __bfloat162float(h0));
    bf16 l1 = __float2bfloat16(f.y - __bfloat162float(h1));
    bf16 l2 = __float2bfloat16(f.z - __bfloat162float(h2));
    bf16 l3 = __float2bfloat16(f.w - __bfloat162float(h3));
    __nv_bfloat162 a, b, c, d;
    a.x = h0; a.y = h1; b.x = h2; b.y = h3;
    c.x = l0; c.y = l1; d.x = l2; d.y = l3;
    h.x = *(uint32_t*)&a; h.y = *(uint32_t*)&b;
    l.x = *(uint32_t*)&c; l.y = *(uint32_t*)&d;
}

// MODE: 0=bias, 1=bias+relu, 2=scores(scale+causal), 3=plain w/ causal K bound
// OUT: 0=fp32 (Cf), 1=bf16 hi/lo (Ch/Cl)
template <int MODE, int OUT>
__global__ void __launch_bounds__(512) mma_gemm(const bf16* __restrict__ Ah, const bf16* __restrict__ Al,
                                                const bf16* __restrict__ Bh, const bf16* __restrict__ Bl,
                                                const float* __restrict__ bias,
                                                float* __restrict__ Cf, bf16* __restrict__ Ch, bf16* __restrict__ Cl,
                                                int lda, int ldb, int ldc, int Kfix,
                                                size_t sA, size_t sB, size_t sC, float scale) {
    extern __shared__ char smem[];
    const int tid = threadIdx.x, wid = tid >> 5, lane = tid & 31;
    const int bm = blockIdx.x, bn = blockIdx.y, bz = blockIdx.z;
    if (MODE == 2 && bn > bm) return;
    Ah += sA * bz + (size_t)bm * 128 * lda;
    Al += sA * bz + (size_t)bm * 128 * lda;
    Bh += sB * bz + (size_t)bn * 128 * ldb;
    Bl += sB * bz + (size_t)bn * 128 * ldb;
    const int K = (MODE == 3) ? (bm + 1) * 128 : Kfix;
    const int NC = K >> 6;
    const uint32_t sb = smem_u32(smem);
    const int wm = wid >> 2, wn = wid & 3;  // warp grid 4x4, warp tile 32x32
    const int lr = lane & 15, lc16 = (lane >> 4) * 16;

    float acc[2][4][4];
#pragma unroll
    for (int i = 0; i < 2; i++)
#pragma unroll
        for (int j = 0; j < 4; j++)
#pragma unroll
            for (int r = 0; r < 4; r++) acc[i][j][r] = 0.f;

    // stage loader: 8x cp.async(16B) per thread = 64KB/stage
#define STAGE_LOAD(S, CIDX) do { \
        uint32_t base_ = sb + (uint32_t)(S) * STAGE_B; \
        int koff_ = (CIDX) * 64; \
        _Pragma("unroll") \
        for (int j_ = 0; j_ < 2; j_++) { \
            int cc_ = tid + j_ * 512; \
            int r_ = cc_ >> 3, cg_ = cc_ & 7; \
            uint32_t so_ = SWZ((uint32_t)r_ * 128u + (uint32_t)cg_ * 16u); \
            size_t ga_ = (size_t)r_ * lda + koff_ + cg_ * 8; \
            size_t gb_ = (size_t)r_ * ldb + koff_ + cg_ * 8; \
            cpa16(base_ + OFF_AHI + so_, Ah + ga_); \
            cpa16(base_ + OFF_ALO + so_, Al + ga_); \
            cpa16(base_ + OFF_BHI + so_, Bh + gb_); \
            cpa16(base_ + OFF_BLO + so_, Bl + gb_); \
        } \
        CPA_COMMIT(); \
    } while (0)

    STAGE_LOAD(0, 0);
    if (NC > 1) STAGE_LOAD(1, 1);

    for (int c = 0; c < NC; c++) {
        if (c + 1 < NC) asm volatile("cp.async.wait_group 1;" ::: "memory");
        else            asm volatile("cp.async.wait_group 0;" ::: "memory");
        __syncthreads();
        const uint32_t base = sb + (uint32_t)(((uint32_t)c) % 3u) * STAGE_B;
#pragma unroll
        for (int ks = 0; ks < 4; ks++) {
            const uint32_t kb = ks * 32 + lc16;
            uint32_t ah[2][4], al[2][4];
#pragma unroll
            for (int mb = 0; mb < 2; mb++) {
                uint32_t ro = (uint32_t)(wm * 32 + mb * 16 + lr) * 128u + kb;
                ldm_x4(ah[mb], base + OFF_AHI + SWZ(ro));
                ldm_x4(al[mb], base + OFF_ALO + SWZ(ro));
            }
            uint32_t bh[4][2], bl[4][2];
#pragma unroll
            for (int n2 = 0; n2 < 2; n2++) {
                uint32_t ro = (uint32_t)(wn * 32 + n2 * 16 + lr) * 128u + kb;
                uint32_t t[4];
                ldm_x4(t, base + OFF_BHI + SWZ(ro));
                bh[n2 * 2][0] = t[0]; bh[n2 * 2][1] = t[2];
                bh[n2 * 2 + 1][0] = t[1]; bh[n2 * 2 + 1][1] = t[3];
                ldm_x4(t, base + OFF_BLO + SWZ(ro));
                bl[n2 * 2][0] = t[0]; bl[n2 * 2][1] = t[2];
                bl[n2 * 2 + 1][0] = t[1]; bl[n2 * 2 + 1][1] = t[3];
            }
#pragma unroll
            for (int mb = 0; mb < 2; mb++)
#pragma unroll
                for (int nb = 0; nb < 4; nb++) {
                    mma16816(acc[mb][nb], ah[mb], bh[nb]);
                    mma16816(acc[mb][nb], ah[mb], bl[nb]);
                    mma16816(acc[mb][nb], al[mb], bh[nb]);
                }
        }
        if (c + 2 < NC) STAGE_LOAD(((uint32_t)(c + 2)) % 3u, c + 2);
    }
#undef STAGE_LOAD

    if (OUT == 0) Cf += sC * bz;
    else { Ch += sC * bz; Cl += sC * bz; }
    const int g = lane >> 2, t4 = lane & 3;
#pragma unroll
    for (int mb = 0; mb < 2; mb++) {
        const int mbase = bm * 128 + wm * 32 + mb * 16 + g;
#pragma unroll
        for (int nb = 0; nb < 4; nb++) {
            const int n0 = bn * 128 + wn * 32 + nb * 8 + t4 * 2;
#pragma unroll
            for (int rr = 0; rr < 2; rr++) {
                const int m = mbase + rr * 8;
                float v0 = acc[mb][nb][rr * 2], v1 = acc[mb][nb][rr * 2 + 1];
                if (MODE == 0) { v0 += bias[n0]; v1 += bias[n0 + 1]; }
                if (MODE == 1) { v0 = fmaxf(v0 + bias[n0], 0.f); v1 = fmaxf(v1 + bias[n0 + 1], 0.f); }
                if (MODE == 2) {
                    v0 = (n0 <= m) ? v0 * scale : 0.f;
                    v1 = (n0 + 1 <= m) ? v1 * scale : 0.f;
                }
                if (OUT == 0) {
                    *(float2*)(Cf + (size_t)m * ldc + n0) = make_float2(v0, v1);
                } else {
                    __nv_bfloat162 hv, lv;
                    hv.x = __float2bfloat16(v0);
                    hv.y = __float2bfloat16(v1);
                    lv.x = __float2bfloat16(v0 - __bfloat162float(hv.x));
                    lv.y = __float2bfloat16(v1 - __bfloat162float(hv.y));
                    *(__nv_bfloat162*)(Ch + (size_t)m * ldc + n0) = hv;
                    *(__nv_bfloat162*)(Cl + (size_t)m * ldc + n0) = lv;
                }
            }
        }
    }
}

// ---------------- elementwise / small kernels ----------------
__global__ __launch_bounds__(256) void gather_split(const int* __restrict__ seq,
                                                    const float* __restrict__ feats,
                                                    const float* __restrict__ emb) {
    int i = blockIdx.x * 256 + threadIdx.x;
    int row = i >> 7, d = (i & 127) << 2;
    float4 val;
    if (d < EMB_DIM) val = *(const float4*)(emb + (size_t)seq[row] * EMB_DIM + d);
    else val = *(const float4*)(feats + (size_t)row * FEAT_DIM + (d - EMB_DIM));
    uint2 h, l;
    split4(val, h, l);
    *(uint2*)(g_xh + ((size_t)row << 9) + d) = h;
    *(uint2*)(g_xl + ((size_t)row << 9) + d) = l;
}

__global__ __launch_bounds__(256) void splitw(const float* __restrict__ W) {
    int i = (blockIdx.x * 256 + threadIdx.x) << 2;  // over DMODEL*DMODEL
    float4 f = *(const float4*)(W + i);
    uint2 h, l;
    split4(f, h, l);
    *(uint2*)(g_wbh + i) = h;
    *(uint2*)(g_wbl + i) = l;
}

__global__ void transpose_split(const float* __restrict__ V) {
    __shared__ float tile[32][33];
    int b = blockIdx.z, s0 = blockIdx.x * 32, d0 = blockIdx.y * 32;
    const float* Vb = V + (size_t)b * SEQ * DMODEL;
    bf16* Vth = g_vth + (size_t)b * DMODEL * SEQ;
    bf16* Vtl = g_vtl + (size_t)b * DMODEL * SEQ;
    int tx = threadIdx.x, ty = threadIdx.y;
#pragma unroll
    for (int i = 0; i < 32; i += 8)
        tile[ty + i][tx] = Vb[(size_t)(s0 + ty + i) * DMODEL + d0 + tx];
    __syncthreads();
#pragma unroll
    for (int i = 0; i < 32; i += 8) {
        float v = tile[tx][ty + i];
        bf16 h = __float2bfloat16(v);
        bf16 l = __float2bfloat16(v - __bfloat162float(h));
        Vth[(size_t)(d0 + ty + i) * SEQ + s0 + tx] = h;
        Vtl[(size_t)(d0 + ty + i) * SEQ + s0 + tx] = l;
    }
}

__global__ void stats_kernel(const float* __restrict__ H) {
    const int b = blockIdx.x, d = blockIdx.y * 32 + threadIdx.x, ty = threadIdx.y;
    float sum = 0.f, sq = 0.f;
    for (int s = ty; s < SEQ; s += 8) {
        float v = H[(size_t)(b * SEQ + s) * DMODEL + d];
        sum += v; sq += v * v;
    }
    __shared__ float ss[8][32], s2[8][32];
    ss[ty][threadIdx.x] = sum; s2[ty][threadIdx.x] = sq;
    __syncthreads();
    if (ty == 0) {
#pragma unroll
        for (int r = 1; r < 8; r++) { sum += ss[r][threadIdx.x]; sq += s2[r][threadIdx.x]; }
        float mean = sum * (1.0f / SEQ);
        float var = fmaxf((sq - sum * mean) * (1.0f / (SEQ - 1)), 0.0f);
        g_mean[b * DMODEL + d] = mean;
        g_rstd[b * DMODEL + d] = 1.0f / (sqrtf(var) + 2e-5f);
    }
}

__global__ __launch_bounds__(256) void norm_split(const float* __restrict__ H) {
    int i = blockIdx.x * 256 + threadIdx.x;
    int row = i >> 7, c4 = (i & 127) << 2, b = row >> 11;
    float4 v = *(const float4*)(H + ((size_t)row << 9) + c4);
    float4 m = *(const float4*)(g_mean + b * DMODEL + c4);
    float4 r = *(const float4*)(g_rstd + b * DMODEL + c4);
    v.x = (v.x - m.x) * r.x; v.y = (v.y - m.y) * r.y;
    v.z = (v.z - m.z) * r.z; v.w = (v.w - m.w) * r.w;
    uint2 h, l;
    split4(v, h, l);
    *(uint2*)(g_hnh + ((size_t)row << 9) + c4) = h;
    *(uint2*)(g_hnl + ((size_t)row << 9) + c4) = l;
}

__global__ void last_gather(void) {
    int i = blockIdx.x * 256 + threadIdx.x;  // 4096
    int b = i >> 9, d = i & 511;
    size_t idx = (size_t)(b * SEQ + SEQ - 1) * DMODEL + d;
    g_last[i] = __bfloat162float(g_hnh[idx]) + __bfloat162float(g_hnl[idx]);
}

template <bool RELU>
__global__ void small_gemm(const float* __restrict__ A, const float* __restrict__ W,
                           const float* __restrict__ bias, float* __restrict__ C) {
    int i = blockIdx.x * 256 + threadIdx.x;  // 4096
    int m = i >> 9, n = i & 511;
    const float* a = A + (size_t)m * DMODEL;
    const float* w = W + (size_t)n * DMODEL;
    float s = 0.f;
#pragma unroll 8
    for (int k2 = 0; k2 < DMODEL; k2 += 4) {
        float4 av = *(const float4*)(a + k2), wv = *(const float4*)(w + k2);
        s += av.x * wv.x + av.y * wv.y + av.z * wv.z + av.w * wv.w;
    }
    s += bias[n];
    if (RELU) s = fmaxf(s, 0.0f);
    C[i] = s;
}

extern "C" void kernel_launch(void* const* d_in, const int* in_sizes, int n_in,
                              void* d_out, int out_size) {
    const int* seq = (const int*)d_in[0];
    const float* feats = (const float*)d_in[1];
    const float* emb = (const float*)d_in[2];
    const float* Wq = (const float*)d_in[3];  const float* bq = (const float*)d_in[4];
    const float* Wk = (const float*)d_in[5];  const float* bk = (const float*)d_in[6];
    const float* Wv = (const float*)d_in[7];  const float* bv = (const float*)d_in[8];
    const float* W1 = (const float*)d_in[9];  const float* b1 = (const float*)d_in[10];
    const float* W2 = (const float*)d_in[11]; const float* b2 = (const float*)d_in[12];
    float* out = (float*)d_out;

    cudaFuncSetAttribute(mma_gemm<0, 0>, cudaFuncAttributeMaxDynamicSharedMemorySize, SMEM_TC);
    cudaFuncSetAttribute(mma_gemm<0, 1>, cudaFuncAttributeMaxDynamicSharedMemorySize, SMEM_TC);
    cudaFuncSetAttribute(mma_gemm<1, 1>, cudaFuncAttributeMaxDynamicSharedMemorySize, SMEM_TC);
    cudaFuncSetAttribute(mma_gemm<2, 1>, cudaFuncAttributeMaxDynamicSharedMemorySize, SMEM_TC);
    cudaFuncSetAttribute(mma_gemm<3, 0>, cudaFuncAttributeMaxDynamicSharedMemorySize, SMEM_TC);

    void *pxh, *pxl, *pqh, *pql, *pkh, *pkl, *pvth, *pvtl, *phnh, *phnl, *pth, *ptl;
    void *psch, *pscl, *pwbh, *pwbl, *pv, *ph, *plast, *plt;
    cudaGetSymbolAddress(&pxh, g_xh);   cudaGetSymbolAddress(&pxl, g_xl);
    cudaGetSymbolAddress(&pqh, g_qh);   cudaGetSymbolAddress(&pql, g_ql);
    cudaGetSymbolAddress(&pkh, g_kh);   cudaGetSymbolAddress(&pkl, g_kl);
    cudaGetSymbolAddress(&pvth, g_vth); cudaGetSymbolAddress(&pvtl, g_vtl);
    cudaGetSymbolAddress(&phnh, g_hnh); cudaGetSymbolAddress(&phnl, g_hnl);
    cudaGetSymbolAddress(&pth, g_th);   cudaGetSymbolAddress(&ptl, g_tl);
    cudaGetSymbolAddress(&psch, g_sch); cudaGetSymbolAddress(&pscl, g_scl);
    cudaGetSymbolAddress(&pwbh, g_wbh); cudaGetSymbolAddress(&pwbl, g_wbl);
    cudaGetSymbolAddress(&pv, g_v);     cudaGetSymbolAddress(&ph, g_h);
    cudaGetSymbolAddress(&plast, g_last); cudaGetSymbolAddress(&plt, g_lt);
    bf16* xh = (bf16*)pxh;   bf16* xl = (bf16*)pxl;
    bf16* qh = (bf16*)pqh;   bf16* ql = (bf16*)pql;
    bf16* kh = (bf16*)pkh;   bf16* kl = (bf16*)pkl;
    bf16* vth = (bf16*)pvth; bf16* vtl = (bf16*)pvtl;
    bf16* hnh = (bf16*)phnh; bf16* hnl = (bf16*)phnl;
    bf16* th = (bf16*)pth;   bf16* tl = (bf16*)ptl;
    bf16* sch = (bf16*)psch; bf16* scl = (bf16*)pscl;
    bf16* wbh = (bf16*)pwbh; bf16* wbl = (bf16*)pwbl;
    float* v = (float*)pv;   float* h = (float*)ph;
    float* last = (float*)plast; float* lt = (float*)plt;

    const float scale = 0.044194173824159216f;  // 1/sqrt(512)
    const int swg = DMODEL * DMODEL / 4 / 256;

    gather_split<<<MTOT * 128 / 256, 256>>>(seq, feats, emb);

    const dim3 gw(MTOT / 128, DMODEL / 128);         // 128 x 4
    const dim3 gs(SEQ / 128, SEQ / 128, NBATCH);     // 16 x 16 x 8
    const dim3 ga(SEQ / 128, DMODEL / 128, NBATCH);  // 16 x 4 x 8

    for (int l = 0; l < 2; l++) {
        const size_t wo = (size_t)l * DMODEL * DMODEL;
        const int bo = l * DMODEL;

        splitw<<<swg, 256>>>(Wq + wo);
        mma_gemm<0, 1><<<gw, 512, SMEM_TC>>>(xh, xl, wbh, wbl, bq + bo, nullptr, qh, ql,
                                             DMODEL, DMODEL, DMODEL, DMODEL, 0, 0, 0, 0.f);
        splitw<<<swg, 256>>>(Wk + wo);
        mma_gemm<0, 1><<<gw, 512, SMEM_TC>>>(xh, xl, wbh, wbl, bk + bo, nullptr, kh, kl,
                                             DMODEL, DMODEL, DMODEL, DMODEL, 0, 0, 0, 0.f);
        splitw<<<swg, 256>>>(Wv + wo);
        mma_gemm<0, 0><<<gw, 512, SMEM_TC>>>(xh, xl, wbh, wbl, bv + bo, v, nullptr, nullptr,
                                             DMODEL, DMODEL, DMODEL, DMODEL, 0, 0, 0, 0.f);

        transpose_split<<<dim3(SEQ / 32, DMODEL / 32, NBATCH), dim3(32, 8)>>>(v);

        mma_gemm<2, 1><<<gs, 512, SMEM_TC>>>(qh, ql, kh, kl, nullptr, nullptr, sch, scl,
                                             DMODEL, DMODEL, SEQ, DMODEL,
                                             (size_t)SEQ * DMODEL, (size_t)SEQ * DMODEL,
                                             (size_t)SEQ * SEQ, scale);
        mma_gemm<3, 0><<<ga, 512, SMEM_TC>>>(sch, scl, vth, vtl, nullptr, h, nullptr, nullptr,
                                             SEQ, SEQ, DMODEL, 0,
                                             (size_t)SEQ * SEQ, (size_t)DMODEL * SEQ,
                                             (size_t)SEQ * DMODEL, 0.f);

        stats_kernel<<<dim3(NBATCH, DMODEL / 32), dim3(32, 8)>>>(h);
        norm_split<<<MTOT * 128 / 256, 256>>>(h);

        if (l == 0) {
            splitw<<<swg, 256>>>(W1 + wo);
            mma_gemm<1, 1><<<gw, 512, SMEM_TC>>>(hnh, hnl, wbh, wbl, b1 + bo, nullptr, th, tl,
                                                 DMODEL, DMODEL, DMODEL, DMODEL, 0, 0, 0, 0.f);
            splitw<<<swg, 256>>>(W2 + wo);
            mma_gemm<0, 1><<<gw, 512, SMEM_TC>>>(th, tl, wbh, wbl, b2 + bo, nullptr, xh, xl,
                                                 DMODEL, DMODEL, DMODEL, DMODEL, 0, 0, 0, 0.f);
        } else {
            last_gather<<<16, 256>>>();
            small_gemm<true><<<16, 256>>>(last, W1 + wo, b1 + bo, lt);
            small_gemm<false><<<16, 256>>>(lt, W2 + wo, b2 + bo, out);
        }
    }
}

// round 7
// speedup vs baseline: 2.8536x; 1.0069x over previous
#include <cuda_runtime.h>
#include <cuda_bf16.h>
#include <math.h>
#include <stdint.h>

#define EMB_DIM 448
#define FEAT_DIM 64
#define DMODEL 512
#define NBATCH 8
#define SEQ 2048
#define MTOT (NBATCH * SEQ)
#define WMAT (DMODEL * DMODEL)
typedef __nv_bfloat16 bf16;

// -------- scratch (device globals) --------
static __device__ bf16 g_xh[MTOT * DMODEL], g_xl[MTOT * DMODEL];
static __device__ bf16 g_qh[MTOT * DMODEL], g_ql[MTOT * DMODEL];
static __device__ bf16 g_kh[MTOT * DMODEL], g_kl[MTOT * DMODEL];
static __device__ bf16 g_vth[MTOT * DMODEL], g_vtl[MTOT * DMODEL];
static __device__ bf16 g_hnh[MTOT * DMODEL], g_hnl[MTOT * DMODEL];
static __device__ bf16 g_th[MTOT * DMODEL], g_tl[MTOT * DMODEL];
static __device__ bf16 g_sch[(size_t)NBATCH * SEQ * SEQ], g_scl[(size_t)NBATCH * SEQ * SEQ];
static __device__ bf16 g_wbh[8 * WMAT], g_wbl[8 * WMAT];   // Wq0,Wk0,Wv0,W1_0,W2_0,Wq1,Wk1,Wv1
static __device__ float g_v[MTOT * DMODEL], g_h[MTOT * DMODEL];
static __device__ float g_mean[NBATCH * DMODEL], g_rstd[NBATCH * DMODEL];
static __device__ float g_last[NBATCH * DMODEL], g_lt[NBATCH * DMODEL];

__device__ __forceinline__ uint32_t smem_u32(const void* p) {
    uint32_t a;
    asm("{ .reg .u64 t; cvta.to.shared.u64 t, %1; cvt.u32.u64 %0, t; }" : "=r"(a) : "l"(p));
    return a;
}
#define SWZ(o) ((o) ^ ((((uint32_t)(o)) >> 3) & 0x70))
#define OFF_AHI 0u
#define OFF_ALO 16384u
#define OFF_BHI 32768u
#define OFF_BLO 49152u
#define STAGE_B 65536u
#define SMEM_TC 196608

__device__ __forceinline__ void ldm_x4(uint32_t* r, uint32_t addr) {
    asm volatile("ldmatrix.sync.aligned.m8n8.x4.shared.b16 {%0,%1,%2,%3}, [%4];"
                 : "=r"(r[0]), "=r"(r[1]), "=r"(r[2]), "=r"(r[3]) : "r"(addr));
}
__device__ __forceinline__ void mma16816(float* c, const uint32_t* a, const uint32_t* b) {
    asm volatile(
        "mma.sync.aligned.m16n8k16.row.col.f32.bf16.bf16.f32 "
        "{%0,%1,%2,%3}, {%4,%5,%6,%7}, {%8,%9}, {%0,%1,%2,%3};"
        : "+f"(c[0]), "+f"(c[1]), "+f"(c[2]), "+f"(c[3])
        : "r"(a[0]), "r"(a[1]), "r"(a[2]), "r"(a[3]), "r"(b[0]), "r"(b[1]));
}
__device__ __forceinline__ void cpa16(uint32_t dst, const void* src) {
    asm volatile("cp.async.cg.shared.global [%0], [%1], 16;" :: "r"(dst), "l"(src));
}
#define CPA_COMMIT() asm volatile("cp.async.commit_group;" ::: "memory")

__device__ __forceinline__ void split4(float4 f, uint2& h, uint2& l) {
    bf16 h0 = __float2bfloat16(f.x), h1 = __float2bfloat16(f.y);
    bf16 h2 = __float2bfloat16(f.z), h3 = __float2bfloat16(f.w);
    bf16 l0 = __float2bfloat16(f.x - __bfloat162float(h0));
    bf16 l1 = __float2bfloat16(f.y - __bfloat162float(h1));
    bf16 l2 = __float2bfloat16(f.z - __bfloat162float(h2));
    bf16 l3 = __float2bfloat16(f.w - __bfloat162float(h3));
    __nv_bfloat162 a, b, c, d;
    a.x = h0; a.y = h1; b.x = h2; b.y = h3;
    c.x = l0; c.y = l1; d.x = l2; d.y = l3;
    h.x = *(uint32_t*)&a; h.y = *(uint32_t*)&b;
    l.x = *(uint32_t*)&c; l.y = *(uint32_t*)&d;
}

// MODE: 0=bias, 1=bias+relu, 2=scores(scale+causal), 3=plain w/ causal K bound
// OUT: 0=fp32 (Cf), 1=bf16 hi/lo (Ch/Cl)
template <int MODE, int OUT>
__global__ void __launch_bounds__(512) mma_gemm(const bf16* __restrict__ Ah, const bf16* __restrict__ Al,
                                                const bf16* __restrict__ Bh, const bf16* __restrict__ Bl,
                                                const float* __restrict__ bias,
                                                float* __restrict__ Cf, bf16* __restrict__ Ch, bf16* __restrict__ Cl,
                                                int lda, int ldb, int ldc, int Kfix,
                                                size_t sA, size_t sB, size_t sC, float scale) {
    extern __shared__ char smem[];
    const int tid = threadIdx.x, wid = tid >> 5, lane = tid & 31;
    const int bm = blockIdx.x, bn = blockIdx.y, bz = blockIdx.z;
    if (MODE == 2 && bn > bm) return;
    Ah += sA * bz + (size_t)bm * 128 * lda;
    Al += sA * bz + (size_t)bm * 128 * lda;
    Bh += sB * bz + (size_t)bn * 128 * ldb;
    Bl += sB * bz + (size_t)bn * 128 * ldb;
    const int K = (MODE == 3) ? (bm + 1) * 128 : Kfix;
    const int NC = K >> 6;
    const uint32_t sb = smem_u32(smem);
    const int wm = wid >> 2, wn = wid & 3;  // warp grid 4x4, warp tile 32x32
    const int lr = lane & 15, lc16 = (lane >> 4) * 16;

    float acc[2][4][4];
#pragma unroll
    for (int i = 0; i < 2; i++)
#pragma unroll
        for (int j = 0; j < 4; j++)
#pragma unroll
            for (int r = 0; r < 4; r++) acc[i][j][r] = 0.f;

#define STAGE_LOAD(S, CIDX) do { \
        uint32_t base_ = sb + (uint32_t)(S) * STAGE_B; \
        int koff_ = (CIDX) * 64; \
        _Pragma("unroll") \
        for (int j_ = 0; j_ < 2; j_++) { \
            int cc_ = tid + j_ * 512; \
            int r_ = cc_ >> 3, cg_ = cc_ & 7; \
            uint32_t so_ = SWZ((uint32_t)r_ * 128u + (uint32_t)cg_ * 16u); \
            size_t ga_ = (size_t)r_ * lda + koff_ + cg_ * 8; \
            size_t gb_ = (size_t)r_ * ldb + koff_ + cg_ * 8; \
            cpa16(base_ + OFF_AHI + so_, Ah + ga_); \
            cpa16(base_ + OFF_ALO + so_, Al + ga_); \
            cpa16(base_ + OFF_BHI + so_, Bh + gb_); \
            cpa16(base_ + OFF_BLO + so_, Bl + gb_); \
        } \
        CPA_COMMIT(); \
    } while (0)

    STAGE_LOAD(0, 0);
    if (NC > 1) STAGE_LOAD(1, 1);

    for (int c = 0; c < NC; c++) {
        if (c + 1 < NC) asm volatile("cp.async.wait_group 1;" ::: "memory");
        else            asm volatile("cp.async.wait_group 0;" ::: "memory");
        __syncthreads();
        const uint32_t base = sb + (uint32_t)(((uint32_t)c) % 3u) * STAGE_B;
#pragma unroll
        for (int ks = 0; ks < 4; ks++) {
            const uint32_t kb = ks * 32 + lc16;
            uint32_t ah[2][4], al[2][4];
#pragma unroll
            for (int mb = 0; mb < 2; mb++) {
                uint32_t ro = (uint32_t)(wm * 32 + mb * 16 + lr) * 128u + kb;
                ldm_x4(ah[mb], base + OFF_AHI + SWZ(ro));
                ldm_x4(al[mb], base + OFF_ALO + SWZ(ro));
            }
            uint32_t bh[4][2], bl[4][2];
#pragma unroll
            for (int n2 = 0; n2 < 2; n2++) {
                uint32_t ro = (uint32_t)(wn * 32 + n2 * 16 + lr) * 128u + kb;
                uint32_t t[4];
                ldm_x4(t, base + OFF_BHI + SWZ(ro));
                bh[n2 * 2][0] = t[0]; bh[n2 * 2][1] = t[2];
                bh[n2 * 2 + 1][0] = t[1]; bh[n2 * 2 + 1][1] = t[3];
                ldm_x4(t, base + OFF_BLO + SWZ(ro));
                bl[n2 * 2][0] = t[0]; bl[n2 * 2][1] = t[2];
                bl[n2 * 2 + 1][0] = t[1]; bl[n2 * 2 + 1][1] = t[3];
            }
            // pass-outer ordering: 8 independent mmas between accumulator reuses
#pragma unroll
            for (int mb = 0; mb < 2; mb++)
#pragma unroll
                for (int nb = 0; nb < 4; nb++)
                    mma16816(acc[mb][nb], ah[mb], bh[nb]);
#pragma unroll
            for (int mb = 0; mb < 2; mb++)
#pragma unroll
                for (int nb = 0; nb < 4; nb++)
                    mma16816(acc[mb][nb], ah[mb], bl[nb]);
#pragma unroll
            for (int mb = 0; mb < 2; mb++)
#pragma unroll
                for (int nb = 0; nb < 4; nb++)
                    mma16816(acc[mb][nb], al[mb], bh[nb]);
        }
        if (c + 2 < NC) STAGE_LOAD(((uint32_t)(c + 2)) % 3u, c + 2);
    }
#undef STAGE_LOAD

    if (OUT == 0) Cf += sC * bz;
    else { Ch += sC * bz; Cl += sC * bz; }
    const int g = lane >> 2, t4 = lane & 3;
#pragma unroll
    for (int mb = 0; mb < 2; mb++) {
        const int mbase = bm * 128 + wm * 32 + mb * 16 + g;
#pragma unroll
        for (int nb = 0; nb < 4; nb++) {
            const int n0 = bn * 128 + wn * 32 + nb * 8 + t4 * 2;
#pragma unroll
            for (int rr = 0; rr < 2; rr++) {
                const int m = mbase + rr * 8;
                float v0 = acc[mb][nb][rr * 2], v1 = acc[mb][nb][rr * 2 + 1];
                if (MODE == 0) { v0 += bias[n0]; v1 += bias[n0 + 1]; }
                if (MODE == 1) { v0 = fmaxf(v0 + bias[n0], 0.f); v1 = fmaxf(v1 + bias[n0 + 1], 0.f); }
                if (MODE == 2) {
                    v0 = (n0 <= m) ? v0 * scale : 0.f;
                    v1 = (n0 + 1 <= m) ? v1 * scale : 0.f;
                }
                if (OUT == 0) {
                    *(float2*)(Cf + (size_t)m * ldc + n0) = make_float2(v0, v1);
                } else {
                    __nv_bfloat162 hv, lv;
                    hv.x = __float2bfloat16(v0);
                    hv.y = __float2bfloat16(v1);
                    lv.x = __float2bfloat16(v0 - __bfloat162float(hv.x));
                    lv.y = __float2bfloat16(v1 - __bfloat162float(hv.y));
                    *(__nv_bfloat162*)(Ch + (size_t)m * ldc + n0) = hv;
                    *(__nv_bfloat162*)(Cl + (size_t)m * ldc + n0) = lv;
                }
            }
        }
    }
}

// ---------------- elementwise / small kernels ----------------
__global__ __launch_bounds__(256) void gather_split(const int* __restrict__ seq,
                                                    const float* __restrict__ feats,
                                                    const float* __restrict__ emb) {
    int i = blockIdx.x * 256 + threadIdx.x;
    int row = i >> 7, d = (i & 127) << 2;
    float4 val;
    if (d < EMB_DIM) val = *(const float4*)(emb + (size_t)seq[row] * EMB_DIM + d);
    else val = *(const float4*)(feats + (size_t)row * FEAT_DIM + (d - EMB_DIM));
    uint2 h, l;
    split4(val, h, l);
    *(uint2*)(g_xh + ((size_t)row << 9) + d) = h;
    *(uint2*)(g_xl + ((size_t)row << 9) + d) = l;
}

// split all 8 big-GEMM weight matrices in one launch
__global__ __launch_bounds__(256) void splitw_all(const float* __restrict__ Wq,
                                                  const float* __restrict__ Wk,
                                                  const float* __restrict__ Wv,
                                                  const float* __restrict__ W1,
                                                  const float* __restrict__ W2) {
    int midx = blockIdx.y;
    const float* src;
    switch (midx) {
        case 0: src = Wq; break;
        case 1: src = Wk; break;
        case 2: src = Wv; break;
        case 3: src = W1; break;
        case 4: src = W2; break;
        case 5: src = Wq + WMAT; break;
        case 6: src = Wk + WMAT; break;
        default: src = Wv + WMAT; break;
    }
    int i = (blockIdx.x * 256 + threadIdx.x) << 2;
    float4 f = *(const float4*)(src + i);
    uint2 h, l;
    split4(f, h, l);
    *(uint2*)(g_wbh + (size_t)midx * WMAT + i) = h;
    *(uint2*)(g_wbl + (size_t)midx * WMAT + i) = l;
}

__global__ void transpose_split(const float* __restrict__ V) {
    __shared__ float tile[32][33];
    int b = blockIdx.z, s0 = blockIdx.x * 32, d0 = blockIdx.y * 32;
    const float* Vb = V + (size_t)b * SEQ * DMODEL;
    bf16* Vth = g_vth + (size_t)b * DMODEL * SEQ;
    bf16* Vtl = g_vtl + (size_t)b * DMODEL * SEQ;
    int tx = threadIdx.x, ty = threadIdx.y;
#pragma unroll
    for (int i = 0; i < 32; i += 8)
        tile[ty + i][tx] = Vb[(size_t)(s0 + ty + i) * DMODEL + d0 + tx];
    __syncthreads();
#pragma unroll
    for (int i = 0; i < 32; i += 8) {
        float v = tile[tx][ty + i];
        bf16 h = __float2bfloat16(v);
        bf16 l = __float2bfloat16(v - __bfloat162float(h));
        Vth[(size_t)(d0 + ty + i) * SEQ + s0 + tx] = h;
        Vtl[(size_t)(d0 + ty + i) * SEQ + s0 + tx] = l;
    }
}

__global__ void stats_kernel(const float* __restrict__ H) {
    const int b = blockIdx.x, d = blockIdx.y * 32 + threadIdx.x, ty = threadIdx.y;
    float sum = 0.f, sq = 0.f;
    for (int s = ty; s < SEQ; s += 8) {
        float v = H[(size_t)(b * SEQ + s) * DMODEL + d];
        sum += v; sq += v * v;
    }
    __shared__ float ss[8][32], s2[8][32];
    ss[ty][threadIdx.x] = sum; s2[ty][threadIdx.x] = sq;
    __syncthreads();
    if (ty == 0) {
#pragma unroll
        for (int r = 1; r < 8; r++) { sum += ss[r][threadIdx.x]; sq += s2[r][threadIdx.x]; }
        float mean = sum * (1.0f / SEQ);
        float var = fmaxf((sq - sum * mean) * (1.0f / (SEQ - 1)), 0.0f);
        g_mean[b * DMODEL + d] = mean;
        g_rstd[b * DMODEL + d] = 1.0f / (sqrtf(var) + 2e-5f);
    }
}

__global__ __launch_bounds__(256) void norm_split(const float* __restrict__ H) {
    int i = blockIdx.x * 256 + threadIdx.x;
    int row = i >> 7, c4 = (i & 127) << 2, b = row >> 11;
    float4 v = *(const float4*)(H + ((size_t)row << 9) + c4);
    float4 m = *(const float4*)(g_mean + b * DMODEL + c4);
    float4 r = *(const float4*)(g_rstd + b * DMODEL + c4);
    v.x = (v.x - m.x) * r.x; v.y = (v.y - m.y) * r.y;
    v.z = (v.z - m.z) * r.z; v.w = (v.w - m.w) * r.w;
    uint2 h, l;
    split4(v, h, l);
    *(uint2*)(g_hnh + ((size_t)row << 9) + c4) = h;
    *(uint2*)(g_hnl + ((size_t)row << 9) + c4) = l;
}

__global__ void last_gather(void) {
    int i = blockIdx.x * 256 + threadIdx.x;  // 4096
    int b = i >> 9, d = i & 511;
    size_t idx = (size_t)(b * SEQ + SEQ - 1) * DMODEL + d;
    g_last[i] = __bfloat162float(g_hnh[idx]) + __bfloat162float(g_hnl[idx]);
}

template <bool RELU>
__global__ void small_gemm(const float* __restrict__ A, const float* __restrict__ W,
                           const float* __restrict__ bias, float* __restrict__ C) {
    int i = blockIdx.x * 256 + threadIdx.x;  // 4096
    int m = i >> 9, n = i & 511;
    const float* a = A + (size_t)m * DMODEL;
    const float* w = W + (size_t)n * DMODEL;
    float s = 0.f;
#pragma unroll 8
    for (int k2 = 0; k2 < DMODEL; k2 += 4) {
        float4 av = *(const float4*)(a + k2), wv = *(const float4*)(w + k2);
        s += av.x * wv.x + av.y * wv.y + av.z * wv.z + av.w * wv.w;
    }
    s += bias[n];
    if (RELU) s = fmaxf(s, 0.0f);
    C[i] = s;
}

extern "C" void kernel_launch(void* const* d_in, const int* in_sizes, int n_in,
                              void* d_out, int out_size) {
    const int* seq = (const int*)d_in[0];
    const float* feats = (const float*)d_in[1];
    const float* emb = (const float*)d_in[2];
    const float* Wq = (const float*)d_in[3];  const float* bq = (const float*)d_in[4];
    const float* Wk = (const float*)d_in[5];  const float* bk = (const float*)d_in[6];
    const float* Wv = (const float*)d_in[7];  const float* bv = (const float*)d_in[8];
    const float* W1 = (const float*)d_in[9];  const float* b1 = (const float*)d_in[10];
    const float* W2 = (const float*)d_in[11]; const float* b2 = (const float*)d_in[12];
    float* out = (float*)d_out;

    cudaFuncSetAttribute(mma_gemm<0, 0>, cudaFuncAttributeMaxDynamicSharedMemorySize, SMEM_TC);
    cudaFuncSetAttribute(mma_gemm<0, 1>, cudaFuncAttributeMaxDynamicSharedMemorySize, SMEM_TC);
    cudaFuncSetAttribute(mma_gemm<1, 1>, cudaFuncAttributeMaxDynamicSharedMemorySize, SMEM_TC);
    cudaFuncSetAttribute(mma_gemm<2, 1>, cudaFuncAttributeMaxDynamicSharedMemorySize, SMEM_TC);
    cudaFuncSetAttribute(mma_gemm<3, 0>, cudaFuncAttributeMaxDynamicSharedMemorySize, SMEM_TC);

    void *pxh, *pxl, *pqh, *pql, *pkh, *pkl, *pvth, *pvtl, *phnh, *phnl, *pth, *ptl;
    void *psch, *pscl, *pwbh, *pwbl, *pv, *ph, *plast, *plt;
    cudaGetSymbolAddress(&pxh, g_xh);   cudaGetSymbolAddress(&pxl, g_xl);
    cudaGetSymbolAddress(&pqh, g_qh);   cudaGetSymbolAddress(&pql, g_ql);
    cudaGetSymbolAddress(&pkh, g_kh);   cudaGetSymbolAddress(&pkl, g_kl);
    cudaGetSymbolAddress(&pvth, g_vth); cudaGetSymbolAddress(&pvtl, g_vtl);
    cudaGetSymbolAddress(&phnh, g_hnh); cudaGetSymbolAddress(&phnl, g_hnl);
    cudaGetSymbolAddress(&pth, g_th);   cudaGetSymbolAddress(&ptl, g_tl);
    cudaGetSymbolAddress(&psch, g_sch); cudaGetSymbolAddress(&pscl, g_scl);
    cudaGetSymbolAddress(&pwbh, g_wbh); cudaGetSymbolAddress(&pwbl, g_wbl);
    cudaGetSymbolAddress(&pv, g_v);     cudaGetSymbolAddress(&ph, g_h);
    cudaGetSymbolAddress(&plast, g_last); cudaGetSymbolAddress(&plt, g_lt);
    bf16* xh = (bf16*)pxh;   bf16* xl = (bf16*)pxl;
    bf16* qh = (bf16*)pqh;   bf16* ql = (bf16*)pql;
    bf16* kh = (bf16*)pkh;   bf16* kl = (bf16*)pkl;
    bf16* vth = (bf16*)pvth; bf16* vtl = (bf16*)pvtl;
    bf16* hnh = (bf16*)phnh; bf16* hnl = (bf16*)phnl;
    bf16* th = (bf16*)pth;   bf16* tl = (bf16*)ptl;
    bf16* sch = (bf16*)psch; bf16* scl = (bf16*)pscl;
    bf16* wbh = (bf16*)pwbh; bf16* wbl = (bf16*)pwbl;
    float* v = (float*)pv;   float* h = (float*)ph;
    float* last = (float*)plast; float* lt = (float*)plt;

    const float scale = 0.044194173824159216f;  // 1/sqrt(512)

    gather_split<<<MTOT * 128 / 256, 256>>>(seq, feats, emb);
    splitw_all<<<dim3(WMAT / 4 / 256, 8), 256>>>(Wq, Wk, Wv, W1, W2);

    const dim3 gw(MTOT / 128, DMODEL / 128);         // 128 x 4
    const dim3 gs(SEQ / 128, SEQ / 128, NBATCH);     // 16 x 16 x 8
    const dim3 ga(SEQ / 128, DMODEL / 128, NBATCH);  // 16 x 4 x 8

    for (int l = 0; l < 2; l++) {
        const int bo = l * DMODEL;
        const size_t mq = (size_t)(l ? 5 : 0) * WMAT;
        const size_t mk = (size_t)(l ? 6 : 1) * WMAT;
        const size_t mv = (size_t)(l ? 7 : 2) * WMAT;

        mma_gemm<0, 1><<<gw, 512, SMEM_TC>>>(xh, xl, wbh + mq, wbl + mq, bq + bo, nullptr, qh, ql,
                                             DMODEL, DMODEL, DMODEL, DMODEL, 0, 0, 0, 0.f);
        mma_gemm<0, 1><<<gw, 512, SMEM_TC>>>(xh, xl, wbh + mk, wbl + mk, bk + bo, nullptr, kh, kl,
                                             DMODEL, DMODEL, DMODEL, DMODEL, 0, 0, 0, 0.f);
        mma_gemm<0, 0><<<gw, 512, SMEM_TC>>>(xh, xl, wbh + mv, wbl + mv, bv + bo, v, nullptr, nullptr,
                                             DMODEL, DMODEL, DMODEL, DMODEL, 0, 0, 0, 0.f);

        transpose_split<<<dim3(SEQ / 32, DMODEL / 32, NBATCH), dim3(32, 8)>>>(v);

        mma_gemm<2, 1><<<gs, 512, SMEM_TC>>>(qh, ql, kh, kl, nullptr, nullptr, sch, scl,
                                             DMODEL, DMODEL, SEQ, DMODEL,
                                             (size_t)SEQ * DMODEL, (size_t)SEQ * DMODEL,
                                             (size_t)SEQ * SEQ, scale);
        mma_gemm<3, 0><<<ga, 512, SMEM_TC>>>(sch, scl, vth, vtl, nullptr, h, nullptr, nullptr,
                                             SEQ, SEQ, DMODEL, 0,
                                             (size_t)SEQ * SEQ, (size_t)DMODEL * SEQ,
                                             (size_t)SEQ * DMODEL, 0.f);

        stats_kernel<<<dim3(NBATCH, DMODEL / 32), dim3(32, 8)>>>(h);
        norm_split<<<MTOT * 128 / 256, 256>>>(h);

        if (l == 0) {
            const size_t m1 = 3 * (size_t)WMAT, m2 = 4 * (size_t)WMAT;
            mma_gemm<1, 1><<<gw, 512, SMEM_TC>>>(hnh, hnl, wbh + m1, wbl + m1, b1 + bo, nullptr, th, tl,
                                                 DMODEL, DMODEL, DMODEL, DMODEL, 0, 0, 0, 0.f);
            mma_gemm<0, 1><<<gw, 512, SMEM_TC>>>(th, tl, wbh + m2, wbl + m2, b2 + bo, nullptr, xh, xl,
                                                 DMODEL, DMODEL, DMODEL, DMODEL, 0, 0, 0, 0.f);
        } else {
            last_gather<<<16, 256>>>();
            small_gemm<true><<<16, 256>>>(last, W1 + (size_t)WMAT, b1 + bo, lt);
            small_gemm<false><<<16, 256>>>(lt, W2 + (size_t)WMAT, b2 + bo, out);
        }
    }
}

// round 8
// speedup vs baseline: 3.0321x; 1.0626x over previous
#include <cuda_runtime.h>
#include <cuda_bf16.h>
#include <math.h>
#include <stdint.h>

#define EMB_DIM 448
#define FEAT_DIM 64
#define DMODEL 512
#define NBATCH 8
#define SEQ 2048
#define MTOT (NBATCH * SEQ)
#define WMAT (DMODEL * DMODEL)
typedef __nv_bfloat16 bf16;

// -------- scratch (device globals) --------
static __device__ bf16 g_xh[MTOT * DMODEL], g_xl[MTOT * DMODEL];
static __device__ bf16 g_qh[MTOT * DMODEL], g_ql[MTOT * DMODEL];
static __device__ bf16 g_kh[MTOT * DMODEL], g_kl[MTOT * DMODEL];
static __device__ bf16 g_vth[MTOT * DMODEL], g_vtl[MTOT * DMODEL];
static __device__ bf16 g_hnh[MTOT * DMODEL], g_hnl[MTOT * DMODEL];
static __device__ bf16 g_th[MTOT * DMODEL], g_tl[MTOT * DMODEL];
static __device__ bf16 g_sch[(size_t)NBATCH * SEQ * SEQ], g_scl[(size_t)NBATCH * SEQ * SEQ];
static __device__ bf16 g_wbh[8 * WMAT], g_wbl[8 * WMAT];  // Wq0,Wk0,Wv0,W1_0,W2_0,Wq1,Wk1,Wv1
static __device__ float g_v[MTOT * DMODEL], g_h[MTOT * DMODEL];
static __device__ float g_last[NBATCH * DMODEL], g_lt[NBATCH * DMODEL];

__device__ __forceinline__ uint32_t smem_u32(const void* p) {
    uint32_t a;
    asm("{ .reg .u64 t; cvta.to.shared.u64 t, %1; cvt.u32.u64 %0, t; }" : "=r"(a) : "l"(p));
    return a;
}
#define SWZ(o) ((o) ^ ((((uint32_t)(o)) >> 3) & 0x70))
#define OFF_AHI 0u
#define OFF_ALO 16384u
#define OFF_BHI 32768u
#define OFF_BLO 49152u
#define STAGE_B 65536u
#define SMEM_TC 196608

__device__ __forceinline__ void ldm_x4(uint32_t* r, uint32_t addr) {
    asm volatile("ldmatrix.sync.aligned.m8n8.x4.shared.b16 {%0,%1,%2,%3}, [%4];"
                 : "=r"(r[0]), "=r"(r[1]), "=r"(r[2]), "=r"(r[3]) : "r"(addr));
}
__device__ __forceinline__ void mma16816(float* c, const uint32_t* a, const uint32_t* b) {
    asm volatile(
        "mma.sync.aligned.m16n8k16.row.col.f32.bf16.bf16.f32 "
        "{%0,%1,%2,%3}, {%4,%5,%6,%7}, {%8,%9}, {%0,%1,%2,%3};"
        : "+f"(c[0]), "+f"(c[1]), "+f"(c[2]), "+f"(c[3])
        : "r"(a[0]), "r"(a[1]), "r"(a[2]), "r"(a[3]), "r"(b[0]), "r"(b[1]));
}
__device__ __forceinline__ void cpa16(uint32_t dst, const void* src) {
    asm volatile("cp.async.cg.shared.global [%0], [%1], 16;" :: "r"(dst), "l"(src));
}
#define CPA_COMMIT() asm volatile("cp.async.commit_group;" ::: "memory")

__device__ __forceinline__ void split4(float4 f, uint2& h, uint2& l) {
    bf16 h0 = __float2bfloat16(f.x), h1 = __float2bfloat16(f.y);
    bf16 h2 = __float2bfloat16(f.z), h3 = __float2bfloat16(f.w);
    bf16 l0 = __float2bfloat16(f.x - __bfloat162float(h0));
    bf16 l1 = __float2bfloat16(f.y - __bfloat162float(h1));
    bf16 l2 = __float2bfloat16(f.z - __bfloat162float(h2));
    bf16 l3 = __float2bfloat16(f.w - __bfloat162float(h3));
    __nv_bfloat162 a, b, c, d;
    a.x = h0; a.y = h1; b.x = h2; b.y = h3;
    c.x = l0; c.y = l1; d.x = l2; d.y = l3;
    h.x = *(uint32_t*)&a; h.y = *(uint32_t*)&b;
    l.x = *(uint32_t*)&c; l.y = *(uint32_t*)&d;
}

// MODE: 0=bias->hi/lo, 1=bias+relu->hi/lo, 2=scores(scale+causal)->hi/lo,
//       3=plain,causal-K->fp32, 4=fused QKV (region-routed epilogue)
template <int MODE>
__global__ void __launch_bounds__(512) mma_gemm(const bf16* __restrict__ Ah, const bf16* __restrict__ Al,
                                                const bf16* __restrict__ Bh, const bf16* __restrict__ Bl,
                                                const float* __restrict__ bias, const float* __restrict__ bias2,
                                                const float* __restrict__ bias3,
                                                float* __restrict__ Cf, bf16* __restrict__ Ch, bf16* __restrict__ Cl,
                                                bf16* __restrict__ C2h, bf16* __restrict__ C2l,
                                                int lda, int ldb, int ldc, int Kfix,
                                                size_t sA, size_t sB, size_t sC, float scale) {
    extern __shared__ char smem[];
    const int tid = threadIdx.x, wid = tid >> 5, lane = tid & 31;
    const int bm = blockIdx.x, bn = blockIdx.y, bz = blockIdx.z;
    if (MODE == 2 && bn > bm) return;
    Ah += sA * bz + (size_t)bm * 128 * lda;
    Al += sA * bz + (size_t)bm * 128 * lda;
    Bh += sB * bz + (size_t)bn * 128 * ldb;
    Bl += sB * bz + (size_t)bn * 128 * ldb;
    const int K = (MODE == 3) ? (bm + 1) * 128 : Kfix;
    const int NC = K >> 6;
    const uint32_t sb = smem_u32(smem);
    const int wm = wid >> 2, wn = wid & 3;  // warp grid 4x4, warp tile 32x32
    const int lr = lane & 15, lc16 = (lane >> 4) * 16;

    float acc[2][4][4];
#pragma unroll
    for (int i = 0; i < 2; i++)
#pragma unroll
        for (int j = 0; j < 4; j++)
#pragma unroll
            for (int r = 0; r < 4; r++) acc[i][j][r] = 0.f;

#define STAGE_LOAD(S, CIDX) do { \
        uint32_t base_ = sb + (uint32_t)(S) * STAGE_B; \
        int koff_ = (CIDX) * 64; \
        _Pragma("unroll") \
        for (int j_ = 0; j_ < 2; j_++) { \
            int cc_ = tid + j_ * 512; \
            int r_ = cc_ >> 3, cg_ = cc_ & 7; \
            uint32_t so_ = SWZ((uint32_t)r_ * 128u + (uint32_t)cg_ * 16u); \
            size_t ga_ = (size_t)r_ * lda + koff_ + cg_ * 8; \
            size_t gb_ = (size_t)r_ * ldb + koff_ + cg_ * 8; \
            cpa16(base_ + OFF_AHI + so_, Ah + ga_); \
            cpa16(base_ + OFF_ALO + so_, Al + ga_); \
            cpa16(base_ + OFF_BHI + so_, Bh + gb_); \
            cpa16(base_ + OFF_BLO + so_, Bl + gb_); \
        } \
        CPA_COMMIT(); \
    } while (0)

    // fragment double buffers (indices constant-folded by full unroll)
    uint32_t ah[2][2][4], al[2][2][4], bh[2][4][2], bl[2][4][2];
#define LDFRAG(BUF, KS) do { \
        const uint32_t kb_ = (KS) * 32 + lc16; \
        _Pragma("unroll") \
        for (int mb_ = 0; mb_ < 2; mb_++) { \
            uint32_t ro_ = (uint32_t)(wm * 32 + mb_ * 16 + lr) * 128u + kb_; \
            ldm_x4(ah[BUF][mb_], base + OFF_AHI + SWZ(ro_)); \
            ldm_x4(al[BUF][mb_], base + OFF_ALO + SWZ(ro_)); \
        } \
        _Pragma("unroll") \
        for (int n2_ = 0; n2_ < 2; n2_++) { \
            uint32_t ro_ = (uint32_t)(wn * 32 + n2_ * 16 + lr) * 128u + kb_; \
            uint32_t t_[4]; \
            ldm_x4(t_, base + OFF_BHI + SWZ(ro_)); \
            bh[BUF][n2_ * 2][0] = t_[0]; bh[BUF][n2_ * 2][1] = t_[2]; \
            bh[BUF][n2_ * 2 + 1][0] = t_[1]; bh[BUF][n2_ * 2 + 1][1] = t_[3]; \
            ldm_x4(t_, base + OFF_BLO + SWZ(ro_)); \
            bl[BUF][n2_ * 2][0] = t_[0]; bl[BUF][n2_ * 2][1] = t_[2]; \
            bl[BUF][n2_ * 2 + 1][0] = t_[1]; bl[BUF][n2_ * 2 + 1][1] = t_[3]; \
        } \
    } while (0)

    STAGE_LOAD(0, 0);
    if (NC > 1) STAGE_LOAD(1, 1);

    for (int c = 0; c < NC; c++) {
        if (c + 1 < NC) asm volatile("cp.async.wait_group 1;" ::: "memory");
        else            asm volatile("cp.async.wait_group 0;" ::: "memory");
        __syncthreads();
        const uint32_t base = sb + (uint32_t)(((uint32_t)c) % 3u) * STAGE_B;
        LDFRAG(0, 0);
#pragma unroll
        for (int ks = 0; ks < 4; ks++) {
            const int cur = ks & 1;
            if (ks < 3) LDFRAG(!(ks & 1), ks + 1);  // prefetch next K-step's frags
#pragma unroll
            for (int mb = 0; mb < 2; mb++)
#pragma unroll
                for (int nb = 0; nb < 4; nb++)
                    mma16816(acc[mb][nb], ah[cur][mb], bh[cur][nb]);
#pragma unroll
            for (int mb = 0; mb < 2; mb++)
#pragma unroll
                for (int nb = 0; nb < 4; nb++)
                    mma16816(acc[mb][nb], ah[cur][mb], bl[cur][nb]);
#pragma unroll
            for (int mb = 0; mb < 2; mb++)
#pragma unroll
                for (int nb = 0; nb < 4; nb++)
                    mma16816(acc[mb][nb], al[cur][mb], bh[cur][nb]);
        }
        if (c + 2 < NC) STAGE_LOAD(((uint32_t)(c + 2)) % 3u, c + 2);
    }
#undef STAGE_LOAD
#undef LDFRAG

    if (MODE == 3) Cf += sC * bz;
    if (MODE == 2) { Ch += sC * bz; Cl += sC * bz; }
    const int g = lane >> 2, t4 = lane & 3;
    const int region = (MODE == 4) ? (bn >> 2) : 0;
#pragma unroll
    for (int mb = 0; mb < 2; mb++) {
        const int mbase = bm * 128 + wm * 32 + mb * 16 + g;
#pragma unroll
        for (int nb = 0; nb < 4; nb++) {
            const int n0 = bn * 128 + wn * 32 + nb * 8 + t4 * 2;
#pragma unroll
            for (int rr = 0; rr < 2; rr++) {
                const int m = mbase + rr * 8;
                float v0 = acc[mb][nb][rr * 2], v1 = acc[mb][nb][rr * 2 + 1];
                if (MODE == 0) { v0 += bias[n0]; v1 += bias[n0 + 1]; }
                if (MODE == 1) { v0 = fmaxf(v0 + bias[n0], 0.f); v1 = fmaxf(v1 + bias[n0 + 1], 0.f); }
                if (MODE == 2) {
                    v0 = (n0 <= m) ? v0 * scale : 0.f;
                    v1 = (n0 + 1 <= m) ? v1 * scale : 0.f;
                }
                if (MODE == 0 || MODE == 1 || MODE == 2) {
                    __nv_bfloat162 hv, lv;
                    hv.x = __float2bfloat16(v0);
                    hv.y = __float2bfloat16(v1);
                    lv.x = __float2bfloat16(v0 - __bfloat162float(hv.x));
                    lv.y = __float2bfloat16(v1 - __bfloat162float(hv.y));
                    *(__nv_bfloat162*)(Ch + (size_t)m * ldc + n0) = hv;
                    *(__nv_bfloat162*)(Cl + (size_t)m * ldc + n0) = lv;
                } else if (MODE == 3) {
                    *(float2*)(Cf + (size_t)m * ldc + n0) = make_float2(v0, v1);
                } else {  // MODE 4: region 0=Q, 1=K, 2=V
                    const int nl = n0 - (region << 9);
                    if (region == 0) {
                        v0 += bias[nl]; v1 += bias[nl + 1];
                        __nv_bfloat162 hv, lv;
                        hv.x = __float2bfloat16(v0); hv.y = __float2bfloat16(v1);
                        lv.x = __float2bfloat16(v0 - __bfloat162float(hv.x));
                        lv.y = __float2bfloat16(v1 - __bfloat162float(hv.y));
                        *(__nv_bfloat162*)(Ch + (size_t)m * DMODEL + nl) = hv;
                        *(__nv_bfloat162*)(Cl + (size_t)m * DMODEL + nl) = lv;
                    } else if (region == 1) {
                        v0 += bias2[nl]; v1 += bias2[nl + 1];
                        __nv_bfloat162 hv, lv;
                        hv.x = __float2bfloat16(v0); hv.y = __float2bfloat16(v1);
                        lv.x = __float2bfloat16(v0 - __bfloat162float(hv.x));
                        lv.y = __float2bfloat16(v1 - __bfloat162float(hv.y));
                        *(__nv_bfloat162*)(C2h + (size_t)m * DMODEL + nl) = hv;
                        *(__nv_bfloat162*)(C2l + (size_t)m * DMODEL + nl) = lv;
                    } else {
                        v0 += bias3[nl]; v1 += bias3[nl + 1];
                        *(float2*)(Cf + (size_t)m * DMODEL + nl) = make_float2(v0, v1);
                    }
                }
            }
        }
    }
}

// ---------------- elementwise / small kernels ----------------
__global__ __launch_bounds__(256) void gather_split(const int* __restrict__ seq,
                                                    const float* __restrict__ feats,
                                                    const float* __restrict__ emb) {
    int i = blockIdx.x * 256 + threadIdx.x;
    int row = i >> 7, d = (i & 127) << 2;
    float4 val;
    if (d < EMB_DIM) val = *(const float4*)(emb + (size_t)seq[row] * EMB_DIM + d);
    else val = *(const float4*)(feats + (size_t)row * FEAT_DIM + (d - EMB_DIM));
    uint2 h, l;
    split4(val, h, l);
    *(uint2*)(g_xh + ((size_t)row << 9) + d) = h;
    *(uint2*)(g_xl + ((size_t)row << 9) + d) = l;
}

__global__ __launch_bounds__(256) void splitw_all(const float* __restrict__ Wq,
                                                  const float* __restrict__ Wk,
                                                  const float* __restrict__ Wv,
                                                  const float* __restrict__ W1,
                                                  const float* __restrict__ W2) {
    int midx = blockIdx.y;
    const float* src;
    switch (midx) {
        case 0: src = Wq; break;
        case 1: src = Wk; break;
        case 2: src = Wv; break;
        case 3: src = W1; break;
        case 4: src = W2; break;
        case 5: src = Wq + WMAT; break;
        case 6: src = Wk + WMAT; break;
        default: src = Wv + WMAT; break;
    }
    int i = (blockIdx.x * 256 + threadIdx.x) << 2;
    float4 f = *(const float4*)(src + i);
    uint2 h, l;
    split4(f, h, l);
    *(uint2*)(g_wbh + (size_t)midx * WMAT + i) = h;
    *(uint2*)(g_wbl + (size_t)midx * WMAT + i) = l;
}

__global__ void transpose_split(const float* __restrict__ V) {
    __shared__ float tile[32][33];
    int b = blockIdx.z, s0 = blockIdx.x * 32, d0 = blockIdx.y * 32;
    const float* Vb = V + (size_t)b * SEQ * DMODEL;
    bf16* Vth = g_vth + (size_t)b * DMODEL * SEQ;
    bf16* Vtl = g_vtl + (size_t)b * DMODEL * SEQ;
    int tx = threadIdx.x, ty = threadIdx.y;
#pragma unroll
    for (int i = 0; i < 32; i += 8)
        tile[ty + i][tx] = Vb[(size_t)(s0 + ty + i) * DMODEL + d0 + tx];
    __syncthreads();
#pragma unroll
    for (int i = 0; i < 32; i += 8) {
        float v = tile[tx][ty + i];
        bf16 h = __float2bfloat16(v);
        bf16 l = __float2bfloat16(v - __bfloat162float(h));
        Vth[(size_t)(d0 + ty + i) * SEQ + s0 + tx] = h;
        Vtl[(size_t)(d0 + ty + i) * SEQ + s0 + tx] = l;
    }
}

// fused stats + normalize. LAST=1: only emit last row into g_last
template <int LAST>
__global__ void norm_fused(const float* __restrict__ H) {
    const int b = blockIdx.x, tx = threadIdx.x, ty = threadIdx.y;
    const int d = blockIdx.y * 32 + tx;
    float sum = 0.f, sq = 0.f;
    for (int s = ty; s < SEQ; s += 8) {
        float v = H[(size_t)(b * SEQ + s) * DMODEL + d];
        sum += v; sq += v * v;
    }
    __shared__ float ss[8][32], s2[8][32], smean[32], srstd[32];
    ss[ty][tx] = sum; s2[ty][tx] = sq;
    __syncthreads();
    if (ty == 0) {
#pragma unroll
        for (int r = 1; r < 8; r++) { sum += ss[r][tx]; sq += s2[r][tx]; }
        float mean = sum * (1.0f / SEQ);
        float var = fmaxf((sq - sum * mean) * (1.0f / (SEQ - 1)), 0.0f);
        smean[tx] = mean;
        srstd[tx] = 1.0f / (sqrtf(var) + 2e-5f);
    }
    __syncthreads();
    const float mean = smean[tx], rstd = srstd[tx];
    if (LAST) {
        if (ty == 7) {  // s = 2047 handled by ty==7
            float v = H[(size_t)(b * SEQ + SEQ - 1) * DMODEL + d];
            g_last[b * DMODEL + d] = (v - mean) * rstd;
        }
    } else {
        for (int s = ty; s < SEQ; s += 8) {
            float v = (H[(size_t)(b * SEQ + s) * DMODEL + d] - mean) * rstd;
            bf16 h = __float2bfloat16(v);
            bf16 l = __float2bfloat16(v - __bfloat162float(h));
            g_hnh[(size_t)(b * SEQ + s) * DMODEL + d] = h;
            g_hnl[(size_t)(b * SEQ + s) * DMODEL + d] = l;
        }
    }
}

template <bool RELU>
__global__ void small_gemm(const float* __restrict__ A, const float* __restrict__ W,
                           const float* __restrict__ bias, float* __restrict__ C) {
    int i = blockIdx.x * 256 + threadIdx.x;  // 4096
    int m = i >> 9, n = i & 511;
    const float* a = A + (size_t)m * DMODEL;
    const float* w = W + (size_t)n * DMODEL;
    float s = 0.f;
#pragma unroll 8
    for (int k2 = 0; k2 < DMODEL; k2 += 4) {
        float4 av = *(const float4*)(a + k2), wv = *(const float4*)(w + k2);
        s += av.x * wv.x + av.y * wv.y + av.z * wv.z + av.w * wv.w;
    }
    s += bias[n];
    if (RELU) s = fmaxf(s, 0.0f);
    C[i] = s;
}

extern "C" void kernel_launch(void* const* d_in, const int* in_sizes, int n_in,
                              void* d_out, int out_size) {
    const int* seq = (const int*)d_in[0];
    const float* feats = (const float*)d_in[1];
    const float* emb = (const float*)d_in[2];
    const float* Wq = (const float*)d_in[3];  const float* bq = (const float*)d_in[4];
    const float* Wk = (const float*)d_in[5];  const float* bk = (const float*)d_in[6];
    const float* Wv = (const float*)d_in[7];  const float* bv = (const float*)d_in[8];
    const float* W1 = (const float*)d_in[9];  const float* b1 = (const float*)d_in[10];
    const float* W2 = (const float*)d_in[11]; const float* b2 = (const float*)d_in[12];
    float* out = (float*)d_out;

    cudaFuncSetAttribute(mma_gemm<0>, cudaFuncAttributeMaxDynamicSharedMemorySize, SMEM_TC);
    cudaFuncSetAttribute(mma_gemm<1>, cudaFuncAttributeMaxDynamicSharedMemorySize, SMEM_TC);
    cudaFuncSetAttribute(mma_gemm<2>, cudaFuncAttributeMaxDynamicSharedMemorySize, SMEM_TC);
    cudaFuncSetAttribute(mma_gemm<3>, cudaFuncAttributeMaxDynamicSharedMemorySize, SMEM_TC);
    cudaFuncSetAttribute(mma_gemm<4>, cudaFuncAttributeMaxDynamicSharedMemorySize, SMEM_TC);

    void *pxh, *pxl, *pqh, *pql, *pkh, *pkl, *pvth, *pvtl, *phnh, *phnl, *pth, *ptl;
    void *psch, *pscl, *pwbh, *pwbl, *pv, *ph, *plast, *plt;
    cudaGetSymbolAddress(&pxh, g_xh);   cudaGetSymbolAddress(&pxl, g_xl);
    cudaGetSymbolAddress(&pqh, g_qh);   cudaGetSymbolAddress(&pql, g_ql);
    cudaGetSymbolAddress(&pkh, g_kh);   cudaGetSymbolAddress(&pkl, g_kl);
    cudaGetSymbolAddress(&pvth, g_vth); cudaGetSymbolAddress(&pvtl, g_vtl);
    cudaGetSymbolAddress(&phnh, g_hnh); cudaGetSymbolAddress(&phnl, g_hnl);
    cudaGetSymbolAddress(&pth, g_th);   cudaGetSymbolAddress(&ptl, g_tl);
    cudaGetSymbolAddress(&psch, g_sch); cudaGetSymbolAddress(&pscl, g_scl);
    cudaGetSymbolAddress(&pwbh, g_wbh); cudaGetSymbolAddress(&pwbl, g_wbl);
    cudaGetSymbolAddress(&pv, g_v);     cudaGetSymbolAddress(&ph, g_h);
    cudaGetSymbolAddress(&plast, g_last); cudaGetSymbolAddress(&plt, g_lt);
    bf16* xh = (bf16*)pxh;   bf16* xl = (bf16*)pxl;
    bf16* qh = (bf16*)pqh;   bf16* ql = (bf16*)pql;
    bf16* kh = (bf16*)pkh;   bf16* kl = (bf16*)pkl;
    bf16* vth = (bf16*)pvth; bf16* vtl = (bf16*)pvtl;
    bf16* hnh = (bf16*)phnh; bf16* hnl = (bf16*)phnl;
    bf16* th = (bf16*)pth;   bf16* tl = (bf16*)ptl;
    bf16* sch = (bf16*)psch; bf16* scl = (bf16*)pscl;
    bf16* wbh = (bf16*)pwbh; bf16* wbl = (bf16*)pwbl;
    float* v = (float*)pv;   float* h = (float*)ph;
    float* last = (float*)plast; float* lt = (float*)plt;

    const float scale = 0.044194173824159216f;  // 1/sqrt(512)

    gather_split<<<MTOT * 128 / 256, 256>>>(seq, feats, emb);
    splitw_all<<<dim3(WMAT / 4 / 256, 8), 256>>>(Wq, Wk, Wv, W1, W2);

    const dim3 gqkv(MTOT / 128, 1536 / 128);         // 128 x 12
    const dim3 gw(MTOT / 128, DMODEL / 128);         // 128 x 4
    const dim3 gs(SEQ / 128, SEQ / 128, NBATCH);     // 16 x 16 x 8
    const dim3 ga(SEQ / 128, DMODEL / 128, NBATCH);  // 16 x 4 x 8

    for (int l = 0; l < 2; l++) {
        const int bo = l * DMODEL;
        const size_t mqkv = (size_t)(l ? 5 : 0) * WMAT;

        mma_gemm<4><<<gqkv, 512, SMEM_TC>>>(xh, xl, wbh + mqkv, wbl + mqkv,
                                            bq + bo, bk + bo, bv + bo,
                                            v, qh, ql, kh, kl,
                                            DMODEL, DMODEL, DMODEL, DMODEL, 0, 0, 0, 0.f);

        transpose_split<<<dim3(SEQ / 32, DMODEL / 32, NBATCH), dim3(32, 8)>>>(v);

        mma_gemm<2><<<gs, 512, SMEM_TC>>>(qh, ql, kh, kl, nullptr, nullptr, nullptr,
                                          nullptr, sch, scl, nullptr, nullptr,
                                          DMODEL, DMODEL, SEQ, DMODEL,
                                          (size_t)SEQ * DMODEL, (size_t)SEQ * DMODEL,
                                          (size_t)SEQ * SEQ, scale);
        mma_gemm<3><<<ga, 512, SMEM_TC>>>(sch, scl, vth, vtl, nullptr, nullptr, nullptr,
                                          h, nullptr, nullptr, nullptr, nullptr,
                                          SEQ, SEQ, DMODEL, 0,
                                          (size_t)SEQ * SEQ, (size_t)DMODEL * SEQ,
                                          (size_t)SEQ * DMODEL, 0.f);

        if (l == 0) {
            norm_fused<0><<<dim3(NBATCH, DMODEL / 32), dim3(32, 8)>>>(h);
            const size_t m1 = 3 * (size_t)WMAT, m2 = 4 * (size_t)WMAT;
            mma_gemm<1><<<gw, 512, SMEM_TC>>>(hnh, hnl, wbh + m1, wbl + m1, b1 + bo, nullptr, nullptr,
                                              nullptr, th, tl, nullptr, nullptr,
                                              DMODEL, DMODEL, DMODEL, DMODEL, 0, 0, 0, 0.f);
            mma_gemm<0><<<gw, 512, SMEM_TC>>>(th, tl, wbh + m2, wbl + m2, b2 + bo, nullptr, nullptr,
                                              nullptr, xh, xl, nullptr, nullptr,
                                              DMODEL, DMODEL, DMODEL, DMODEL, 0, 0, 0, 0.f);
        } else {
            norm_fused<1><<<dim3(NBATCH, DMODEL / 32), dim3(32, 8)>>>(h);
            small_gemm<true><<<16, 256>>>(last, W1 + (size_t)WMAT, b1 + bo, lt);
            small_gemm<false><<<16, 256>>>(lt, W2 + (size_t)WMAT, b2 + bo, out);
        }
    }
}

// round 9
// speedup vs baseline: 4.3044x; 1.4196x over previous
#include <cuda_runtime.h>
#include <cuda_bf16.h>
#include <cuda_fp16.h>
#include <math.h>
#include <stdint.h>

#define EMB_DIM 448
#define FEAT_DIM 64
#define DMODEL 512
#define NBATCH 8
#define SEQ 2048
#define MTOT (NBATCH * SEQ)
#define WMAT (DMODEL * DMODEL)
typedef __nv_bfloat16 bf16;

// -------- scratch (device globals) --------
static __device__ bf16 g_xh[MTOT * DMODEL], g_xl[MTOT * DMODEL];
static __device__ bf16 g_hnh[MTOT * DMODEL], g_hnl[MTOT * DMODEL];
static __device__ bf16 g_th[MTOT * DMODEL], g_tl[MTOT * DMODEL];
static __device__ bf16 g_wbh[8 * WMAT], g_wbl[8 * WMAT];  // Wq0,Wk0,Wv0,W1_0,W2_0,Wq1,Wk1,Wv1
static __device__ __half g_qf[MTOT * DMODEL], g_kf[MTOT * DMODEL];
static __device__ __half g_vtf[MTOT * DMODEL];
static __device__ __half g_sf[(size_t)NBATCH * SEQ * SEQ];
static __device__ float g_v[MTOT * DMODEL], g_h[MTOT * DMODEL];
static __device__ float g_last[NBATCH * DMODEL], g_lt[NBATCH * DMODEL];

__device__ __forceinline__ uint32_t smem_u32(const void* p) {
    uint32_t a;
    asm("{ .reg .u64 t; cvta.to.shared.u64 t, %1; cvt.u32.u64 %0, t; }" : "=r"(a) : "l"(p));
    return a;
}
#define SWZ(o) ((o) ^ ((((uint32_t)(o)) >> 3) & 0x70))
#define OFF_AHI 0u
#define OFF_ALO 16384u
#define OFF_BHI 32768u
#define OFF_BLO 49152u
#define STAGE_B 65536u
#define SMEM_TC 196608
// attention kernel stages: A 32KB (256x128B) + B 16KB
#define AT_OFF_B 32768u
#define AT_STAGE 49152u
#define SMEM_AT 147456

__device__ __forceinline__ void ldm_x4(uint32_t* r, uint32_t addr) {
    asm volatile("ldmatrix.sync.aligned.m8n8.x4.shared.b16 {%0,%1,%2,%3}, [%4];"
                 : "=r"(r[0]), "=r"(r[1]), "=r"(r[2]), "=r"(r[3]) : "r"(addr));
}
__device__ __forceinline__ void mma16816(float* c, const uint32_t* a, const uint32_t* b) {
    asm volatile(
        "mma.sync.aligned.m16n8k16.row.col.f32.bf16.bf16.f32 "
        "{%0,%1,%2,%3}, {%4,%5,%6,%7}, {%8,%9}, {%0,%1,%2,%3};"
        : "+f"(c[0]), "+f"(c[1]), "+f"(c[2]), "+f"(c[3])
        : "r"(a[0]), "r"(a[1]), "r"(a[2]), "r"(a[3]), "r"(b[0]), "r"(b[1]));
}
__device__ __forceinline__ void mma16816h(float* c, const uint32_t* a, const uint32_t* b) {
    asm volatile(
        "mma.sync.aligned.m16n8k16.row.col.f32.f16.f16.f32 "
        "{%0,%1,%2,%3}, {%4,%5,%6,%7}, {%8,%9}, {%0,%1,%2,%3};"
        : "+f"(c[0]), "+f"(c[1]), "+f"(c[2]), "+f"(c[3])
        : "r"(a[0]), "r"(a[1]), "r"(a[2]), "r"(a[3]), "r"(b[0]), "r"(b[1]));
}
__device__ __forceinline__ void cpa16(uint32_t dst, const void* src) {
    asm volatile("cp.async.cg.shared.global [%0], [%1], 16;" :: "r"(dst), "l"(src));
}
#define CPA_COMMIT() asm volatile("cp.async.commit_group;" ::: "memory")

__device__ __forceinline__ void split4(float4 f, uint2& h, uint2& l) {
    bf16 h0 = __float2bfloat16(f.x), h1 = __float2bfloat16(f.y);
    bf16 h2 = __float2bfloat16(f.z), h3 = __float2bfloat16(f.w);
    bf16 l0 = __float2bfloat16(f.x - __bfloat162float(h0));
    bf16 l1 = __float2bfloat16(f.y - __bfloat162float(h1));
    bf16 l2 = __float2bfloat16(f.z - __bfloat162float(h2));
    bf16 l3 = __float2bfloat16(f.w - __bfloat162float(h3));
    __nv_bfloat162 a, b, c, d;
    a.x = h0; a.y = h1; b.x = h2; b.y = h3;
    c.x = l0; c.y = l1; d.x = l2; d.y = l3;
    h.x = *(uint32_t*)&a; h.y = *(uint32_t*)&b;
    l.x = *(uint32_t*)&c; l.y = *(uint32_t*)&d;
}

// ============ bf16x3 GEMM (projections / MLP) ============
// MODE: 0=bias->hi/lo, 1=bias+relu->hi/lo, 4=fused QKV (Q,K->fp16; V->fp32)
template <int MODE>
__global__ void __launch_bounds__(512) mma_gemm(const bf16* __restrict__ Ah, const bf16* __restrict__ Al,
                                                const bf16* __restrict__ Bh, const bf16* __restrict__ Bl,
                                                const float* __restrict__ bias, const float* __restrict__ bias2,
                                                const float* __restrict__ bias3,
                                                float* __restrict__ Cf, bf16* __restrict__ Ch, bf16* __restrict__ Cl,
                                                bf16* __restrict__ C2h,
                                                int lda, int ldb, int ldc, int Kfix) {
    extern __shared__ char smem[];
    const int tid = threadIdx.x, wid = tid >> 5, lane = tid & 31;
    const int bm = blockIdx.x, bn = blockIdx.y;
    Ah += (size_t)bm * 128 * lda;
    Al += (size_t)bm * 128 * lda;
    Bh += (size_t)bn * 128 * ldb;
    Bl += (size_t)bn * 128 * ldb;
    const int NC = Kfix >> 6;
    const uint32_t sb = smem_u32(smem);
    const int wm = wid >> 2, wn = wid & 3;
    const int lr = lane & 15, lc16 = (lane >> 4) * 16;

    float acc[2][4][4];
#pragma unroll
    for (int i = 0; i < 2; i++)
#pragma unroll
        for (int j = 0; j < 4; j++)
#pragma unroll
            for (int r = 0; r < 4; r++) acc[i][j][r] = 0.f;

#define STAGE_LOAD(S, CIDX) do { \
        uint32_t base_ = sb + (uint32_t)(S) * STAGE_B; \
        int koff_ = (CIDX) * 64; \
        _Pragma("unroll") \
        for (int j_ = 0; j_ < 2; j_++) { \
            int cc_ = tid + j_ * 512; \
            int r_ = cc_ >> 3, cg_ = cc_ & 7; \
            uint32_t so_ = SWZ((uint32_t)r_ * 128u + (uint32_t)cg_ * 16u); \
            size_t ga_ = (size_t)r_ * lda + koff_ + cg_ * 8; \
            size_t gb_ = (size_t)r_ * ldb + koff_ + cg_ * 8; \
            cpa16(base_ + OFF_AHI + so_, Ah + ga_); \
            cpa16(base_ + OFF_ALO + so_, Al + ga_); \
            cpa16(base_ + OFF_BHI + so_, Bh + gb_); \
            cpa16(base_ + OFF_BLO + so_, Bl + gb_); \
        } \
        CPA_COMMIT(); \
    } while (0)

    uint32_t ah[2][2][4], al[2][2][4], bh[2][4][2], bl[2][4][2];
#define LDFRAG(BUF, KS) do { \
        const uint32_t kb_ = (KS) * 32 + lc16; \
        _Pragma("unroll") \
        for (int mb_ = 0; mb_ < 2; mb_++) { \
            uint32_t ro_ = (uint32_t)(wm * 32 + mb_ * 16 + lr) * 128u + kb_; \
            ldm_x4(ah[BUF][mb_], base + OFF_AHI + SWZ(ro_)); \
            ldm_x4(al[BUF][mb_], base + OFF_ALO + SWZ(ro_)); \
        } \
        _Pragma("unroll") \
        for (int n2_ = 0; n2_ < 2; n2_++) { \
            uint32_t ro_ = (uint32_t)(wn * 32 + n2_ * 16 + lr) * 128u + kb_; \
            uint32_t t_[4]; \
            ldm_x4(t_, base + OFF_BHI + SWZ(ro_)); \
            bh[BUF][n2_ * 2][0] = t_[0]; bh[BUF][n2_ * 2][1] = t_[2]; \
            bh[BUF][n2_ * 2 + 1][0] = t_[1]; bh[BUF][n2_ * 2 + 1][1] = t_[3]; \
            ldm_x4(t_, base + OFF_BLO + SWZ(ro_)); \
            bl[BUF][n2_ * 2][0] = t_[0]; bl[BUF][n2_ * 2][1] = t_[2]; \
            bl[BUF][n2_ * 2 + 1][0] = t_[1]; bl[BUF][n2_ * 2 + 1][1] = t_[3]; \
        } \
    } while (0)

    STAGE_LOAD(0, 0);
    if (NC > 1) STAGE_LOAD(1, 1);

    for (int c = 0; c < NC; c++) {
        if (c + 1 < NC) asm volatile("cp.async.wait_group 1;" ::: "memory");
        else            asm volatile("cp.async.wait_group 0;" ::: "memory");
        __syncthreads();
        const uint32_t base = sb + (uint32_t)(((uint32_t)c) % 3u) * STAGE_B;
        LDFRAG(0, 0);
#pragma unroll
        for (int ks = 0; ks < 4; ks++) {
            const int cur = ks & 1;
            if (ks < 3) LDFRAG(!(ks & 1), ks + 1);
#pragma unroll
            for (int mb = 0; mb < 2; mb++)
#pragma unroll
                for (int nb = 0; nb < 4; nb++)
                    mma16816(acc[mb][nb], ah[cur][mb], bh[cur][nb]);
#pragma unroll
            for (int mb = 0; mb < 2; mb++)
#pragma unroll
                for (int nb = 0; nb < 4; nb++)
                    mma16816(acc[mb][nb], ah[cur][mb], bl[cur][nb]);
#pragma unroll
            for (int mb = 0; mb < 2; mb++)
#pragma unroll
                for (int nb = 0; nb < 4; nb++)
                    mma16816(acc[mb][nb], al[cur][mb], bh[cur][nb]);
        }
        if (c + 2 < NC) STAGE_LOAD(((uint32_t)(c + 2)) % 3u, c + 2);
    }
#undef STAGE_LOAD
#undef LDFRAG

    const int g = lane >> 2, t4 = lane & 3;
    const int region = (MODE == 4) ? (bn >> 2) : 0;
#pragma unroll
    for (int mb = 0; mb < 2; mb++) {
        const int mbase = bm * 128 + wm * 32 + mb * 16 + g;
#pragma unroll
        for (int nb = 0; nb < 4; nb++) {
            const int n0 = bn * 128 + wn * 32 + nb * 8 + t4 * 2;
#pragma unroll
            for (int rr = 0; rr < 2; rr++) {
                const int m = mbase + rr * 8;
                float v0 = acc[mb][nb][rr * 2], v1 = acc[mb][nb][rr * 2 + 1];
                if (MODE == 0) { v0 += bias[n0]; v1 += bias[n0 + 1]; }
                if (MODE == 1) { v0 = fmaxf(v0 + bias[n0], 0.f); v1 = fmaxf(v1 + bias[n0 + 1], 0.f); }
                if (MODE == 0 || MODE == 1) {
                    __nv_bfloat162 hv, lv;
                    hv.x = __float2bfloat16(v0);
                    hv.y = __float2bfloat16(v1);
                    lv.x = __float2bfloat16(v0 - __bfloat162float(hv.x));
                    lv.y = __float2bfloat16(v1 - __bfloat162float(hv.y));
                    *(__nv_bfloat162*)(Ch + (size_t)m * ldc + n0) = hv;
                    *(__nv_bfloat162*)(Cl + (size_t)m * ldc + n0) = lv;
                } else {  // MODE 4: region 0=Q(fp16), 1=K(fp16), 2=V(fp32)
                    const int nl = n0 - (region << 9);
                    if (region == 0) {
                        *(__half2*)((__half*)Ch + (size_t)m * DMODEL + nl) =
                            __floats2half2_rn(v0 + bias[nl], v1 + bias[nl + 1]);
                    } else if (region == 1) {
                        *(__half2*)((__half*)C2h + (size_t)m * DMODEL + nl) =
                            __floats2half2_rn(v0 + bias2[nl], v1 + bias2[nl + 1]);
                    } else {
                        *(float2*)(Cf + (size_t)m * DMODEL + nl) =
                            make_float2(v0 + bias3[nl], v1 + bias3[nl + 1]);
                    }
                }
            }
        }
    }
}

// ============ fp16 single-pass attention GEMM ============
// MODE 0: scores = tril(QK^T)*scale -> fp16 ; MODE 1: h = S @ Vt^T -> fp32 (causal K bound)
// CTA 256x128, 512 thr, warp grid 4x4, warp tile 64x32
template <int MODE>
__global__ void __launch_bounds__(512) mma_attn(const __half* __restrict__ A, const __half* __restrict__ B,
                                                __half* __restrict__ Sout, float* __restrict__ Hout,
                                                int lda, int ldb,
                                                size_t sA, size_t sB, size_t sC, float scale) {
    extern __shared__ char smem[];
    const int tid = threadIdx.x, wid = tid >> 5, lane = tid & 31;
    const int bm = blockIdx.x, bn = blockIdx.y, bz = blockIdx.z;
    if (MODE == 0 && bn > 2 * bm + 1) return;  // fully-masked score tile
    A += sA * bz + (size_t)bm * 256 * lda;
    B += sB * bz + (size_t)bn * 128 * ldb;
    const int NC = (MODE == 1) ? (bm + 1) * 4 : 8;
    const uint32_t sb = smem_u32(smem);
    const int wm = wid >> 2, wn = wid & 3;
    const int lr = lane & 15, lc16 = (lane >> 4) * 16;

    float acc[4][4][4];
#pragma unroll
    for (int i = 0; i < 4; i++)
#pragma unroll
        for (int j = 0; j < 4; j++)
#pragma unroll
            for (int r = 0; r < 4; r++) acc[i][j][r] = 0.f;

#define AT_LOAD(S, CIDX) do { \
        uint32_t base_ = sb + (uint32_t)(S) * AT_STAGE; \
        int koff_ = (CIDX) * 64; \
        _Pragma("unroll") \
        for (int j_ = 0; j_ < 4; j_++) { \
            int cc_ = tid + j_ * 512; \
            int r_ = cc_ >> 3, cg_ = cc_ & 7; \
            cpa16(base_ + SWZ((uint32_t)r_ * 128u + (uint32_t)cg_ * 16u), \
                  A + (size_t)r_ * lda + koff_ + cg_ * 8); \
        } \
        _Pragma("unroll") \
        for (int j_ = 0; j_ < 2; j_++) { \
            int cc_ = tid + j_ * 512; \
            int r_ = cc_ >> 3, cg_ = cc_ & 7; \
            cpa16(base_ + AT_OFF_B + SWZ((uint32_t)r_ * 128u + (uint32_t)cg_ * 16u), \
                  B + (size_t)r_ * ldb + koff_ + cg_ * 8); \
        } \
        CPA_COMMIT(); \
    } while (0)

    AT_LOAD(0, 0);
    if (NC > 1) AT_LOAD(1, 1);

    for (int c = 0; c < NC; c++) {
        if (c + 1 < NC) asm volatile("cp.async.wait_group 1;" ::: "memory");
        else            asm volatile("cp.async.wait_group 0;" ::: "memory");
        __syncthreads();
        const uint32_t base = sb + (uint32_t)(((uint32_t)c) % 3u) * AT_STAGE;
#pragma unroll
        for (int ks = 0; ks < 4; ks++) {
            const uint32_t kb = ks * 32 + lc16;
            uint32_t ah[4][4], bh[4][2];
#pragma unroll
            for (int mb = 0; mb < 4; mb++) {
                uint32_t ro = (uint32_t)(wm * 64 + mb * 16 + lr) * 128u + kb;
                ldm_x4(ah[mb], base + SWZ(ro));
            }
#pragma unroll
            for (int n2 = 0; n2 < 2; n2++) {
                uint32_t ro = (uint32_t)(wn * 32 + n2 * 16 + lr) * 128u + kb;
                uint32_t t[4];
                ldm_x4(t, base + AT_OFF_B + SWZ(ro));
                bh[n2 * 2][0] = t[0]; bh[n2 * 2][1] = t[2];
                bh[n2 * 2 + 1][0] = t[1]; bh[n2 * 2 + 1][1] = t[3];
            }
#pragma unroll
            for (int mb = 0; mb < 4; mb++)
#pragma unroll
                for (int nb = 0; nb < 4; nb++)
                    mma16816h(acc[mb][nb], ah[mb], bh[nb]);
        }
        if (c + 2 < NC) AT_LOAD(((uint32_t)(c + 2)) % 3u, c + 2);
    }
#undef AT_LOAD

    const int g = lane >> 2, t4 = lane & 3;
    if (MODE == 0) Sout += sC * bz;
    else           Hout += sC * bz;
#pragma unroll
    for (int mb = 0; mb < 4; mb++) {
        const int mbase = bm * 256 + wm * 64 + mb * 16 + g;
#pragma unroll
        for (int nb = 0; nb < 4; nb++) {
            const int n0 = bn * 128 + wn * 32 + nb * 8 + t4 * 2;
#pragma unroll
            for (int rr = 0; rr < 2; rr++) {
                const int m = mbase + rr * 8;
                float v0 = acc[mb][nb][rr * 2], v1 = acc[mb][nb][rr * 2 + 1];
                if (MODE == 0) {
                    v0 = (n0 <= m) ? v0 * scale : 0.f;
                    v1 = (n0 + 1 <= m) ? v1 * scale : 0.f;
                    *(__half2*)(Sout + (size_t)m * SEQ + n0) = __floats2half2_rn(v0, v1);
                } else {
                    *(float2*)(Hout + (size_t)m * DMODEL + n0) = make_float2(v0, v1);
                }
            }
        }
    }
}

// ---------------- elementwise / small kernels ----------------
__global__ __launch_bounds__(256) void gather_split(const int* __restrict__ seq,
                                                    const float* __restrict__ feats,
                                                    const float* __restrict__ emb) {
    int i = blockIdx.x * 256 + threadIdx.x;
    int row = i >> 7, d = (i & 127) << 2;
    float4 val;
    if (d < EMB_DIM) val = *(const float4*)(emb + (size_t)seq[row] * EMB_DIM + d);
    else val = *(const float4*)(feats + (size_t)row * FEAT_DIM + (d - EMB_DIM));
    uint2 h, l;
    split4(val, h, l);
    *(uint2*)(g_xh + ((size_t)row << 9) + d) = h;
    *(uint2*)(g_xl + ((size_t)row << 9) + d) = l;
}

__global__ __launch_bounds__(256) void splitw_all(const float* __restrict__ Wq,
                                                  const float* __restrict__ Wk,
                                                  const float* __restrict__ Wv,
                                                  const float* __restrict__ W1,
                                                  const float* __restrict__ W2) {
    int midx = blockIdx.y;
    const float* src;
    switch (midx) {
        case 0: src = Wq; break;
        case 1: src = Wk; break;
        case 2: src = Wv; break;
        case 3: src = W1; break;
        case 4: src = W2; break;
        case 5: src = Wq + WMAT; break;
        case 6: src = Wk + WMAT; break;
        default: src = Wv + WMAT; break;
    }
    int i = (blockIdx.x * 256 + threadIdx.x) << 2;
    float4 f = *(const float4*)(src + i);
    uint2 h, l;
    split4(f, h, l);
    *(uint2*)(g_wbh + (size_t)midx * WMAT + i) = h;
    *(uint2*)(g_wbl + (size_t)midx * WMAT + i) = l;
}

__global__ void transpose_half(const float* __restrict__ V) {
    __shared__ float tile[32][33];
    int b = blockIdx.z, s0 = blockIdx.x * 32, d0 = blockIdx.y * 32;
    const float* Vb = V + (size_t)b * SEQ * DMODEL;
    __half* Vt = g_vtf + (size_t)b * DMODEL * SEQ;
    int tx = threadIdx.x, ty = threadIdx.y;
#pragma unroll
    for (int i = 0; i < 32; i += 8)
        tile[ty + i][tx] = Vb[(size_t)(s0 + ty + i) * DMODEL + d0 + tx];
    __syncthreads();
#pragma unroll
    for (int i = 0; i < 32; i += 8)
        Vt[(size_t)(d0 + ty + i) * SEQ + s0 + tx] = __float2half(tile[tx][ty + i]);
}

// fused stats + normalize. LAST=1: only emit last row into g_last
template <int LAST>
__global__ void norm_fused(const float* __restrict__ H) {
    const int b = blockIdx.x, tx = threadIdx.x, ty = threadIdx.y;
    const int d = blockIdx.y * 32 + tx;
    float sum = 0.f, sq = 0.f;
    for (int s = ty; s < SEQ; s += 8) {
        float v = H[(size_t)(b * SEQ + s) * DMODEL + d];
        sum += v; sq += v * v;
    }
    __shared__ float ss[8][32], s2[8][32], smean[32], srstd[32];
    ss[ty][tx] = sum; s2[ty][tx] = sq;
    __syncthreads();
    if (ty == 0) {
#pragma unroll
        for (int r = 1; r < 8; r++) { sum += ss[r][tx]; sq += s2[r][tx]; }
        float mean = sum * (1.0f / SEQ);
        float var = fmaxf((sq - sum * mean) * (1.0f / (SEQ - 1)), 0.0f);
        smean[tx] = mean;
        srstd[tx] = 1.0f / (sqrtf(var) + 2e-5f);
    }
    __syncthreads();
    const float mean = smean[tx], rstd = srstd[tx];
    if (LAST) {
        if (ty == 7) {
            float v = H[(size_t)(b * SEQ + SEQ - 1) * DMODEL + d];
            g_last[b * DMODEL + d] = (v - mean) * rstd;
        }
    } else {
        for (int s = ty; s < SEQ; s += 8) {
            float v = (H[(size_t)(b * SEQ + s) * DMODEL + d] - mean) * rstd;
            bf16 h = __float2bfloat16(v);
            bf16 l = __float2bfloat16(v - __bfloat162float(h));
            g_hnh[(size_t)(b * SEQ + s) * DMODEL + d] = h;
            g_hnl[(size_t)(b * SEQ + s) * DMODEL + d] = l;
        }
    }
}

template <bool RELU>
__global__ void small_gemm(const float* __restrict__ A, const float* __restrict__ W,
                           const float* __restrict__ bias, float* __restrict__ C) {
    int i = blockIdx.x * 256 + threadIdx.x;  // 4096
    int m = i >> 9, n = i & 511;
    const float* a = A + (size_t)m * DMODEL;
    const float* w = W + (size_t)n * DMODEL;
    float s = 0.f;
#pragma unroll 8
    for (int k2 = 0; k2 < DMODEL; k2 += 4) {
        float4 av = *(const float4*)(a + k2), wv = *(const float4*)(w + k2);
        s += av.x * wv.x + av.y * wv.y + av.z * wv.z + av.w * wv.w;
    }
    s += bias[n];
    if (RELU) s = fmaxf(s, 0.0f);
    C[i] = s;
}

extern "C" void kernel_launch(void* const* d_in, const int* in_sizes, int n_in,
                              void* d_out, int out_size) {
    const int* seq = (const int*)d_in[0];
    const float* feats = (const float*)d_in[1];
    const float* emb = (const float*)d_in[2];
    const float* Wq = (const float*)d_in[3];  const float* bq = (const float*)d_in[4];
    const float* Wk = (const float*)d_in[5];  const float* bk = (const float*)d_in[6];
    const float* Wv = (const float*)d_in[7];  const float* bv = (const float*)d_in[8];
    const float* W1 = (const float*)d_in[9];  const float* b1 = (const float*)d_in[10];
    const float* W2 = (const float*)d_in[11]; const float* b2 = (const float*)d_in[12];
    float* out = (float*)d_out;

    cudaFuncSetAttribute(mma_gemm<0>, cudaFuncAttributeMaxDynamicSharedMemorySize, SMEM_TC);
    cudaFuncSetAttribute(mma_gemm<1>, cudaFuncAttributeMaxDynamicSharedMemorySize, SMEM_TC);
    cudaFuncSetAttribute(mma_gemm<4>, cudaFuncAttributeMaxDynamicSharedMemorySize, SMEM_TC);
    cudaFuncSetAttribute(mma_attn<0>, cudaFuncAttributeMaxDynamicSharedMemorySize, SMEM_AT);
    cudaFuncSetAttribute(mma_attn<1>, cudaFuncAttributeMaxDynamicSharedMemorySize, SMEM_AT);

    void *pxh, *pxl, *phnh, *phnl, *pth, *ptl, *pwbh, *pwbl;
    void *pqf, *pkf, *pvtf, *psf, *pv, *ph, *plast, *plt;
    cudaGetSymbolAddress(&pxh, g_xh);   cudaGetSymbolAddress(&pxl, g_xl);
    cudaGetSymbolAddress(&phnh, g_hnh); cudaGetSymbolAddress(&phnl, g_hnl);
    cudaGetSymbolAddress(&pth, g_th);   cudaGetSymbolAddress(&ptl, g_tl);
    cudaGetSymbolAddress(&pwbh, g_wbh); cudaGetSymbolAddress(&pwbl, g_wbl);
    cudaGetSymbolAddress(&pqf, g_qf);   cudaGetSymbolAddress(&pkf, g_kf);
    cudaGetSymbolAddress(&pvtf, g_vtf); cudaGetSymbolAddress(&psf, g_sf);
    cudaGetSymbolAddress(&pv, g_v);     cudaGetSymbolAddress(&ph, g_h);
    cudaGetSymbolAddress(&plast, g_last); cudaGetSymbolAddress(&plt, g_lt);
    bf16* xh = (bf16*)pxh;   bf16* xl = (bf16*)pxl;
    bf16* hnh = (bf16*)phnh; bf16* hnl = (bf16*)phnl;
    bf16* th = (bf16*)pth;   bf16* tl = (bf16*)ptl;
    bf16* wbh = (bf16*)pwbh; bf16* wbl = (bf16*)pwbl;
    __half* qf = (__half*)pqf;  __half* kf = (__half*)pkf;
    __half* vtf = (__half*)pvtf; __half* sf = (__half*)psf;
    float* v = (float*)pv;   float* h = (float*)ph;
    float* last = (float*)plast; float* lt = (float*)plt;

    const float scale = 0.044194173824159216f;  // 1/sqrt(512)

    gather_split<<<MTOT * 128 / 256, 256>>>(seq, feats, emb);
    splitw_all<<<dim3(WMAT / 4 / 256, 8), 256>>>(Wq, Wk, Wv, W1, W2);

    const dim3 gqkv(MTOT / 128, 1536 / 128);         // 128 x 12
    const dim3 gw(MTOT / 128, DMODEL / 128);         // 128 x 4
    const dim3 gs(SEQ / 256, SEQ / 128, NBATCH);     // 8 x 16 x 8
    const dim3 ga(SEQ / 256, DMODEL / 128, NBATCH);  // 8 x 4 x 8

    for (int l = 0; l < 2; l++) {
        const int bo = l * DMODEL;
        const size_t mqkv = (size_t)(l ? 5 : 0) * WMAT;

        mma_gemm<4><<<gqkv, 512, SMEM_TC>>>(xh, xl, wbh + mqkv, wbl + mqkv,
                                            bq + bo, bk + bo, bv + bo,
                                            v, (bf16*)qf, nullptr, (bf16*)kf,
                                            DMODEL, DMODEL, DMODEL, DMODEL);

        transpose_half<<<dim3(SEQ / 32, DMODEL / 32, NBATCH), dim3(32, 8)>>>(v);

        mma_attn<0><<<gs, 512, SMEM_AT>>>(qf, kf, sf, nullptr, DMODEL, DMODEL,
                                          (size_t)SEQ * DMODEL, (size_t)SEQ * DMODEL,
                                          (size_t)SEQ * SEQ, scale);
        mma_attn<1><<<ga, 512, SMEM_AT>>>(sf, vtf, nullptr, h, SEQ, SEQ,
                                          (size_t)SEQ * SEQ, (size_t)DMODEL * SEQ,
                                          (size_t)SEQ * DMODEL, 0.f);

        if (l == 0) {
            norm_fused<0><<<dim3(NBATCH, DMODEL / 32), dim3(32, 8)>>>(h);
            const size_t m1 = 3 * (size_t)WMAT, m2 = 4 * (size_t)WMAT;
            mma_gemm<1><<<gw, 512, SMEM_TC>>>(hnh, hnl, wbh + m1, wbl + m1, b1 + bo, nullptr, nullptr,
                                              nullptr, th, tl, nullptr,
                                              DMODEL, DMODEL, DMODEL, DMODEL);
            mma_gemm<0><<<gw, 512, SMEM_TC>>>(th, tl, wbh + m2, wbl + m2, b2 + bo, nullptr, nullptr,
                                              nullptr, xh, xl, nullptr,
                                              DMODEL, DMODEL, DMODEL, DMODEL);
        } else {
            norm_fused<1><<<dim3(NBATCH, DMODEL / 32), dim3(32, 8)>>>(h);
            small_gemm<true><<<16, 256>>>(last, W1 + (size_t)WMAT, b1 + bo, lt);
            small_gemm<false><<<16, 256>>>(lt, W2 + (size_t)WMAT, b2 + bo, out);
        }
    }
}

// round 11
// speedup vs baseline: 4.5888x; 1.0661x over previous
#include <cuda_runtime.h>
#include <cuda_fp16.h>
#include <math.h>
#include <stdint.h>

#define EMB_DIM 448
#define FEAT_DIM 64
#define DMODEL 512
#define NBATCH 8
#define SEQ 2048
#define MTOT (NBATCH * SEQ)
#define WMAT (DMODEL * DMODEL)

// -------- scratch (device globals) --------
static __device__ __half g_xh[MTOT * DMODEL], g_xl[MTOT * DMODEL];
static __device__ __half g_hnh[MTOT * DMODEL], g_hnl[MTOT * DMODEL];
static __device__ __half g_th[MTOT * DMODEL], g_tl[MTOT * DMODEL];
static __device__ __half g_wfh[8 * WMAT], g_wfl[8 * WMAT];  // fp16 hi/lo weights
static __device__ __half g_qf[MTOT * DMODEL], g_kf[MTOT * DMODEL];
static __device__ __half g_vf[MTOT * DMODEL], g_vtf[MTOT * DMODEL];
static __device__ __half g_sf[(size_t)NBATCH * SEQ * SEQ];
static __device__ float g_h[MTOT * DMODEL];
static __device__ float g_last[NBATCH * DMODEL], g_lt[NBATCH * DMODEL];

__device__ __forceinline__ uint32_t smem_u32(const void* p) {
    uint32_t a;
    asm("{ .reg .u64 t; cvta.to.shared.u64 t, %1; cvt.u32.u64 %0, t; }" : "=r"(a) : "l"(p));
    return a;
}
#define SWZ(o) ((o) ^ ((((uint32_t)(o)) >> 3) & 0x70))
// projection GEMM stage: Ahi 16K | Alo 16K | Bhi 16K | Blo 16K
#define OFF_ALO 16384u
#define OFF_BHI 32768u
#define OFF_BLO 49152u
#define STAGE_B 65536u
#define SMEM_TC 196608
// attention stages: A 32K (256 rows) + B 16K
#define AT_OFF_B 32768u
#define AT_STAGE 49152u
#define SMEM_AT 147456

__device__ __forceinline__ void ldm_x4(uint32_t* r, uint32_t addr) {
    asm volatile("ldmatrix.sync.aligned.m8n8.x4.shared.b16 {%0,%1,%2,%3}, [%4];"
                 : "=r"(r[0]), "=r"(r[1]), "=r"(r[2]), "=r"(r[3]) : "r"(addr));
}
__device__ __forceinline__ void mma16816h(float* c, const uint32_t* a, const uint32_t* b) {
    asm volatile(
        "mma.sync.aligned.m16n8k16.row.col.f32.f16.f16.f32 "
        "{%0,%1,%2,%3}, {%4,%5,%6,%7}, {%8,%9}, {%0,%1,%2,%3};"
        : "+f"(c[0]), "+f"(c[1]), "+f"(c[2]), "+f"(c[3])
        : "r"(a[0]), "r"(a[1]), "r"(a[2]), "r"(a[3]), "r"(b[0]), "r"(b[1]));
}
__device__ __forceinline__ void cpa16(uint32_t dst, const void* src) {
    asm volatile("cp.async.cg.shared.global [%0], [%1], 16;" :: "r"(dst), "l"(src));
}
#define CPA_COMMIT() asm volatile("cp.async.commit_group;" ::: "memory")

__device__ __forceinline__ void split4h(float4 f, uint2& h, uint2& l) {
    __half2 h0 = __floats2half2_rn(f.x, f.y);
    __half2 h1 = __floats2half2_rn(f.z, f.w);
    __half2 l0 = __floats2half2_rn(f.x - __half2float(h0.x), f.y - __half2float(h0.y));
    __half2 l1 = __floats2half2_rn(f.z - __half2float(h1.x), f.w - __half2float(h1.y));
    h.x = *(uint32_t*)&h0; h.y = *(uint32_t*)&h1;
    l.x = *(uint32_t*)&l0; l.y = *(uint32_t*)&l1;
}

// ============ fp16 split projection/MLP GEMM ============
// A = Ah+Al (fp16 hi/lo), W = Wh (+Wl if PASSES==3). K = DMODEL fixed.
// MODE: 0=bias->hi/lo, 1=bias+relu->hi/lo, 4=fused QKV (Q,K,V all fp16)
template <int MODE, int PASSES>
__global__ void __launch_bounds__(512) mma_gemm(const __half* __restrict__ Ah, const __half* __restrict__ Al,
                                                const __half* __restrict__ Bh, const __half* __restrict__ Bl,
                                                const float* __restrict__ bias, const float* __restrict__ bias2,
                                                const float* __restrict__ bias3,
                                                __half* __restrict__ Ch, __half* __restrict__ Cl,
                                                __half* __restrict__ C2h, __half* __restrict__ C3h) {
    extern __shared__ char smem[];
    const int tid = threadIdx.x, wid = tid >> 5, lane = tid & 31;
    const int bm = blockIdx.x, bn = blockIdx.y;
    Ah += (size_t)bm * 128 * DMODEL;
    Al += (size_t)bm * 128 * DMODEL;
    Bh += (size_t)bn * 128 * DMODEL;
    Bl += (size_t)bn * 128 * DMODEL;
    const int NC = DMODEL >> 6;  // 8
    const uint32_t sb = smem_u32(smem);
    const int wm = wid >> 2, wn = wid & 3;  // warp grid 4x4, warp tile 32x32
    const int lr = lane & 15, lc16 = (lane >> 4) * 16;

    float acc[2][4][4];
#pragma unroll
    for (int i = 0; i < 2; i++)
#pragma unroll
        for (int j = 0; j < 4; j++)
#pragma unroll
            for (int r = 0; r < 4; r++) acc[i][j][r] = 0.f;

#define STAGE_LOAD(S, CIDX) do { \
        uint32_t base_ = sb + (uint32_t)(S) * STAGE_B; \
        int koff_ = (CIDX) * 64; \
        _Pragma("unroll") \
        for (int j_ = 0; j_ < 2; j_++) { \
            int cc_ = tid + j_ * 512; \
            int r_ = cc_ >> 3, cg_ = cc_ & 7; \
            uint32_t so_ = SWZ((uint32_t)r_ * 128u + (uint32_t)cg_ * 16u); \
            size_t ga_ = (size_t)r_ * DMODEL + koff_ + cg_ * 8; \
            cpa16(base_ + so_, Ah + ga_); \
            cpa16(base_ + OFF_ALO + so_, Al + ga_); \
            cpa16(base_ + OFF_BHI + so_, Bh + ga_ - (size_t)bm * 128 * DMODEL + (size_t)0); \
        } \
        _Pragma("unroll") \
        for (int j_ = 0; j_ < 2; j_++) { \
            int cc_ = tid + j_ * 512; \
            int r_ = cc_ >> 3, cg_ = cc_ & 7; \
            uint32_t so_ = SWZ((uint32_t)r_ * 128u + (uint32_t)cg_ * 16u); \
            size_t gb_ = (size_t)r_ * DMODEL + koff_ + cg_ * 8; \
            if (PASSES == 3) cpa16(base_ + OFF_BLO + so_, Bl + gb_); \
        } \
        CPA_COMMIT(); \
    } while (0)

    // NOTE: Bh index must be its own row offset, not derived from Ah; fix below.
#undef STAGE_LOAD
#define STAGE_LOAD(S, CIDX) do { \
        uint32_t base_ = sb + (uint32_t)(S) * STAGE_B; \
        int koff_ = (CIDX) * 64; \
        _Pragma("unroll") \
        for (int j_ = 0; j_ < 2; j_++) { \
            int cc_ = tid + j_ * 512; \
            int r_ = cc_ >> 3, cg_ = cc_ & 7; \
            uint32_t so_ = SWZ((uint32_t)r_ * 128u + (uint32_t)cg_ * 16u); \
            size_t g_ = (size_t)r_ * DMODEL + koff_ + cg_ * 8; \
            cpa16(base_ + so_, Ah + g_); \
            cpa16(base_ + OFF_ALO + so_, Al + g_); \
            cpa16(base_ + OFF_BHI + so_, Bh + g_); \
            if (PASSES == 3) cpa16(base_ + OFF_BLO + so_, Bl + g_); \
        } \
        CPA_COMMIT(); \
    } while (0)

    uint32_t ah[2][2][4], al[2][2][4], bhf[2][4][2], blf[2][4][2];
#define LDFRAG(BUF, KS) do { \
        const uint32_t kb_ = (KS) * 32 + lc16; \
        _Pragma("unroll") \
        for (int mb_ = 0; mb_ < 2; mb_++) { \
            uint32_t ro_ = (uint32_t)(wm * 32 + mb_ * 16 + lr) * 128u + kb_; \
            ldm_x4(ah[BUF][mb_], base + SWZ(ro_)); \
            ldm_x4(al[BUF][mb_], base + OFF_ALO + SWZ(ro_)); \
        } \
        _Pragma("unroll") \
        for (int n2_ = 0; n2_ < 2; n2_++) { \
            uint32_t ro_ = (uint32_t)(wn * 32 + n2_ * 16 + lr) * 128u + kb_; \
            uint32_t t_[4]; \
            ldm_x4(t_, base + OFF_BHI + SWZ(ro_)); \
            bhf[BUF][n2_ * 2][0] = t_[0]; bhf[BUF][n2_ * 2][1] = t_[2]; \
            bhf[BUF][n2_ * 2 + 1][0] = t_[1]; bhf[BUF][n2_ * 2 + 1][1] = t_[3]; \
            if (PASSES == 3) { \
                ldm_x4(t_, base + OFF_BLO + SWZ(ro_)); \
                blf[BUF][n2_ * 2][0] = t_[0]; blf[BUF][n2_ * 2][1] = t_[2]; \
                blf[BUF][n2_ * 2 + 1][0] = t_[1]; blf[BUF][n2_ * 2 + 1][1] = t_[3]; \
            } \
        } \
    } while (0)

    STAGE_LOAD(0, 0);
    STAGE_LOAD(1, 1);

    for (int c = 0; c < NC; c++) {
        if (c + 1 < NC) asm volatile("cp.async.wait_group 1;" ::: "memory");
        else            asm volatile("cp.async.wait_group 0;" ::: "memory");
        __syncthreads();
        const uint32_t base = sb + (uint32_t)(((uint32_t)c) % 3u) * STAGE_B;
        LDFRAG(0, 0);
#pragma unroll
        for (int ks = 0; ks < 4; ks++) {
            const int cur = ks & 1;
            if (ks < 3) LDFRAG(!(ks & 1), ks + 1);
#pragma unroll
            for (int mb = 0; mb < 2; mb++)
#pragma unroll
                for (int nb = 0; nb < 4; nb++)
                    mma16816h(acc[mb][nb], ah[cur][mb], bhf[cur][nb]);
#pragma unroll
            for (int mb = 0; mb < 2; mb++)
#pragma unroll
                for (int nb = 0; nb < 4; nb++)
                    mma16816h(acc[mb][nb], al[cur][mb], bhf[cur][nb]);
            if (PASSES == 3) {
#pragma unroll
                for (int mb = 0; mb < 2; mb++)
#pragma unroll
                    for (int nb = 0; nb < 4; nb++)
                        mma16816h(acc[mb][nb], ah[cur][mb], blf[cur][nb]);
            }
        }
        if (c + 2 < NC) STAGE_LOAD(((uint32_t)(c + 2)) % 3u, c + 2);
    }
#undef STAGE_LOAD
#undef LDFRAG

    const int g = lane >> 2, t4 = lane & 3;
    const int region = (MODE == 4) ? (bn >> 2) : 0;
#pragma unroll
    for (int mb = 0; mb < 2; mb++) {
        const int mbase = bm * 128 + wm * 32 + mb * 16 + g;
#pragma unroll
        for (int nb = 0; nb < 4; nb++) {
            const int n0 = bn * 128 + wn * 32 + nb * 8 + t4 * 2;
#pragma unroll
            for (int rr = 0; rr < 2; rr++) {
                const int m = mbase + rr * 8;
                float v0 = acc[mb][nb][rr * 2], v1 = acc[mb][nb][rr * 2 + 1];
                if (MODE == 0) { v0 += bias[n0]; v1 += bias[n0 + 1]; }
                if (MODE == 1) { v0 = fmaxf(v0 + bias[n0], 0.f); v1 = fmaxf(v1 + bias[n0 + 1], 0.f); }
                if (MODE == 0 || MODE == 1) {
                    __half2 hv = __floats2half2_rn(v0, v1);
                    __half2 lv = __floats2half2_rn(v0 - __half2float(hv.x), v1 - __half2float(hv.y));
                    *(__half2*)(Ch + (size_t)m * DMODEL + n0) = hv;
                    *(__half2*)(Cl + (size_t)m * DMODEL + n0) = lv;
                } else {  // MODE 4: region 0=Q, 1=K, 2=V — all fp16
                    const int nl = n0 - (region << 9);
                    if (region == 0) {
                        *(__half2*)(Ch + (size_t)m * DMODEL + nl) =
                            __floats2half2_rn(v0 + bias[nl], v1 + bias[nl + 1]);
                    } else if (region == 1) {
                        *(__half2*)(C2h + (size_t)m * DMODEL + nl) =
                            __floats2half2_rn(v0 + bias2[nl], v1 + bias2[nl + 1]);
                    } else {
                        *(__half2*)(C3h + (size_t)m * DMODEL + nl) =
                            __floats2half2_rn(v0 + bias3[nl], v1 + bias3[nl + 1]);
                    }
                }
            }
        }
    }
}

// ============ fp16 single-pass attention GEMM ============
// MODE 0: scores = tril(QK^T)*scale -> fp16 ; MODE 1: h = S @ Vt^T -> fp32 (causal K bound)
template <int MODE>
__global__ void __launch_bounds__(512) mma_attn(const __half* __restrict__ A, const __half* __restrict__ B,
                                                __half* __restrict__ Sout, float* __restrict__ Hout,
                                                int lda, int ldb,
                                                size_t sA, size_t sB, size_t sC, float scale) {
    extern __shared__ char smem[];
    const int tid = threadIdx.x, wid = tid >> 5, lane = tid & 31;
    const int bm = blockIdx.x, bn = blockIdx.y, bz = blockIdx.z;
    if (MODE == 0 && bn > 2 * bm + 1) return;
    A += sA * bz + (size_t)bm * 256 * lda;
    B += sB * bz + (size_t)bn * 128 * ldb;
    const int NC = (MODE == 1) ? (bm + 1) * 4 : 8;
    const uint32_t sb = smem_u32(smem);
    const int wm = wid >> 2, wn = wid & 3;
    const int lr = lane & 15, lc16 = (lane >> 4) * 16;

    float acc[4][4][4];
#pragma unroll
    for (int i = 0; i < 4; i++)
#pragma unroll
        for (int j = 0; j < 4; j++)
#pragma unroll
            for (int r = 0; r < 4; r++) acc[i][j][r] = 0.f;

#define AT_LOAD(S, CIDX) do { \
        uint32_t base_ = sb + (uint32_t)(S) * AT_STAGE; \
        int koff_ = (CIDX) * 64; \
        _Pragma("unroll") \
        for (int j_ = 0; j_ < 4; j_++) { \
            int cc_ = tid + j_ * 512; \
            int r_ = cc_ >> 3, cg_ = cc_ & 7; \
            cpa16(base_ + SWZ((uint32_t)r_ * 128u + (uint32_t)cg_ * 16u), \
                  A + (size_t)r_ * lda + koff_ + cg_ * 8); \
        } \
        _Pragma("unroll") \
        for (int j_ = 0; j_ < 2; j_++) { \
            int cc_ = tid + j_ * 512; \
            int r_ = cc_ >> 3, cg_ = cc_ & 7; \
            cpa16(base_ + AT_OFF_B + SWZ((uint32_t)r_ * 128u + (uint32_t)cg_ * 16u), \
                  B + (size_t)r_ * ldb + koff_ + cg_ * 8); \
        } \
        CPA_COMMIT(); \
    } while (0)

    AT_LOAD(0, 0);
    if (NC > 1) AT_LOAD(1, 1);

    for (int c = 0; c < NC; c++) {
        if (c + 1 < NC) asm volatile("cp.async.wait_group 1;" ::: "memory");
        else            asm volatile("cp.async.wait_group 0;" ::: "memory");
        __syncthreads();
        const uint32_t base = sb + (uint32_t)(((uint32_t)c) % 3u) * AT_STAGE;
#pragma unroll
        for (int ks = 0; ks < 4; ks++) {
            const uint32_t kb = ks * 32 + lc16;
            uint32_t ah[4][4], bh[4][2];
#pragma unroll
            for (int mb = 0; mb < 4; mb++) {
                uint32_t ro = (uint32_t)(wm * 64 + mb * 16 + lr) * 128u + kb;
                ldm_x4(ah[mb], base + SWZ(ro));
            }
#pragma unroll
            for (int n2 = 0; n2 < 2; n2++) {
                uint32_t ro = (uint32_t)(wn * 32 + n2 * 16 + lr) * 128u + kb;
                uint32_t t[4];
                ldm_x4(t, base + AT_OFF_B + SWZ(ro));
                bh[n2 * 2][0] = t[0]; bh[n2 * 2][1] = t[2];
                bh[n2 * 2 + 1][0] = t[1]; bh[n2 * 2 + 1][1] = t[3];
            }
#pragma unroll
            for (int mb = 0; mb < 4; mb++)
#pragma unroll
                for (int nb = 0; nb < 4; nb++)
                    mma16816h(acc[mb][nb], ah[mb], bh[nb]);
        }
        if (c + 2 < NC) AT_LOAD(((uint32_t)(c + 2)) % 3u, c + 2);
    }
#undef AT_LOAD

    const int g = lane >> 2, t4 = lane & 3;
    if (MODE == 0) Sout += sC * bz;
    else           Hout += sC * bz;
#pragma unroll
    for (int mb = 0; mb < 4; mb++) {
        const int mbase = bm * 256 + wm * 64 + mb * 16 + g;
#pragma unroll
        for (int nb = 0; nb < 4; nb++) {
            const int n0 = bn * 128 + wn * 32 + nb * 8 + t4 * 2;
#pragma unroll
            for (int rr = 0; rr < 2; rr++) {
                const int m = mbase + rr * 8;
                float v0 = acc[mb][nb][rr * 2], v1 = acc[mb][nb][rr * 2 + 1];
                if (MODE == 0) {
                    v0 = (n0 <= m) ? v0 * scale : 0.f;
                    v1 = (n0 + 1 <= m) ? v1 * scale : 0.f;
                    *(__half2*)(Sout + (size_t)m * SEQ + n0) = __floats2half2_rn(v0, v1);
                } else {
                    *(float2*)(Hout + (size_t)m * DMODEL + n0) = make_float2(v0, v1);
                }
            }
        }
    }
}

// ---------------- elementwise / small kernels ----------------
__global__ __launch_bounds__(256) void gather_split(const int* __restrict__ seq,
                                                    const float* __restrict__ feats,
                                                    const float* __restrict__ emb) {
    int i = blockIdx.x * 256 + threadIdx.x;
    int row = i >> 7, d = (i & 127) << 2;
    float4 val;
    if (d < EMB_DIM) val = *(const float4*)(emb + (size_t)seq[row] * EMB_DIM + d);
    else val = *(const float4*)(feats + (size_t)row * FEAT_DIM + (d - EMB_DIM));
    uint2 h, l;
    split4h(val, h, l);
    *(uint2*)(g_xh + ((size_t)row << 9) + d) = h;
    *(uint2*)(g_xl + ((size_t)row << 9) + d) = l;
}

// split all 8 weight matrices to fp16 hi/lo in one launch
__global__ __launch_bounds__(256) void convw_all(const float* __restrict__ Wq,
                                                 const float* __restrict__ Wk,
                                                 const float* __restrict__ Wv,
                                                 const float* __restrict__ W1,
                                                 const float* __restrict__ W2) {
    int midx = blockIdx.y;
    const float* src;
    switch (midx) {
        case 0: src = Wq; break;
        case 1: src = Wk; break;
        case 2: src = Wv; break;
        case 3: src = W1; break;
        case 4: src = W2; break;
        case 5: src = Wq + WMAT; break;
        case 6: src = Wk + WMAT; break;
        default: src = Wv + WMAT; break;
    }
    int i = (blockIdx.x * 256 + threadIdx.x) << 2;
    float4 f = *(const float4*)(src + i);
    uint2 h, l;
    split4h(f, h, l);
    *(uint2*)(g_wfh + (size_t)midx * WMAT + i) = h;
    *(uint2*)(g_wfl + (size_t)midx * WMAT + i) = l;
}

__global__ void transpose_half(void) {
    __shared__ __half tile[32][40];
    int b = blockIdx.z, s0 = blockIdx.x * 32, d0 = blockIdx.y * 32;
    const __half* Vb = g_vf + (size_t)b * SEQ * DMODEL;
    __half* Vt = g_vtf + (size_t)b * DMODEL * SEQ;
    int tx = threadIdx.x, ty = threadIdx.y;
#pragma unroll
    for (int i = 0; i < 32; i += 8)
        tile[ty + i][tx] = Vb[(size_t)(s0 + ty + i) * DMODEL + d0 + tx];
    __syncthreads();
#pragma unroll
    for (int i = 0; i < 32; i += 8)
        Vt[(size_t)(d0 + ty + i) * SEQ + s0 + tx] = tile[tx][ty + i];
}

// fused stats + normalize. LAST=1: only emit last row into g_last
template <int LAST>
__global__ void norm_fused(const float* __restrict__ H) {
    const int b = blockIdx.x, tx = threadIdx.x, ty = threadIdx.y;
    const int d = blockIdx.y * 32 + tx;
    float sum = 0.f, sq = 0.f;
    for (int s = ty; s < SEQ; s += 8) {
        float v = H[(size_t)(b * SEQ + s) * DMODEL + d];
        sum += v; sq += v * v;
    }
    __shared__ float ss[8][32], s2[8][32], smean[32], srstd[32];
    ss[ty][tx] = sum; s2[ty][tx] = sq;
    __syncthreads();
    if (ty == 0) {
#pragma unroll
        for (int r = 1; r < 8; r++) { sum += ss[r][tx]; sq += s2[r][tx]; }
        float mean = sum * (1.0f / SEQ);
        float var = fmaxf((sq - sum * mean) * (1.0f / (SEQ - 1)), 0.0f);
        smean[tx] = mean;
        srstd[tx] = 1.0f / (sqrtf(var) + 2e-5f);
    }
    __syncthreads();
    const float mean = smean[tx], rstd = srstd[tx];
    if (LAST) {
        if (ty == 7) {
            float v = H[(size_t)(b * SEQ + SEQ - 1) * DMODEL + d];
            g_last[b * DMODEL + d] = (v - mean) * rstd;
        }
    } else {
        for (int s = ty; s < SEQ; s += 8) {
            float v = (H[(size_t)(b * SEQ + s) * DMODEL + d] - mean) * rstd;
            __half h = __float2half(v);
            __half l = __float2half(v - __half2float(h));
            g_hnh[(size_t)(b * SEQ + s) * DMODEL + d] = h;
            g_hnl[(size_t)(b * SEQ + s) * DMODEL + d] = l;
        }
    }
}

template <bool RELU>
__global__ void small_gemm(const float* __restrict__ A, const float* __restrict__ W,
                           const float* __restrict__ bias, float* __restrict__ C) {
    int i = blockIdx.x * 256 + threadIdx.x;  // 4096
    int m = i >> 9, n = i & 511;
    const float* a = A + (size_t)m * DMODEL;
    const float* w = W + (size_t)n * DMODEL;
    float s = 0.f;
#pragma unroll 8
    for (int k2 = 0; k2 < DMODEL; k2 += 4) {
        float4 av = *(const float4*)(a + k2), wv = *(const float4*)(w + k2);
        s += av.x * wv.x + av.y * wv.y + av.z * wv.z + av.w * wv.w;
    }
    s += bias[n];
    if (RELU) s = fmaxf(s, 0.0f);
    C[i] = s;
}

extern "C" void kernel_launch(void* const* d_in, const int* in_sizes, int n_in,
                              void* d_out, int out_size) {
    const int* seq = (const int*)d_in[0];
    const float* feats = (const float*)d_in[1];
    const float* emb = (const float*)d_in[2];
    const float* Wq = (const float*)d_in[3];  const float* bq = (const float*)d_in[4];
    const float* Wk = (const float*)d_in[5];  const float* bk = (const float*)d_in[6];
    const float* Wv = (const float*)d_in[7];  const float* bv = (const float*)d_in[8];
    const float* W1 = (const float*)d_in[9];  const float* b1 = (const float*)d_in[10];
    const float* W2 = (const float*)d_in[11]; const float* b2 = (const float*)d_in[12];
    float* out = (float*)d_out;

    cudaFuncSetAttribute(mma_gemm<0, 3>, cudaFuncAttributeMaxDynamicSharedMemorySize, SMEM_TC);
    cudaFuncSetAttribute(mma_gemm<1, 3>, cudaFuncAttributeMaxDynamicSharedMemorySize, SMEM_TC);
    cudaFuncSetAttribute(mma_gemm<4, 3>, cudaFuncAttributeMaxDynamicSharedMemorySize, SMEM_TC);
    cudaFuncSetAttribute(mma_gemm<4, 2>, cudaFuncAttributeMaxDynamicSharedMemorySize, SMEM_TC);
    cudaFuncSetAttribute(mma_attn<0>, cudaFuncAttributeMaxDynamicSharedMemorySize, SMEM_AT);
    cudaFuncSetAttribute(mma_attn<1>, cudaFuncAttributeMaxDynamicSharedMemorySize, SMEM_AT);

    void *pxh, *pxl, *phnh, *phnl, *pth, *ptl, *pwfh, *pwfl;
    void *pqf, *pkf, *pvf, *pvtf, *psf, *ph, *plast, *plt;
    cudaGetSymbolAddress(&pxh, g_xh);   cudaGetSymbolAddress(&pxl, g_xl);
    cudaGetSymbolAddress(&phnh, g_hnh); cudaGetSymbolAddress(&phnl, g_hnl);
    cudaGetSymbolAddress(&pth, g_th);   cudaGetSymbolAddress(&ptl, g_tl);
    cudaGetSymbolAddress(&pwfh, g_wfh); cudaGetSymbolAddress(&pwfl, g_wfl);
    cudaGetSymbolAddress(&pqf, g_qf);   cudaGetSymbolAddress(&pkf, g_kf);
    cudaGetSymbolAddress(&pvf, g_vf);   cudaGetSymbolAddress(&pvtf, g_vtf);
    cudaGetSymbolAddress(&psf, g_sf);   cudaGetSymbolAddress(&ph, g_h);
    cudaGetSymbolAddress(&plast, g_last); cudaGetSymbolAddress(&plt, g_lt);
    __half* xh = (__half*)pxh;   __half* xl = (__half*)pxl;
    __half* hnh = (__half*)phnh; __half* hnl = (__half*)phnl;
    __half* th = (__half*)pth;   __half* tl = (__half*)ptl;
    __half* wfh = (__half*)pwfh; __half* wfl = (__half*)pwfl;
    __half* qf = (__half*)pqf;   __half* kf = (__half*)pkf;
    __half* vf = (__half*)pvf;   __half* vtf = (__half*)pvtf;
    __half* sf = (__half*)psf;
    float* h = (float*)ph;
    float* last = (float*)plast; float* lt = (float*)plt;

    const float scale = 0.044194173824159216f;  // 1/sqrt(512)

    gather_split<<<MTOT * 128 / 256, 256>>>(seq, feats, emb);
    convw_all<<<dim3(WMAT / 4 / 256, 8), 256>>>(Wq, Wk, Wv, W1, W2);

    const dim3 gqkv(MTOT / 128, 1536 / 128);         // 128 x 12
    const dim3 gw(MTOT / 128, DMODEL / 128);         // 128 x 4
    const dim3 gs(SEQ / 256, SEQ / 128, NBATCH);     // 8 x 16 x 8
    const dim3 ga(SEQ / 256, DMODEL / 128, NBATCH);  // 8 x 4 x 8

    for (int l = 0; l < 2; l++) {
        const int bo = l * DMODEL;
        const size_t mqkv = (size_t)(l ? 5 : 0) * WMAT;

        if (l == 0)
            mma_gemm<4, 3><<<gqkv, 512, SMEM_TC>>>(xh, xl, wfh + mqkv, wfl + mqkv,
                                                   bq + bo, bk + bo, bv + bo,
                                                   qf, nullptr, kf, vf);
        else
            mma_gemm<4, 2><<<gqkv, 512, SMEM_TC>>>(xh, xl, wfh + mqkv, wfl + mqkv,
                                                   bq + bo, bk + bo, bv + bo,
                                                   qf, nullptr, kf, vf);

        transpose_half<<<dim3(SEQ / 32, DMODEL / 32, NBATCH), dim3(32, 8)>>>();

        mma_attn<0><<<gs, 512, SMEM_AT>>>(qf, kf, sf, nullptr, DMODEL, DMODEL,
                                          (size_t)SEQ * DMODEL, (size_t)SEQ * DMODEL,
                                          (size_t)SEQ * SEQ, scale);
        mma_attn<1><<<ga, 512, SMEM_AT>>>(sf, vtf, nullptr, h, SEQ, SEQ,
                                          (size_t)SEQ * SEQ, (size_t)DMODEL * SEQ,
                                          (size_t)SEQ * DMODEL, 0.f);

        if (l == 0) {
            norm_fused<0><<<dim3(NBATCH, DMODEL / 32), dim3(32, 8)>>>(h);
            const size_t m1 = 3 * (size_t)WMAT, m2 = 4 * (size_t)WMAT;
            mma_gemm<1, 3><<<gw, 512, SMEM_TC>>>(hnh, hnl, wfh + m1, wfl + m1,
                                                 b1 + bo, nullptr, nullptr,
                                                 th, tl, nullptr, nullptr);
            mma_gemm<0, 3><<<gw, 512, SMEM_TC>>>(th, tl, wfh + m2, wfl + m2,
                                                 b2 + bo, nullptr, nullptr,
                                                 xh, xl, nullptr, nullptr);
        } else {
            norm_fused<1><<<dim3(NBATCH, DMODEL / 32), dim3(32, 8)>>>(h);
            small_gemm<true><<<16, 256>>>(last, W1 + (size_t)WMAT, b1 + bo, lt);
            small_gemm<false><<<16, 256>>>(lt, W2 + (size_t)WMAT, b2 + bo, out);
        }
    }
}

// round 12
// speedup vs baseline: 4.7574x; 1.0367x over previous
#include <cuda_runtime.h>
#include <cuda_fp16.h>
#include <math.h>
#include <stdint.h>

#define EMB_DIM 448
#define FEAT_DIM 64
#define DMODEL 512
#define NBATCH 8
#define SEQ 2048
#define MTOT (NBATCH * SEQ)
#define WMAT (DMODEL * DMODEL)

// -------- scratch (device globals) --------
static __device__ __half g_xh[MTOT * DMODEL], g_xl[MTOT * DMODEL];
static __device__ __half g_hnh[MTOT * DMODEL], g_hnl[MTOT * DMODEL];
static __device__ __half g_th[MTOT * DMODEL], g_tl[MTOT * DMODEL];
static __device__ __half g_wfh[8 * WMAT], g_wfl[8 * WMAT];  // fp16 hi/lo weights
static __device__ __half g_qf[MTOT * DMODEL], g_kf[MTOT * DMODEL];
static __device__ __half g_vf[MTOT * DMODEL];
static __device__ __half g_sf[(size_t)NBATCH * SEQ * SEQ];
static __device__ float g_h[MTOT * DMODEL];
static __device__ float g_last[NBATCH * DMODEL], g_lt[NBATCH * DMODEL];

__device__ __forceinline__ uint32_t smem_u32(const void* p) {
    uint32_t a;
    asm("{ .reg .u64 t; cvta.to.shared.u64 t, %1; cvt.u32.u64 %0, t; }" : "=r"(a) : "l"(p));
    return a;
}
#define SWZ(o) ((o) ^ ((((uint32_t)(o)) >> 3) & 0x70))
// projection GEMM stage: Ahi 16K | Alo 16K | Bhi 16K | Blo 16K
#define OFF_ALO 16384u
#define OFF_BHI 32768u
#define OFF_BLO 49152u
#define STAGE_B 65536u
#define SMEM_TC 196608
// attention stages: A 32K (256 rows x 128B) + B 16K (two 8K subtiles)
#define AT_OFF_B 32768u
#define AT_STAGE 49152u
#define SMEM_AT 147456

__device__ __forceinline__ void ldm_x4(uint32_t* r, uint32_t addr) {
    asm volatile("ldmatrix.sync.aligned.m8n8.x4.shared.b16 {%0,%1,%2,%3}, [%4];"
                 : "=r"(r[0]), "=r"(r[1]), "=r"(r[2]), "=r"(r[3]) : "r"(addr));
}
__device__ __forceinline__ void ldm_x4t(uint32_t* r, uint32_t addr) {
    asm volatile("ldmatrix.sync.aligned.m8n8.x4.trans.shared.b16 {%0,%1,%2,%3}, [%4];"
                 : "=r"(r[0]), "=r"(r[1]), "=r"(r[2]), "=r"(r[3]) : "r"(addr));
}
__device__ __forceinline__ void mma16816h(float* c, const uint32_t* a, const uint32_t* b) {
    asm volatile(
        "mma.sync.aligned.m16n8k16.row.col.f32.f16.f16.f32 "
        "{%0,%1,%2,%3}, {%4,%5,%6,%7}, {%8,%9}, {%0,%1,%2,%3};"
        : "+f"(c[0]), "+f"(c[1]), "+f"(c[2]), "+f"(c[3])
        : "r"(a[0]), "r"(a[1]), "r"(a[2]), "r"(a[3]), "r"(b[0]), "r"(b[1]));
}
__device__ __forceinline__ void cpa16(uint32_t dst, const void* src) {
    asm volatile("cp.async.cg.shared.global [%0], [%1], 16;" :: "r"(dst), "l"(src));
}
#define CPA_COMMIT() asm volatile("cp.async.commit_group;" ::: "memory")

__device__ __forceinline__ void split4h(float4 f, uint2& h, uint2& l) {
    __half2 h0 = __floats2half2_rn(f.x, f.y);
    __half2 h1 = __floats2half2_rn(f.z, f.w);
    __half2 l0 = __floats2half2_rn(f.x - __half2float(h0.x), f.y - __half2float(h0.y));
    __half2 l1 = __floats2half2_rn(f.z - __half2float(h1.x), f.w - __half2float(h1.y));
    h.x = *(uint32_t*)&h0; h.y = *(uint32_t*)&h1;
    l.x = *(uint32_t*)&l0; l.y = *(uint32_t*)&l1;
}

// ============ fp16 split projection/MLP GEMM ============
// A = Ah+Al (fp16 hi/lo), W = Wh (+Wl if PASSES==3). K = DMODEL fixed.
// MODE: 0=bias->hi/lo, 1=bias+relu->hi/lo, 4=fused QKV (Q,K,V all fp16)
template <int MODE, int PASSES>
__global__ void __launch_bounds__(512) mma_gemm(const __half* __restrict__ Ah, const __half* __restrict__ Al,
                                                const __half* __restrict__ Bh, const __half* __restrict__ Bl,
                                                const float* __restrict__ bias, const float* __restrict__ bias2,
                                                const float* __restrict__ bias3,
                                                __half* __restrict__ Ch, __half* __restrict__ Cl,
                                                __half* __restrict__ C2h, __half* __restrict__ C3h) {
    extern __shared__ char smem[];
    const int tid = threadIdx.x, wid = tid >> 5, lane = tid & 31;
    const int bm = blockIdx.x, bn = blockIdx.y;
    Ah += (size_t)bm * 128 * DMODEL;
    Al += (size_t)bm * 128 * DMODEL;
    Bh += (size_t)bn * 128 * DMODEL;
    Bl += (size_t)bn * 128 * DMODEL;
    const int NC = DMODEL >> 6;  // 8
    const uint32_t sb = smem_u32(smem);
    const int wm = wid >> 2, wn = wid & 3;  // warp grid 4x4, warp tile 32x32
    const int lr = lane & 15, lc16 = (lane >> 4) * 16;

    float acc[2][4][4];
#pragma unroll
    for (int i = 0; i < 2; i++)
#pragma unroll
        for (int j = 0; j < 4; j++)
#pragma unroll
            for (int r = 0; r < 4; r++) acc[i][j][r] = 0.f;

#define STAGE_LOAD(S, CIDX) do { \
        uint32_t base_ = sb + (uint32_t)(S) * STAGE_B; \
        int koff_ = (CIDX) * 64; \
        _Pragma("unroll") \
        for (int j_ = 0; j_ < 2; j_++) { \
            int cc_ = tid + j_ * 512; \
            int r_ = cc_ >> 3, cg_ = cc_ & 7; \
            uint32_t so_ = SWZ((uint32_t)r_ * 128u + (uint32_t)cg_ * 16u); \
            size_t g_ = (size_t)r_ * DMODEL + koff_ + cg_ * 8; \
            cpa16(base_ + so_, Ah + g_); \
            cpa16(base_ + OFF_ALO + so_, Al + g_); \
            cpa16(base_ + OFF_BHI + so_, Bh + g_); \
            if (PASSES == 3) cpa16(base_ + OFF_BLO + so_, Bl + g_); \
        } \
        CPA_COMMIT(); \
    } while (0)

    uint32_t ah[2][2][4], al[2][2][4], bhf[2][4][2], blf[2][4][2];
#define LDFRAG(BUF, KS) do { \
        const uint32_t kb_ = (KS) * 32 + lc16; \
        _Pragma("unroll") \
        for (int mb_ = 0; mb_ < 2; mb_++) { \
            uint32_t ro_ = (uint32_t)(wm * 32 + mb_ * 16 + lr) * 128u + kb_; \
            ldm_x4(ah[BUF][mb_], base + SWZ(ro_)); \
            ldm_x4(al[BUF][mb_], base + OFF_ALO + SWZ(ro_)); \
        } \
        _Pragma("unroll") \
        for (int n2_ = 0; n2_ < 2; n2_++) { \
            uint32_t ro_ = (uint32_t)(wn * 32 + n2_ * 16 + lr) * 128u + kb_; \
            uint32_t t_[4]; \
            ldm_x4(t_, base + OFF_BHI + SWZ(ro_)); \
            bhf[BUF][n2_ * 2][0] = t_[0]; bhf[BUF][n2_ * 2][1] = t_[2]; \
            bhf[BUF][n2_ * 2 + 1][0] = t_[1]; bhf[BUF][n2_ * 2 + 1][1] = t_[3]; \
            if (PASSES == 3) { \
                ldm_x4(t_, base + OFF_BLO + SWZ(ro_)); \
                blf[BUF][n2_ * 2][0] = t_[0]; blf[BUF][n2_ * 2][1] = t_[2]; \
                blf[BUF][n2_ * 2 + 1][0] = t_[1]; blf[BUF][n2_ * 2 + 1][1] = t_[3]; \
            } \
        } \
    } while (0)

    STAGE_LOAD(0, 0);
    STAGE_LOAD(1, 1);

    for (int c = 0; c < NC; c++) {
        if (c + 1 < NC) asm volatile("cp.async.wait_group 1;" ::: "memory");
        else            asm volatile("cp.async.wait_group 0;" ::: "memory");
        __syncthreads();
        const uint32_t base = sb + (uint32_t)(((uint32_t)c) % 3u) * STAGE_B;
        LDFRAG(0, 0);
#pragma unroll
        for (int ks = 0; ks < 4; ks++) {
            const int cur = ks & 1;
            if (ks < 3) LDFRAG(!(ks & 1), ks + 1);
#pragma unroll
            for (int mb = 0; mb < 2; mb++)
#pragma unroll
                for (int nb = 0; nb < 4; nb++)
                    mma16816h(acc[mb][nb], ah[cur][mb], bhf[cur][nb]);
#pragma unroll
            for (int mb = 0; mb < 2; mb++)
#pragma unroll
                for (int nb = 0; nb < 4; nb++)
                    mma16816h(acc[mb][nb], al[cur][mb], bhf[cur][nb]);
            if (PASSES == 3) {
#pragma unroll
                for (int mb = 0; mb < 2; mb++)
#pragma unroll
                    for (int nb = 0; nb < 4; nb++)
                        mma16816h(acc[mb][nb], ah[cur][mb], blf[cur][nb]);
            }
        }
        if (c + 2 < NC) STAGE_LOAD(((uint32_t)(c + 2)) % 3u, c + 2);
    }
#undef STAGE_LOAD
#undef LDFRAG

    const int g = lane >> 2, t4 = lane & 3;
    const int region = (MODE == 4) ? (bn >> 2) : 0;
#pragma unroll
    for (int mb = 0; mb < 2; mb++) {
        const int mbase = bm * 128 + wm * 32 + mb * 16 + g;
#pragma unroll
        for (int nb = 0; nb < 4; nb++) {
            const int n0 = bn * 128 + wn * 32 + nb * 8 + t4 * 2;
#pragma unroll
            for (int rr = 0; rr < 2; rr++) {
                const int m = mbase + rr * 8;
                float v0 = acc[mb][nb][rr * 2], v1 = acc[mb][nb][rr * 2 + 1];
                if (MODE == 0) { v0 += bias[n0]; v1 += bias[n0 + 1]; }
                if (MODE == 1) { v0 = fmaxf(v0 + bias[n0], 0.f); v1 = fmaxf(v1 + bias[n0 + 1], 0.f); }
                if (MODE == 0 || MODE == 1) {
                    __half2 hv = __floats2half2_rn(v0, v1);
                    __half2 lv = __floats2half2_rn(v0 - __half2float(hv.x), v1 - __half2float(hv.y));
                    *(__half2*)(Ch + (size_t)m * DMODEL + n0) = hv;
                    *(__half2*)(Cl + (size_t)m * DMODEL + n0) = lv;
                } else {  // MODE 4: region 0=Q, 1=K, 2=V — all fp16
                    const int nl = n0 - (region << 9);
                    if (region == 0) {
                        *(__half2*)(Ch + (size_t)m * DMODEL + nl) =
                            __floats2half2_rn(v0 + bias[nl], v1 + bias[nl + 1]);
                    } else if (region == 1) {
                        *(__half2*)(C2h + (size_t)m * DMODEL + nl) =
                            __floats2half2_rn(v0 + bias2[nl], v1 + bias2[nl + 1]);
                    } else {
                        *(__half2*)(C3h + (size_t)m * DMODEL + nl) =
                            __floats2half2_rn(v0 + bias3[nl], v1 + bias3[nl + 1]);
                    }
                }
            }
        }
    }
}

// ============ fp16 single-pass attention GEMM ============
// MODE 0: scores = tril(QK^T)*scale -> fp16 ; B = K [s][d] K-major (row = n)
// MODE 1: h = S @ V -> fp32, causal K bound; B = V [s][d], read via ldmatrix.trans
// CTA 256x128, 512 thr, warp grid 4x4, warp tile 64x32
template <int MODE>
__global__ void __launch_bounds__(512) mma_attn(const __half* __restrict__ A, const __half* __restrict__ B,
                                                __half* __restrict__ Sout, float* __restrict__ Hout,
                                                int lda, int ldb,
                                                size_t sA, size_t sB, size_t sC, float scale) {
    extern __shared__ char smem[];
    const int tid = threadIdx.x, wid = tid >> 5, lane = tid & 31;
    const int bm = blockIdx.x, bn = blockIdx.y, bz = blockIdx.z;
    if (MODE == 0 && bn > 2 * bm + 1) return;
    A += sA * bz + (size_t)bm * 256 * lda;
    if (MODE == 0) B += sB * bz + (size_t)bn * 128 * ldb;  // row offset (n = s-rows of K)
    else           B += sB * bz + (size_t)bn * 128;        // column offset (d) into V[s][d]
    const int NC = (MODE == 1) ? (bm + 1) * 4 : 8;
    const uint32_t sb = smem_u32(smem);
    const int wm = wid >> 2, wn = wid & 3;
    const int lr = lane & 15, lc16 = (lane >> 4) * 16;

    float acc[4][4][4];
#pragma unroll
    for (int i = 0; i < 4; i++)
#pragma unroll
        for (int j = 0; j < 4; j++)
#pragma unroll
            for (int r = 0; r < 4; r++) acc[i][j][r] = 0.f;

#define AT_LOAD(S, CIDX) do { \
        uint32_t base_ = sb + (uint32_t)(S) * AT_STAGE; \
        int koff_ = (CIDX) * 64; \
        _Pragma("unroll") \
        for (int j_ = 0; j_ < 4; j_++) { \
            int cc_ = tid + j_ * 512; \
            int r_ = cc_ >> 3, cg_ = cc_ & 7; \
            cpa16(base_ + SWZ((uint32_t)r_ * 128u + (uint32_t)cg_ * 16u), \
                  A + (size_t)r_ * lda + koff_ + cg_ * 8); \
        } \
        _Pragma("unroll") \
        for (int j_ = 0; j_ < 2; j_++) { \
            int cc_ = tid + j_ * 512; \
            if (MODE == 0) { \
                int r_ = cc_ >> 3, cg_ = cc_ & 7; \
                cpa16(base_ + AT_OFF_B + SWZ((uint32_t)r_ * 128u + (uint32_t)cg_ * 16u), \
                      B + (size_t)r_ * ldb + koff_ + cg_ * 8); \
            } else { \
                int r_ = cc_ >> 4, sub_ = (cc_ >> 3) & 1, cg_ = cc_ & 7; \
                cpa16(base_ + AT_OFF_B + (uint32_t)sub_ * 8192u + \
                          SWZ((uint32_t)r_ * 128u + (uint32_t)cg_ * 16u), \
                      B + (size_t)(koff_ + r_) * DMODEL + sub_ * 64 + cg_ * 8); \
            } \
        } \
        CPA_COMMIT(); \
    } while (0)

    AT_LOAD(0, 0);
    if (NC > 1) AT_LOAD(1, 1);

    for (int c = 0; c < NC; c++) {
        if (c + 1 < NC) asm volatile("cp.async.wait_group 1;" ::: "memory");
        else            asm volatile("cp.async.wait_group 0;" ::: "memory");
        __syncthreads();
        const uint32_t base = sb + (uint32_t)(((uint32_t)c) % 3u) * AT_STAGE;
#pragma unroll
        for (int ks = 0; ks < 4; ks++) {
            const uint32_t kb = ks * 32 + lc16;
            uint32_t ah[4][4], bh[4][2];
#pragma unroll
            for (int mb = 0; mb < 4; mb++) {
                uint32_t ro = (uint32_t)(wm * 64 + mb * 16 + lr) * 128u + kb;
                ldm_x4(ah[mb], base + SWZ(ro));
            }
#pragma unroll
            for (int n2 = 0; n2 < 2; n2++) {
                uint32_t t[4];
                if (MODE == 0) {
                    uint32_t ro = (uint32_t)(wn * 32 + n2 * 16 + lr) * 128u + kb;
                    ldm_x4(t, base + AT_OFF_B + SWZ(ro));
                    bh[n2 * 2][0] = t[0]; bh[n2 * 2][1] = t[2];
                    bh[n2 * 2 + 1][0] = t[1]; bh[n2 * 2 + 1][1] = t[3];
                } else {
                    // trans load from V[s][d]: row = s within chunk, col = d
                    int d_loc = wn * 32 + n2 * 16 + ((lane >> 4) << 3);
                    uint32_t row = (uint32_t)(ks * 16 + (lane & 15));
                    uint32_t addr = base + AT_OFF_B + ((uint32_t)(d_loc >> 6)) * 8192u +
                                    SWZ(row * 128u + (uint32_t)(d_loc & 63) * 2u);
                    ldm_x4t(t, addr);
                    bh[n2 * 2][0] = t[0]; bh[n2 * 2][1] = t[1];
                    bh[n2 * 2 + 1][0] = t[2]; bh[n2 * 2 + 1][1] = t[3];
                }
            }
#pragma unroll
            for (int mb = 0; mb < 4; mb++)
#pragma unroll
                for (int nb = 0; nb < 4; nb++)
                    mma16816h(acc[mb][nb], ah[mb], bh[nb]);
        }
        if (c + 2 < NC) AT_LOAD(((uint32_t)(c + 2)) % 3u, c + 2);
    }
#undef AT_LOAD

    const int g = lane >> 2, t4 = lane & 3;
    if (MODE == 0) Sout += sC * bz;
    else           Hout += sC * bz;
#pragma unroll
    for (int mb = 0; mb < 4; mb++) {
        const int mbase = bm * 256 + wm * 64 + mb * 16 + g;
#pragma unroll
        for (int nb = 0; nb < 4; nb++) {
            const int n0 = bn * 128 + wn * 32 + nb * 8 + t4 * 2;
#pragma unroll
            for (int rr = 0; rr < 2; rr++) {
                const int m = mbase + rr * 8;
                float v0 = acc[mb][nb][rr * 2], v1 = acc[mb][nb][rr * 2 + 1];
                if (MODE == 0) {
                    v0 = (n0 <= m) ? v0 * scale : 0.f;
                    v1 = (n0 + 1 <= m) ? v1 * scale : 0.f;
                    *(__half2*)(Sout + (size_t)m * SEQ + n0) = __floats2half2_rn(v0, v1);
                } else {
                    *(float2*)(Hout + (size_t)m * DMODEL + n0) = make_float2(v0, v1);
                }
            }
        }
    }
}

// ---------------- elementwise / small kernels ----------------
__global__ __launch_bounds__(256) void gather_split(const int* __restrict__ seq,
                                                    const float* __restrict__ feats,
                                                    const float* __restrict__ emb) {
    int i = blockIdx.x * 256 + threadIdx.x;
    int row = i >> 7, d = (i & 127) << 2;
    float4 val;
    if (d < EMB_DIM) val = *(const float4*)(emb + (size_t)seq[row] * EMB_DIM + d);
    else val = *(const float4*)(feats + (size_t)row * FEAT_DIM + (d - EMB_DIM));
    uint2 h, l;
    split4h(val, h, l);
    *(uint2*)(g_xh + ((size_t)row << 9) + d) = h;
    *(uint2*)(g_xl + ((size_t)row << 9) + d) = l;
}

__global__ __launch_bounds__(256) void convw_all(const float* __restrict__ Wq,
                                                 const float* __restrict__ Wk,
                                                 const float* __restrict__ Wv,
                                                 const float* __restrict__ W1,
                                                 const float* __restrict__ W2) {
    int midx = blockIdx.y;
    const float* src;
    switch (midx) {
        case 0: src = Wq; break;
        case 1: src = Wk; break;
        case 2: src = Wv; break;
        case 3: src = W1; break;
        case 4: src = W2; break;
        case 5: src = Wq + WMAT; break;
        case 6: src = Wk + WMAT; break;
        default: src = Wv + WMAT; break;
    }
    int i = (blockIdx.x * 256 + threadIdx.x) << 2;
    float4 f = *(const float4*)(src + i);
    uint2 h, l;
    split4h(f, h, l);
    *(uint2*)(g_wfh + (size_t)midx * WMAT + i) = h;
    *(uint2*)(g_wfl + (size_t)midx * WMAT + i) = l;
}

// fused stats + normalize. LAST=1: only emit last row into g_last
template <int LAST>
__global__ void norm_fused(const float* __restrict__ H) {
    const int b = blockIdx.x, tx = threadIdx.x, ty = threadIdx.y;
    const int d = blockIdx.y * 32 + tx;
    float sum = 0.f, sq = 0.f;
    for (int s = ty; s < SEQ; s += 8) {
        float v = H[(size_t)(b * SEQ + s) * DMODEL + d];
        sum += v; sq += v * v;
    }
    __shared__ float ss[8][32], s2[8][32], smean[32], srstd[32];
    ss[ty][tx] = sum; s2[ty][tx] = sq;
    __syncthreads();
    if (ty == 0) {
#pragma unroll
        for (int r = 1; r < 8; r++) { sum += ss[r][tx]; sq += s2[r][tx]; }
        float mean = sum * (1.0f / SEQ);
        float var = fmaxf((sq - sum * mean) * (1.0f / (SEQ - 1)), 0.0f);
        smean[tx] = mean;
        srstd[tx] = 1.0f / (sqrtf(var) + 2e-5f);
    }
    __syncthreads();
    const float mean = smean[tx], rstd = srstd[tx];
    if (LAST) {
        if (ty == 7) {
            float v = H[(size_t)(b * SEQ + SEQ - 1) * DMODEL + d];
            g_last[b * DMODEL + d] = (v - mean) * rstd;
        }
    } else {
        for (int s = ty; s < SEQ; s += 8) {
            float v = (H[(size_t)(b * SEQ + s) * DMODEL + d] - mean) * rstd;
            __half h = __float2half(v);
            __half l = __float2half(v - __half2float(h));
            g_hnh[(size_t)(b * SEQ + s) * DMODEL + d] = h;
            g_hnl[(size_t)(b * SEQ + s) * DMODEL + d] = l;
        }
    }
}

template <bool RELU>
__global__ void small_gemm(const float* __restrict__ A, const float* __restrict__ W,
                           const float* __restrict__ bias, float* __restrict__ C) {
    int i = blockIdx.x * 256 + threadIdx.x;  // 4096
    int m = i >> 9, n = i & 511;
    const float* a = A + (size_t)m * DMODEL;
    const float* w = W + (size_t)n * DMODEL;
    float s = 0.f;
#pragma unroll 8
    for (int k2 = 0; k2 < DMODEL; k2 += 4) {
        float4 av = *(const float4*)(a + k2), wv = *(const float4*)(w + k2);
        s += av.x * wv.x + av.y * wv.y + av.z * wv.z + av.w * wv.w;
    }
    s += bias[n];
    if (RELU) s = fmaxf(s, 0.0f);
    C[i] = s;
}

extern "C" void kernel_launch(void* const* d_in, const int* in_sizes, int n_in,
                              void* d_out, int out_size) {
    const int* seq = (const int*)d_in[0];
    const float* feats = (const float*)d_in[1];
    const float* emb = (const float*)d_in[2];
    const float* Wq = (const float*)d_in[3];  const float* bq = (const float*)d_in[4];
    const float* Wk = (const float*)d_in[5];  const float* bk = (const float*)d_in[6];
    const float* Wv = (const float*)d_in[7];  const float* bv = (const float*)d_in[8];
    const float* W1 = (const float*)d_in[9];  const float* b1 = (const float*)d_in[10];
    const float* W2 = (const float*)d_in[11]; const float* b2 = (const float*)d_in[12];
    float* out = (float*)d_out;

    cudaFuncSetAttribute(mma_gemm<0, 3>, cudaFuncAttributeMaxDynamicSharedMemorySize, SMEM_TC);
    cudaFuncSetAttribute(mma_gemm<1, 3>, cudaFuncAttributeMaxDynamicSharedMemorySize, SMEM_TC);
    cudaFuncSetAttribute(mma_gemm<4, 3>, cudaFuncAttributeMaxDynamicSharedMemorySize, SMEM_TC);
    cudaFuncSetAttribute(mma_gemm<4, 2>, cudaFuncAttributeMaxDynamicSharedMemorySize, SMEM_TC);
    cudaFuncSetAttribute(mma_attn<0>, cudaFuncAttributeMaxDynamicSharedMemorySize, SMEM_AT);
    cudaFuncSetAttribute(mma_attn<1>, cudaFuncAttributeMaxDynamicSharedMemorySize, SMEM_AT);

    void *pxh, *pxl, *phnh, *phnl, *pth, *ptl, *pwfh, *pwfl;
    void *pqf, *pkf, *pvf, *psf, *ph, *plast, *plt;
    cudaGetSymbolAddress(&pxh, g_xh);   cudaGetSymbolAddress(&pxl, g_xl);
    cudaGetSymbolAddress(&phnh, g_hnh); cudaGetSymbolAddress(&phnl, g_hnl);
    cudaGetSymbolAddress(&pth, g_th);   cudaGetSymbolAddress(&ptl, g_tl);
    cudaGetSymbolAddress(&pwfh, g_wfh); cudaGetSymbolAddress(&pwfl, g_wfl);
    cudaGetSymbolAddress(&pqf, g_qf);   cudaGetSymbolAddress(&pkf, g_kf);
    cudaGetSymbolAddress(&pvf, g_vf);   cudaGetSymbolAddress(&psf, g_sf);
    cudaGetSymbolAddress(&ph, g_h);
    cudaGetSymbolAddress(&plast, g_last); cudaGetSymbolAddress(&plt, g_lt);
    __half* xh = (__half*)pxh;   __half* xl = (__half*)pxl;
    __half* hnh = (__half*)phnh; __half* hnl = (__half*)phnl;
    __half* th = (__half*)pth;   __half* tl = (__half*)ptl;
    __half* wfh = (__half*)pwfh; __half* wfl = (__half*)pwfl;
    __half* qf = (__half*)pqf;   __half* kf = (__half*)pkf;
    __half* vf = (__half*)pvf;   __half* sf = (__half*)psf;
    float* h = (float*)ph;
    float* last = (float*)plast; float* lt = (float*)plt;

    const float scale = 0.044194173824159216f;  // 1/sqrt(512)

    gather_split<<<MTOT * 128 / 256, 256>>>(seq, feats, emb);
    convw_all<<<dim3(WMAT / 4 / 256, 8), 256>>>(Wq, Wk, Wv, W1, W2);

    const dim3 gqkv(MTOT / 128, 1536 / 128);         // 128 x 12
    const dim3 gw(MTOT / 128, DMODEL / 128);         // 128 x 4
    const dim3 gs(SEQ / 256, SEQ / 128, NBATCH);     // 8 x 16 x 8
    const dim3 ga(SEQ / 256, DMODEL / 128, NBATCH);  // 8 x 4 x 8

    for (int l = 0; l < 2; l++) {
        const int bo = l * DMODEL;
        const size_t mqkv = (size_t)(l ? 5 : 0) * WMAT;

        if (l == 0)
            mma_gemm<4, 3><<<gqkv, 512, SMEM_TC>>>(xh, xl, wfh + mqkv, wfl + mqkv,
                                                   bq + bo, bk + bo, bv + bo,
                                                   qf, nullptr, kf, vf);
        else
            mma_gemm<4, 2><<<gqkv, 512, SMEM_TC>>>(xh, xl, wfh + mqkv, wfl + mqkv,
                                                   bq + bo, bk + bo, bv + bo,
                                                   qf, nullptr, kf, vf);

        mma_attn<0><<<gs, 512, SMEM_AT>>>(qf, kf, sf, nullptr, DMODEL, DMODEL,
                                          (size_t)SEQ * DMODEL, (size_t)SEQ * DMODEL,
                                          (size_t)SEQ * SEQ, scale);
        mma_attn<1><<<ga, 512, SMEM_AT>>>(sf, vf, nullptr, h, SEQ, DMODEL,
                                          (size_t)SEQ * SEQ, (size_t)SEQ * DMODEL,
                                          (size_t)SEQ * DMODEL, 0.f);

        if (l == 0) {
            norm_fused<0><<<dim3(NBATCH, DMODEL / 32), dim3(32, 8)>>>(h);
            const size_t m1 = 3 * (size_t)WMAT, m2 = 4 * (size_t)WMAT;
            mma_gemm<1, 3><<<gw, 512, SMEM_TC>>>(hnh, hnl, wfh + m1, wfl + m1,
                                                 b1 + bo, nullptr, nullptr,
                                                 th, tl, nullptr, nullptr);
            mma_gemm<0, 3><<<gw, 512, SMEM_TC>>>(th, tl, wfh + m2, wfl + m2,
                                                 b2 + bo, nullptr, nullptr,
                                                 xh, xl, nullptr, nullptr);
        } else {
            norm_fused<1><<<dim3(NBATCH, DMODEL / 32), dim3(32, 8)>>>(h);
            small_gemm<true><<<16, 256>>>(last, W1 + (size_t)WMAT, b1 + bo, lt);
            small_gemm<false><<<16, 256>>>(lt, W2 + (size_t)WMAT, b2 + bo, out);
        }
    }
}

// round 13
// speedup vs baseline: 4.8616x; 1.0219x over previous
#include <cuda_runtime.h>
#include <cuda_fp16.h>
#include <math.h>
#include <stdint.h>

#define EMB_DIM 448
#define FEAT_DIM 64
#define DMODEL 512
#define NBATCH 8
#define SEQ 2048
#define MTOT (NBATCH * SEQ)
#define WMAT (DMODEL * DMODEL)

// -------- scratch (device globals) --------
static __device__ __half g_xh[MTOT * DMODEL], g_xl[MTOT * DMODEL];
static __device__ __half g_hnh[MTOT * DMODEL], g_hnl[MTOT * DMODEL];
static __device__ __half g_th[MTOT * DMODEL], g_tl[MTOT * DMODEL];
static __device__ __half g_wfh[8 * WMAT], g_wfl[8 * WMAT];  // fp16 hi/lo weights
static __device__ __half g_qf[MTOT * DMODEL], g_kf[MTOT * DMODEL];
static __device__ __half g_vf[MTOT * DMODEL];
static __device__ __half g_sf[(size_t)NBATCH * SEQ * SEQ];
static __device__ float g_h[MTOT * DMODEL];
static __device__ float g_last[NBATCH * DMODEL], g_lt[NBATCH * DMODEL];

__device__ __forceinline__ uint32_t smem_u32(const void* p) {
    uint32_t a;
    asm("{ .reg .u64 t; cvta.to.shared.u64 t, %1; cvt.u32.u64 %0, t; }" : "=r"(a) : "l"(p));
    return a;
}
#define SWZ(o) ((o) ^ ((((uint32_t)(o)) >> 3) & 0x70))
// projection GEMM stage: Ahi 16K | Alo 16K | Bhi 16K | Blo 16K
#define OFF_ALO 16384u
#define OFF_BHI 32768u
#define OFF_BLO 49152u
#define STAGE_B 65536u
#define SMEM_TC 196608
// attention stages (128x128 CTA): A 16K + B 16K = 32K/stage, 3 stages
#define AT_OFF_B 16384u
#define AT_STAGE 32768u
#define SMEM_AT 98304

__device__ __forceinline__ void ldm_x4(uint32_t* r, uint32_t addr) {
    asm volatile("ldmatrix.sync.aligned.m8n8.x4.shared.b16 {%0,%1,%2,%3}, [%4];"
                 : "=r"(r[0]), "=r"(r[1]), "=r"(r[2]), "=r"(r[3]) : "r"(addr));
}
__device__ __forceinline__ void ldm_x4t(uint32_t* r, uint32_t addr) {
    asm volatile("ldmatrix.sync.aligned.m8n8.x4.trans.shared.b16 {%0,%1,%2,%3}, [%4];"
                 : "=r"(r[0]), "=r"(r[1]), "=r"(r[2]), "=r"(r[3]) : "r"(addr));
}
__device__ __forceinline__ void mma16816h(float* c, const uint32_t* a, const uint32_t* b) {
    asm volatile(
        "mma.sync.aligned.m16n8k16.row.col.f32.f16.f16.f32 "
        "{%0,%1,%2,%3}, {%4,%5,%6,%7}, {%8,%9}, {%0,%1,%2,%3};"
        : "+f"(c[0]), "+f"(c[1]), "+f"(c[2]), "+f"(c[3])
        : "r"(a[0]), "r"(a[1]), "r"(a[2]), "r"(a[3]), "r"(b[0]), "r"(b[1]));
}
__device__ __forceinline__ void cpa16(uint32_t dst, const void* src) {
    asm volatile("cp.async.cg.shared.global [%0], [%1], 16;" :: "r"(dst), "l"(src));
}
#define CPA_COMMIT() asm volatile("cp.async.commit_group;" ::: "memory")

__device__ __forceinline__ void split4h(float4 f, uint2& h, uint2& l) {
    __half2 h0 = __floats2half2_rn(f.x, f.y);
    __half2 h1 = __floats2half2_rn(f.z, f.w);
    __half2 l0 = __floats2half2_rn(f.x - __half2float(h0.x), f.y - __half2float(h0.y));
    __half2 l1 = __floats2half2_rn(f.z - __half2float(h1.x), f.w - __half2float(h1.y));
    h.x = *(uint32_t*)&h0; h.y = *(uint32_t*)&h1;
    l.x = *(uint32_t*)&l0; l.y = *(uint32_t*)&l1;
}

// ============ fp16 split projection/MLP GEMM (512 thr, CTA 128x128) ============
// MODE: 0=bias->hi/lo, 1=bias+relu->hi/lo, 4=fused QKV (Q,K,V all fp16)
template <int MODE, int PASSES>
__global__ void __launch_bounds__(512) mma_gemm(const __half* __restrict__ Ah, const __half* __restrict__ Al,
                                                const __half* __restrict__ Bh, const __half* __restrict__ Bl,
                                                const float* __restrict__ bias, const float* __restrict__ bias2,
                                                const float* __restrict__ bias3,
                                                __half* __restrict__ Ch, __half* __restrict__ Cl,
                                                __half* __restrict__ C2h, __half* __restrict__ C3h) {
    extern __shared__ char smem[];
    const int tid = threadIdx.x, wid = tid >> 5, lane = tid & 31;
    const int bm = blockIdx.x, bn = blockIdx.y;
    Ah += (size_t)bm * 128 * DMODEL;
    Al += (size_t)bm * 128 * DMODEL;
    Bh += (size_t)bn * 128 * DMODEL;
    Bl += (size_t)bn * 128 * DMODEL;
    const int NC = DMODEL >> 6;  // 8
    const uint32_t sb = smem_u32(smem);
    const int wm = wid >> 2, wn = wid & 3;  // warp grid 4x4, warp tile 32x32
    const int lr = lane & 15, lc16 = (lane >> 4) * 16;

    float acc[2][4][4];
#pragma unroll
    for (int i = 0; i < 2; i++)
#pragma unroll
        for (int j = 0; j < 4; j++)
#pragma unroll
            for (int r = 0; r < 4; r++) acc[i][j][r] = 0.f;

#define STAGE_LOAD(S, CIDX) do { \
        uint32_t base_ = sb + (uint32_t)(S) * STAGE_B; \
        int koff_ = (CIDX) * 64; \
        _Pragma("unroll") \
        for (int j_ = 0; j_ < 2; j_++) { \
            int cc_ = tid + j_ * 512; \
            int r_ = cc_ >> 3, cg_ = cc_ & 7; \
            uint32_t so_ = SWZ((uint32_t)r_ * 128u + (uint32_t)cg_ * 16u); \
            size_t g_ = (size_t)r_ * DMODEL + koff_ + cg_ * 8; \
            cpa16(base_ + so_, Ah + g_); \
            cpa16(base_ + OFF_ALO + so_, Al + g_); \
            cpa16(base_ + OFF_BHI + so_, Bh + g_); \
            if (PASSES == 3) cpa16(base_ + OFF_BLO + so_, Bl + g_); \
        } \
        CPA_COMMIT(); \
    } while (0)

    uint32_t ah[2][2][4], al[2][2][4], bhf[2][4][2], blf[2][4][2];
#define LDFRAG(BUF, KS) do { \
        const uint32_t kb_ = (KS) * 32 + lc16; \
        _Pragma("unroll") \
        for (int mb_ = 0; mb_ < 2; mb_++) { \
            uint32_t ro_ = (uint32_t)(wm * 32 + mb_ * 16 + lr) * 128u + kb_; \
            ldm_x4(ah[BUF][mb_], base + SWZ(ro_)); \
            ldm_x4(al[BUF][mb_], base + OFF_ALO + SWZ(ro_)); \
        } \
        _Pragma("unroll") \
        for (int n2_ = 0; n2_ < 2; n2_++) { \
            uint32_t ro_ = (uint32_t)(wn * 32 + n2_ * 16 + lr) * 128u + kb_; \
            uint32_t t_[4]; \
            ldm_x4(t_, base + OFF_BHI + SWZ(ro_)); \
            bhf[BUF][n2_ * 2][0] = t_[0]; bhf[BUF][n2_ * 2][1] = t_[2]; \
            bhf[BUF][n2_ * 2 + 1][0] = t_[1]; bhf[BUF][n2_ * 2 + 1][1] = t_[3]; \
            if (PASSES == 3) { \
                ldm_x4(t_, base + OFF_BLO + SWZ(ro_)); \
                blf[BUF][n2_ * 2][0] = t_[0]; blf[BUF][n2_ * 2][1] = t_[2]; \
                blf[BUF][n2_ * 2 + 1][0] = t_[1]; blf[BUF][n2_ * 2 + 1][1] = t_[3]; \
            } \
        } \
    } while (0)

    STAGE_LOAD(0, 0);
    STAGE_LOAD(1, 1);

    for (int c = 0; c < NC; c++) {
        if (c + 1 < NC) asm volatile("cp.async.wait_group 1;" ::: "memory");
        else            asm volatile("cp.async.wait_group 0;" ::: "memory");
        __syncthreads();
        const uint32_t base = sb + (uint32_t)(((uint32_t)c) % 3u) * STAGE_B;
        LDFRAG(0, 0);
#pragma unroll
        for (int ks = 0; ks < 4; ks++) {
            const int cur = ks & 1;
            if (ks < 3) LDFRAG(!(ks & 1), ks + 1);
#pragma unroll
            for (int mb = 0; mb < 2; mb++)
#pragma unroll
                for (int nb = 0; nb < 4; nb++)
                    mma16816h(acc[mb][nb], ah[cur][mb], bhf[cur][nb]);
#pragma unroll
            for (int mb = 0; mb < 2; mb++)
#pragma unroll
                for (int nb = 0; nb < 4; nb++)
                    mma16816h(acc[mb][nb], al[cur][mb], bhf[cur][nb]);
            if (PASSES == 3) {
#pragma unroll
                for (int mb = 0; mb < 2; mb++)
#pragma unroll
                    for (int nb = 0; nb < 4; nb++)
                        mma16816h(acc[mb][nb], ah[cur][mb], blf[cur][nb]);
            }
        }
        if (c + 2 < NC) STAGE_LOAD(((uint32_t)(c + 2)) % 3u, c + 2);
    }
#undef STAGE_LOAD
#undef LDFRAG

    const int g = lane >> 2, t4 = lane & 3;
    const int region = (MODE == 4) ? (bn >> 2) : 0;
#pragma unroll
    for (int mb = 0; mb < 2; mb++) {
        const int mbase = bm * 128 + wm * 32 + mb * 16 + g;
#pragma unroll
        for (int nb = 0; nb < 4; nb++) {
            const int n0 = bn * 128 + wn * 32 + nb * 8 + t4 * 2;
#pragma unroll
            for (int rr = 0; rr < 2; rr++) {
                const int m = mbase + rr * 8;
                float v0 = acc[mb][nb][rr * 2], v1 = acc[mb][nb][rr * 2 + 1];
                if (MODE == 0) { v0 += bias[n0]; v1 += bias[n0 + 1]; }
                if (MODE == 1) { v0 = fmaxf(v0 + bias[n0], 0.f); v1 = fmaxf(v1 + bias[n0 + 1], 0.f); }
                if (MODE == 0 || MODE == 1) {
                    __half2 hv = __floats2half2_rn(v0, v1);
                    __half2 lv = __floats2half2_rn(v0 - __half2float(hv.x), v1 - __half2float(hv.y));
                    *(__half2*)(Ch + (size_t)m * DMODEL + n0) = hv;
                    *(__half2*)(Cl + (size_t)m * DMODEL + n0) = lv;
                } else {  // MODE 4: region 0=Q, 1=K, 2=V — all fp16
                    const int nl = n0 - (region << 9);
                    if (region == 0) {
                        *(__half2*)(Ch + (size_t)m * DMODEL + nl) =
                            __floats2half2_rn(v0 + bias[nl], v1 + bias[nl + 1]);
                    } else if (region == 1) {
                        *(__half2*)(C2h + (size_t)m * DMODEL + nl) =
                            __floats2half2_rn(v0 + bias2[nl], v1 + bias2[nl + 1]);
                    } else {
                        *(__half2*)(C3h + (size_t)m * DMODEL + nl) =
                            __floats2half2_rn(v0 + bias3[nl], v1 + bias3[nl + 1]);
                    }
                }
            }
        }
    }
}

// ============ fp16 single-pass attention GEMM (CTA 128x128, 256 thr, 2 CTA/SM) ============
// MODE 0: scores = tril(QK^T)*scale -> fp16 ; B = K rows (K-major)
// MODE 1: h = S @ V -> fp32, causal K bound; B = V [s][d] via ldmatrix.trans
// warp grid 2m x 4n, warp tile 64x32
template <int MODE>
__global__ void __launch_bounds__(256, 2) mma_attn(const __half* __restrict__ A, const __half* __restrict__ B,
                                                   __half* __restrict__ Sout, float* __restrict__ Hout,
                                                   int lda, int ldb,
                                                   size_t sA, size_t sB, size_t sC, float scale) {
    extern __shared__ char smem[];
    const int tid = threadIdx.x, wid = tid >> 5, lane = tid & 31;
    const int bm = blockIdx.x, bn = blockIdx.y, bz = blockIdx.z;
    if (MODE == 0 && bn > bm) return;  // fully-masked 128x128 tile
    A += sA * bz + (size_t)bm * 128 * lda;
    if (MODE == 0) B += sB * bz + (size_t)bn * 128 * ldb;  // row offset (n = s-rows of K)
    else           B += sB * bz + (size_t)bn * 128;        // column offset (d) into V[s][d]
    const int NC = (MODE == 1) ? (bm + 1) * 2 : 8;
    const uint32_t sb = smem_u32(smem);
    const int wm = wid >> 2, wn = wid & 3;  // 2m x 4n
    const int lr = lane & 15, lc16 = (lane >> 4) * 16;

    float acc[4][4][4];
#pragma unroll
    for (int i = 0; i < 4; i++)
#pragma unroll
        for (int j = 0; j < 4; j++)
#pragma unroll
            for (int r = 0; r < 4; r++) acc[i][j][r] = 0.f;

#define AT_LOAD(S, CIDX) do { \
        uint32_t base_ = sb + (uint32_t)(S) * AT_STAGE; \
        int koff_ = (CIDX) * 64; \
        _Pragma("unroll") \
        for (int j_ = 0; j_ < 4; j_++) { \
            int cc_ = tid + j_ * 256; \
            int r_ = cc_ >> 3, cg_ = cc_ & 7; \
            cpa16(base_ + SWZ((uint32_t)r_ * 128u + (uint32_t)cg_ * 16u), \
                  A + (size_t)r_ * lda + koff_ + cg_ * 8); \
        } \
        _Pragma("unroll") \
        for (int j_ = 0; j_ < 4; j_++) { \
            int cc_ = tid + j_ * 256; \
            if (MODE == 0) { \
                int r_ = cc_ >> 3, cg_ = cc_ & 7; \
                cpa16(base_ + AT_OFF_B + SWZ((uint32_t)r_ * 128u + (uint32_t)cg_ * 16u), \
                      B + (size_t)r_ * ldb + koff_ + cg_ * 8); \
            } else { \
                int r_ = cc_ >> 4, sub_ = (cc_ >> 3) & 1, cg_ = cc_ & 7; \
                cpa16(base_ + AT_OFF_B + (uint32_t)sub_ * 8192u + \
                          SWZ((uint32_t)r_ * 128u + (uint32_t)cg_ * 16u), \
                      B + (size_t)(koff_ + r_) * DMODEL + sub_ * 64 + cg_ * 8); \
            } \
        } \
        CPA_COMMIT(); \
    } while (0)

    AT_LOAD(0, 0);
    if (NC > 1) AT_LOAD(1, 1);

    for (int c = 0; c < NC; c++) {
        if (c + 1 < NC) asm volatile("cp.async.wait_group 1;" ::: "memory");
        else            asm volatile("cp.async.wait_group 0;" ::: "memory");
        __syncthreads();
        const uint32_t base = sb + (uint32_t)(((uint32_t)c) % 3u) * AT_STAGE;
#pragma unroll
        for (int ks = 0; ks < 4; ks++) {
            const uint32_t kb = ks * 32 + lc16;
            uint32_t ah[4][4], bh[4][2];
#pragma unroll
            for (int mb = 0; mb < 4; mb++) {
                uint32_t ro = (uint32_t)(wm * 64 + mb * 16 + lr) * 128u + kb;
                ldm_x4(ah[mb], base + SWZ(ro));
            }
#pragma unroll
            for (int n2 = 0; n2 < 2; n2++) {
                uint32_t t[4];
                if (MODE == 0) {
                    uint32_t ro = (uint32_t)(wn * 32 + n2 * 16 + lr) * 128u + kb;
                    ldm_x4(t, base + AT_OFF_B + SWZ(ro));
                    bh[n2 * 2][0] = t[0]; bh[n2 * 2][1] = t[2];
                    bh[n2 * 2 + 1][0] = t[1]; bh[n2 * 2 + 1][1] = t[3];
                } else {
                    int d_loc = wn * 32 + n2 * 16 + ((lane >> 4) << 3);
                    uint32_t row = (uint32_t)(ks * 16 + (lane & 15));
                    uint32_t addr = base + AT_OFF_B + ((uint32_t)(d_loc >> 6)) * 8192u +
                                    SWZ(row * 128u + (uint32_t)(d_loc & 63) * 2u);
                    ldm_x4t(t, addr);
                    bh[n2 * 2][0] = t[0]; bh[n2 * 2][1] = t[1];
                    bh[n2 * 2 + 1][0] = t[2]; bh[n2 * 2 + 1][1] = t[3];
                }
            }
#pragma unroll
            for (int mb = 0; mb < 4; mb++)
#pragma unroll
                for (int nb = 0; nb < 4; nb++)
                    mma16816h(acc[mb][nb], ah[mb], bh[nb]);
        }
        if (c + 2 < NC) AT_LOAD(((uint32_t)(c + 2)) % 3u, c + 2);
    }
#undef AT_LOAD

    const int g = lane >> 2, t4 = lane & 3;
    if (MODE == 0) Sout += sC * bz;
    else           Hout += sC * bz;
#pragma unroll
    for (int mb = 0; mb < 4; mb++) {
        const int mbase = bm * 128 + wm * 64 + mb * 16 + g;
#pragma unroll
        for (int nb = 0; nb < 4; nb++) {
            const int n0 = bn * 128 + wn * 32 + nb * 8 + t4 * 2;
#pragma unroll
            for (int rr = 0; rr < 2; rr++) {
                const int m = mbase + rr * 8;
                float v0 = acc[mb][nb][rr * 2], v1 = acc[mb][nb][rr * 2 + 1];
                if (MODE == 0) {
                    v0 = (n0 <= m) ? v0 * scale : 0.f;
                    v1 = (n0 + 1 <= m) ? v1 * scale : 0.f;
                    *(__half2*)(Sout + (size_t)m * SEQ + n0) = __floats2half2_rn(v0, v1);
                } else {
                    *(float2*)(Hout + (size_t)m * DMODEL + n0) = make_float2(v0, v1);
                }
            }
        }
    }
}

// ---------------- elementwise / small kernels ----------------
__global__ __launch_bounds__(256) void gather_split(const int* __restrict__ seq,
                                                    const float* __restrict__ feats,
                                                    const float* __restrict__ emb) {
    int i = blockIdx.x * 256 + threadIdx.x;
    int row = i >> 7, d = (i & 127) << 2;
    float4 val;
    if (d < EMB_DIM) val = *(const float4*)(emb + (size_t)seq[row] * EMB_DIM + d);
    else val = *(const float4*)(feats + (size_t)row * FEAT_DIM + (d - EMB_DIM));
    uint2 h, l;
    split4h(val, h, l);
    *(uint2*)(g_xh + ((size_t)row << 9) + d) = h;
    *(uint2*)(g_xl + ((size_t)row << 9) + d) = l;
}

__global__ __launch_bounds__(256) void convw_all(const float* __restrict__ Wq,
                                                 const float* __restrict__ Wk,
                                                 const float* __restrict__ Wv,
                                                 const float* __restrict__ W1,
                                                 const float* __restrict__ W2) {
    int midx = blockIdx.y;
    const float* src;
    switch (midx) {
        case 0: src = Wq; break;
        case 1: src = Wk; break;
        case 2: src = Wv; break;
        case 3: src = W1; break;
        case 4: src = W2; break;
        case 5: src = Wq + WMAT; break;
        case 6: src = Wk + WMAT; break;
        default: src = Wv + WMAT; break;
    }
    int i = (blockIdx.x * 256 + threadIdx.x) << 2;
    float4 f = *(const float4*)(src + i);
    uint2 h, l;
    split4h(f, h, l);
    *(uint2*)(g_wfh + (size_t)midx * WMAT + i) = h;
    *(uint2*)(g_wfl + (size_t)midx * WMAT + i) = l;
}

// fused stats + normalize. LAST=1: only emit last row into g_last
template <int LAST>
__global__ void norm_fused(const float* __restrict__ H) {
    const int b = blockIdx.x, tx = threadIdx.x, ty = threadIdx.y;
    const int d = blockIdx.y * 32 + tx;
    float sum = 0.f, sq = 0.f;
    for (int s = ty; s < SEQ; s += 8) {
        float v = H[(size_t)(b * SEQ + s) * DMODEL + d];
        sum += v; sq += v * v;
    }
    __shared__ float ss[8][32], s2[8][32], smean[32], srstd[32];
    ss[ty][tx] = sum; s2[ty][tx] = sq;
    __syncthreads();
    if (ty == 0) {
#pragma unroll
        for (int r = 1; r < 8; r++) { sum += ss[r][tx]; sq += s2[r][tx]; }
        float mean = sum * (1.0f / SEQ);
        float var = fmaxf((sq - sum * mean) * (1.0f / (SEQ - 1)), 0.0f);
        smean[tx] = mean;
        srstd[tx] = 1.0f / (sqrtf(var) + 2e-5f);
    }
    __syncthreads();
    const float mean = smean[tx], rstd = srstd[tx];
    if (LAST) {
        if (ty == 7) {
            float v = H[(size_t)(b * SEQ + SEQ - 1) * DMODEL + d];
            g_last[b * DMODEL + d] = (v - mean) * rstd;
        }
    } else {
        for (int s = ty; s < SEQ; s += 8) {
            float v = (H[(size_t)(b * SEQ + s) * DMODEL + d] - mean) * rstd;
            __half h = __float2half(v);
            __half l = __float2half(v - __half2float(h));
            g_hnh[(size_t)(b * SEQ + s) * DMODEL + d] = h;
            g_hnl[(size_t)(b * SEQ + s) * DMODEL + d] = l;
        }
    }
}

template <bool RELU>
__global__ void small_gemm(const float* __restrict__ A, const float* __restrict__ W,
                           const float* __restrict__ bias, float* __restrict__ C) {
    int i = blockIdx.x * 256 + threadIdx.x;  // 4096
    int m = i >> 9, n = i & 511;
    const float* a = A + (size_t)m * DMODEL;
    const float* w = W + (size_t)n * DMODEL;
    float s = 0.f;
#pragma unroll 8
    for (int k2 = 0; k2 < DMODEL; k2 += 4) {
        float4 av = *(const float4*)(a + k2), wv = *(const float4*)(w + k2);
        s += av.x * wv.x + av.y * wv.y + av.z * wv.z + av.w * wv.w;
    }
    s += bias[n];
    if (RELU) s = fmaxf(s, 0.0f);
    C[i] = s;
}

extern "C" void kernel_launch(void* const* d_in, const int* in_sizes, int n_in,
                              void* d_out, int out_size) {
    const int* seq = (const int*)d_in[0];
    const float* feats = (const float*)d_in[1];
    const float* emb = (const float*)d_in[2];
    const float* Wq = (const float*)d_in[3];  const float* bq = (const float*)d_in[4];
    const float* Wk = (const float*)d_in[5];  const float* bk = (const float*)d_in[6];
    const float* Wv = (const float*)d_in[7];  const float* bv = (const float*)d_in[8];
    const float* W1 = (const float*)d_in[9];  const float* b1 = (const float*)d_in[10];
    const float* W2 = (const float*)d_in[11]; const float* b2 = (const float*)d_in[12];
    float* out = (float*)d_out;

    cudaFuncSetAttribute(mma_gemm<0, 3>, cudaFuncAttributeMaxDynamicSharedMemorySize, SMEM_TC);
    cudaFuncSetAttribute(mma_gemm<1, 3>, cudaFuncAttributeMaxDynamicSharedMemorySize, SMEM_TC);
    cudaFuncSetAttribute(mma_gemm<4, 3>, cudaFuncAttributeMaxDynamicSharedMemorySize, SMEM_TC);
    cudaFuncSetAttribute(mma_gemm<4, 2>, cudaFuncAttributeMaxDynamicSharedMemorySize, SMEM_TC);
    cudaFuncSetAttribute(mma_attn<0>, cudaFuncAttributeMaxDynamicSharedMemorySize, SMEM_AT);
    cudaFuncSetAttribute(mma_attn<1>, cudaFuncAttributeMaxDynamicSharedMemorySize, SMEM_AT);

    void *pxh, *pxl, *phnh, *phnl, *pth, *ptl, *pwfh, *pwfl;
    void *pqf, *pkf, *pvf, *psf, *ph, *plast, *plt;
    cudaGetSymbolAddress(&pxh, g_xh);   cudaGetSymbolAddress(&pxl, g_xl);
    cudaGetSymbolAddress(&phnh, g_hnh); cudaGetSymbolAddress(&phnl, g_hnl);
    cudaGetSymbolAddress(&pth, g_th);   cudaGetSymbolAddress(&ptl, g_tl);
    cudaGetSymbolAddress(&pwfh, g_wfh); cudaGetSymbolAddress(&pwfl, g_wfl);
    cudaGetSymbolAddress(&pqf, g_qf);   cudaGetSymbolAddress(&pkf, g_kf);
    cudaGetSymbolAddress(&pvf, g_vf);   cudaGetSymbolAddress(&psf, g_sf);
    cudaGetSymbolAddress(&ph, g_h);
    cudaGetSymbolAddress(&plast, g_last); cudaGetSymbolAddress(&plt, g_lt);
    __half* xh = (__half*)pxh;   __half* xl = (__half*)pxl;
    __half* hnh = (__half*)phnh; __half* hnl = (__half*)phnl;
    __half* th = (__half*)pth;   __half* tl = (__half*)ptl;
    __half* wfh = (__half*)pwfh; __half* wfl = (__half*)pwfl;
    __half* qf = (__half*)pqf;   __half* kf = (__half*)pkf;
    __half* vf = (__half*)pvf;   __half* sf = (__half*)psf;
    float* h = (float*)ph;
    float* last = (float*)plast; float* lt = (float*)plt;

    const float scale = 0.044194173824159216f;  // 1/sqrt(512)

    gather_split<<<MTOT * 128 / 256, 256>>>(seq, feats, emb);
    convw_all<<<dim3(WMAT / 4 / 256, 8), 256>>>(Wq, Wk, Wv, W1, W2);

    const dim3 gqkv(MTOT / 128, 1536 / 128);         // 128 x 12
    const dim3 gw(MTOT / 128, DMODEL / 128);         // 128 x 4
    const dim3 gs(SEQ / 128, SEQ / 128, NBATCH);     // 16 x 16 x 8
    const dim3 ga(SEQ / 128, DMODEL / 128, NBATCH);  // 16 x 4 x 8

    for (int l = 0; l < 2; l++) {
        const int bo = l * DMODEL;
        const size_t mqkv = (size_t)(l ? 5 : 0) * WMAT;

        if (l == 0)
            mma_gemm<4, 3><<<gqkv, 512, SMEM_TC>>>(xh, xl, wfh + mqkv, wfl + mqkv,
                                                   bq + bo, bk + bo, bv + bo,
                                                   qf, nullptr, kf, vf);
        else
            mma_gemm<4, 2><<<gqkv, 512, SMEM_TC>>>(xh, xl, wfh + mqkv, wfl + mqkv,
                                                   bq + bo, bk + bo, bv + bo,
                                                   qf, nullptr, kf, vf);

        mma_attn<0><<<gs, 256, SMEM_AT>>>(qf, kf, sf, nullptr, DMODEL, DMODEL,
                                          (size_t)SEQ * DMODEL, (size_t)SEQ * DMODEL,
                                          (size_t)SEQ * SEQ, scale);
        mma_attn<1><<<ga, 256, SMEM_AT>>>(sf, vf, nullptr, h, SEQ, DMODEL,
                                          (size_t)SEQ * SEQ, (size_t)SEQ * DMODEL,
                                          (size_t)SEQ * DMODEL, 0.f);

        if (l == 0) {
            norm_fused<0><<<dim3(NBATCH, DMODEL / 32), dim3(32, 8)>>>(h);
            const size_t m1 = 3 * (size_t)WMAT, m2 = 4 * (size_t)WMAT;
            mma_gemm<1, 3><<<gw, 512, SMEM_TC>>>(hnh, hnl, wfh + m1, wfl + m1,
                                                 b1 + bo, nullptr, nullptr,
                                                 th, tl, nullptr, nullptr);
            mma_gemm<0, 3><<<gw, 512, SMEM_TC>>>(th, tl, wfh + m2, wfl + m2,
                                                 b2 + bo, nullptr, nullptr,
                                                 xh, xl, nullptr, nullptr);
        } else {
            norm_fused<1><<<dim3(NBATCH, DMODEL / 32), dim3(32, 8)>>>(h);
            small_gemm<true><<<16, 256>>>(last, W1 + (size_t)WMAT, b1 + bo, lt);
            small_gemm<false><<<16, 256>>>(lt, W2 + (size_t)WMAT, b2 + bo, out);
        }
    }
}

// round 14
// speedup vs baseline: 4.9488x; 1.0180x over previous
#include <cuda_runtime.h>
#include <cuda_fp16.h>
#include <math.h>
#include <stdint.h>

#define EMB_DIM 448
#define FEAT_DIM 64
#define DMODEL 512
#define NBATCH 8
#define SEQ 2048
#define MTOT (NBATCH * SEQ)
#define WMAT (DMODEL * DMODEL)

// -------- scratch (device globals) --------
static __device__ __half g_xh[MTOT * DMODEL], g_xl[MTOT * DMODEL];
static __device__ __half g_hnh[MTOT * DMODEL], g_hnl[MTOT * DMODEL];
static __device__ __half g_th[MTOT * DMODEL], g_tl[MTOT * DMODEL];
static __device__ __half g_wfh[8 * WMAT], g_wfl[8 * WMAT];  // fp16 hi/lo weights
static __device__ __half g_qf[MTOT * DMODEL], g_kf[MTOT * DMODEL];
static __device__ __half g_vf[MTOT * DMODEL];
static __device__ __half g_sf[(size_t)NBATCH * SEQ * SEQ];
static __device__ float g_h[MTOT * DMODEL];
static __device__ float g_last[NBATCH * DMODEL], g_lt[NBATCH * DMODEL];

__device__ __forceinline__ uint32_t smem_u32(const void* p) {
    uint32_t a;
    asm("{ .reg .u64 t; cvta.to.shared.u64 t, %1; cvt.u32.u64 %0, t; }" : "=r"(a) : "l"(p));
    return a;
}
#define SWZ(o) ((o) ^ ((((uint32_t)(o)) >> 3) & 0x70))
// projection GEMM stage: Ahi 16K | Alo 16K | Bhi 16K | Blo 16K
#define OFF_ALO 16384u
#define OFF_BHI 32768u
#define OFF_BLO 49152u
#define STAGE_B 65536u
#define SMEM_TC 196608
// attention stages (64x128 CTA): A 8K + B 16K = 24K/stage, 3 stages -> 72K (3 CTA/SM)
#define AT_OFF_B 8192u
#define AT_STAGE 24576u
#define SMEM_AT 73728

__device__ __forceinline__ void ldm_x4(uint32_t* r, uint32_t addr) {
    asm volatile("ldmatrix.sync.aligned.m8n8.x4.shared.b16 {%0,%1,%2,%3}, [%4];"
                 : "=r"(r[0]), "=r"(r[1]), "=r"(r[2]), "=r"(r[3]) : "r"(addr));
}
__device__ __forceinline__ void ldm_x4t(uint32_t* r, uint32_t addr) {
    asm volatile("ldmatrix.sync.aligned.m8n8.x4.trans.shared.b16 {%0,%1,%2,%3}, [%4];"
                 : "=r"(r[0]), "=r"(r[1]), "=r"(r[2]), "=r"(r[3]) : "r"(addr));
}
__device__ __forceinline__ void mma16816h(float* c, const uint32_t* a, const uint32_t* b) {
    asm volatile(
        "mma.sync.aligned.m16n8k16.row.col.f32.f16.f16.f32 "
        "{%0,%1,%2,%3}, {%4,%5,%6,%7}, {%8,%9}, {%0,%1,%2,%3};"
        : "+f"(c[0]), "+f"(c[1]), "+f"(c[2]), "+f"(c[3])
        : "r"(a[0]), "r"(a[1]), "r"(a[2]), "r"(a[3]), "r"(b[0]), "r"(b[1]));
}
__device__ __forceinline__ void cpa16(uint32_t dst, const void* src) {
    asm volatile("cp.async.cg.shared.global [%0], [%1], 16;" :: "r"(dst), "l"(src));
}
#define CPA_COMMIT() asm volatile("cp.async.commit_group;" ::: "memory")

__device__ __forceinline__ void split4h(float4 f, uint2& h, uint2& l) {
    __half2 h0 = __floats2half2_rn(f.x, f.y);
    __half2 h1 = __floats2half2_rn(f.z, f.w);
    __half2 l0 = __floats2half2_rn(f.x - __half2float(h0.x), f.y - __half2float(h0.y));
    __half2 l1 = __floats2half2_rn(f.z - __half2float(h1.x), f.w - __half2float(h1.y));
    h.x = *(uint32_t*)&h0; h.y = *(uint32_t*)&h1;
    l.x = *(uint32_t*)&l0; l.y = *(uint32_t*)&l1;
}

// ============ fp16 split projection/MLP GEMM (512 thr, CTA 128x128) ============
// MODE: 0=bias->hi/lo, 1=bias+relu->hi/lo, 4=fused QKV (Q,K,V all fp16)
template <int MODE, int PASSES>
__global__ void __launch_bounds__(512) mma_gemm(const __half* __restrict__ Ah, const __half* __restrict__ Al,
                                                const __half* __restrict__ Bh, const __half* __restrict__ Bl,
                                                const float* __restrict__ bias, const float* __restrict__ bias2,
                                                const float* __restrict__ bias3,
                                                __half* __restrict__ Ch, __half* __restrict__ Cl,
                                                __half* __restrict__ C2h, __half* __restrict__ C3h) {
    extern __shared__ char smem[];
    const int tid = threadIdx.x, wid = tid >> 5, lane = tid & 31;
    const int bm = blockIdx.x, bn = blockIdx.y;
    Ah += (size_t)bm * 128 * DMODEL;
    Al += (size_t)bm * 128 * DMODEL;
    Bh += (size_t)bn * 128 * DMODEL;
    Bl += (size_t)bn * 128 * DMODEL;
    const int NC = DMODEL >> 6;  // 8
    const uint32_t sb = smem_u32(smem);
    const int wm = wid >> 2, wn = wid & 3;  // warp grid 4x4, warp tile 32x32
    const int lr = lane & 15, lc16 = (lane >> 4) * 16;

    float acc[2][4][4];
#pragma unroll
    for (int i = 0; i < 2; i++)
#pragma unroll
        for (int j = 0; j < 4; j++)
#pragma unroll
            for (int r = 0; r < 4; r++) acc[i][j][r] = 0.f;

#define STAGE_LOAD(S, CIDX) do { \
        uint32_t base_ = sb + (uint32_t)(S) * STAGE_B; \
        int koff_ = (CIDX) * 64; \
        _Pragma("unroll") \
        for (int j_ = 0; j_ < 2; j_++) { \
            int cc_ = tid + j_ * 512; \
            int r_ = cc_ >> 3, cg_ = cc_ & 7; \
            uint32_t so_ = SWZ((uint32_t)r_ * 128u + (uint32_t)cg_ * 16u); \
            size_t g_ = (size_t)r_ * DMODEL + koff_ + cg_ * 8; \
            cpa16(base_ + so_, Ah + g_); \
            cpa16(base_ + OFF_ALO + so_, Al + g_); \
            cpa16(base_ + OFF_BHI + so_, Bh + g_); \
            if (PASSES == 3) cpa16(base_ + OFF_BLO + so_, Bl + g_); \
        } \
        CPA_COMMIT(); \
    } while (0)

    uint32_t ah[2][2][4], al[2][2][4], bhf[2][4][2], blf[2][4][2];
#define LDFRAG(BUF, KS) do { \
        const uint32_t kb_ = (KS) * 32 + lc16; \
        _Pragma("unroll") \
        for (int mb_ = 0; mb_ < 2; mb_++) { \
            uint32_t ro_ = (uint32_t)(wm * 32 + mb_ * 16 + lr) * 128u + kb_; \
            ldm_x4(ah[BUF][mb_], base + SWZ(ro_)); \
            ldm_x4(al[BUF][mb_], base + OFF_ALO + SWZ(ro_)); \
        } \
        _Pragma("unroll") \
        for (int n2_ = 0; n2_ < 2; n2_++) { \
            uint32_t ro_ = (uint32_t)(wn * 32 + n2_ * 16 + lr) * 128u + kb_; \
            uint32_t t_[4]; \
            ldm_x4(t_, base + OFF_BHI + SWZ(ro_)); \
            bhf[BUF][n2_ * 2][0] = t_[0]; bhf[BUF][n2_ * 2][1] = t_[2]; \
            bhf[BUF][n2_ * 2 + 1][0] = t_[1]; bhf[BUF][n2_ * 2 + 1][1] = t_[3]; \
            if (PASSES == 3) { \
                ldm_x4(t_, base + OFF_BLO + SWZ(ro_)); \
                blf[BUF][n2_ * 2][0] = t_[0]; blf[BUF][n2_ * 2][1] = t_[2]; \
                blf[BUF][n2_ * 2 + 1][0] = t_[1]; blf[BUF][n2_ * 2 + 1][1] = t_[3]; \
            } \
        } \
    } while (0)

    STAGE_LOAD(0, 0);
    STAGE_LOAD(1, 1);

    for (int c = 0; c < NC; c++) {
        if (c + 1 < NC) asm volatile("cp.async.wait_group 1;" ::: "memory");
        else            asm volatile("cp.async.wait_group 0;" ::: "memory");
        __syncthreads();
        const uint32_t base = sb + (uint32_t)(((uint32_t)c) % 3u) * STAGE_B;
        LDFRAG(0, 0);
#pragma unroll
        for (int ks = 0; ks < 4; ks++) {
            const int cur = ks & 1;
            if (ks < 3) LDFRAG(!(ks & 1), ks + 1);
#pragma unroll
            for (int mb = 0; mb < 2; mb++)
#pragma unroll
                for (int nb = 0; nb < 4; nb++)
                    mma16816h(acc[mb][nb], ah[cur][mb], bhf[cur][nb]);
#pragma unroll
            for (int mb = 0; mb < 2; mb++)
#pragma unroll
                for (int nb = 0; nb < 4; nb++)
                    mma16816h(acc[mb][nb], al[cur][mb], bhf[cur][nb]);
            if (PASSES == 3) {
#pragma unroll
                for (int mb = 0; mb < 2; mb++)
#pragma unroll
                    for (int nb = 0; nb < 4; nb++)
                        mma16816h(acc[mb][nb], ah[cur][mb], blf[cur][nb]);
            }
        }
        if (c + 2 < NC) STAGE_LOAD(((uint32_t)(c + 2)) % 3u, c + 2);
    }
#undef STAGE_LOAD
#undef LDFRAG

    const int g = lane >> 2, t4 = lane & 3;
    const int region = (MODE == 4) ? (bn >> 2) : 0;
#pragma unroll
    for (int mb = 0; mb < 2; mb++) {
        const int mbase = bm * 128 + wm * 32 + mb * 16 + g;
#pragma unroll
        for (int nb = 0; nb < 4; nb++) {
            const int n0 = bn * 128 + wn * 32 + nb * 8 + t4 * 2;
#pragma unroll
            for (int rr = 0; rr < 2; rr++) {
                const int m = mbase + rr * 8;
                float v0 = acc[mb][nb][rr * 2], v1 = acc[mb][nb][rr * 2 + 1];
                if (MODE == 0) { v0 += bias[n0]; v1 += bias[n0 + 1]; }
                if (MODE == 1) { v0 = fmaxf(v0 + bias[n0], 0.f); v1 = fmaxf(v1 + bias[n0 + 1], 0.f); }
                if (MODE == 0 || MODE == 1) {
                    __half2 hv = __floats2half2_rn(v0, v1);
                    __half2 lv = __floats2half2_rn(v0 - __half2float(hv.x), v1 - __half2float(hv.y));
                    *(__half2*)(Ch + (size_t)m * DMODEL + n0) = hv;
                    *(__half2*)(Cl + (size_t)m * DMODEL + n0) = lv;
                } else {  // MODE 4: region 0=Q, 1=K, 2=V — all fp16
                    const int nl = n0 - (region << 9);
                    if (region == 0) {
                        *(__half2*)(Ch + (size_t)m * DMODEL + nl) =
                            __floats2half2_rn(v0 + bias[nl], v1 + bias[nl + 1]);
                    } else if (region == 1) {
                        *(__half2*)(C2h + (size_t)m * DMODEL + nl) =
                            __floats2half2_rn(v0 + bias2[nl], v1 + bias2[nl + 1]);
                    } else {
                        *(__half2*)(C3h + (size_t)m * DMODEL + nl) =
                            __floats2half2_rn(v0 + bias3[nl], v1 + bias3[nl + 1]);
                    }
                }
            }
        }
    }
}

// ============ fp16 attention GEMM (CTA 64x128, 256 thr, target 3 CTA/SM) ============
// MODE 0: scores = tril(QK^T)*scale -> fp16 ; B = K rows (K-major)
// MODE 1: h = S @ V -> fp32, causal K bound; B = V [s][d] via ldmatrix.trans
// warp grid 2m x 4n, warp tile 32x32, single-buffered frags. bm reversed for tail packing.
template <int MODE>
__global__ void __launch_bounds__(256, 3) mma_attn(const __half* __restrict__ A, const __half* __restrict__ B,
                                                   __half* __restrict__ Sout, float* __restrict__ Hout,
                                                   int lda, int ldb,
                                                   size_t sA, size_t sB, size_t sC, float scale) {
    extern __shared__ char smem[];
    const int tid = threadIdx.x, wid = tid >> 5, lane = tid & 31;
    const int bm = gridDim.x - 1 - blockIdx.x;  // heavy tiles dispatched first
    const int bn = blockIdx.y, bz = blockIdx.z;
    if (MODE == 0 && 2 * bn > bm) return;  // fully-masked 64x128 tile
    A += sA * bz + (size_t)bm * 64 * lda;
    if (MODE == 0) B += sB * bz + (size_t)bn * 128 * ldb;  // row offset (n = s-rows of K)
    else           B += sB * bz + (size_t)bn * 128;        // column offset (d) into V[s][d]
    const int NC = (MODE == 1) ? (bm + 1) : 8;
    const uint32_t sb = smem_u32(smem);
    const int wm = wid >> 2, wn = wid & 3;  // 2m x 4n
    const int lr = lane & 15, lc16 = (lane >> 4) * 16;

    float acc[2][4][4];
#pragma unroll
    for (int i = 0; i < 2; i++)
#pragma unroll
        for (int j = 0; j < 4; j++)
#pragma unroll
            for (int r = 0; r < 4; r++) acc[i][j][r] = 0.f;

#define AT_LOAD(S, CIDX) do { \
        uint32_t base_ = sb + (uint32_t)(S) * AT_STAGE; \
        int koff_ = (CIDX) * 64; \
        _Pragma("unroll") \
        for (int j_ = 0; j_ < 2; j_++) { \
            int cc_ = tid + j_ * 256; \
            int r_ = cc_ >> 3, cg_ = cc_ & 7; \
            cpa16(base_ + SWZ((uint32_t)r_ * 128u + (uint32_t)cg_ * 16u), \
                  A + (size_t)r_ * lda + koff_ + cg_ * 8); \
        } \
        _Pragma("unroll") \
        for (int j_ = 0; j_ < 4; j_++) { \
            int cc_ = tid + j_ * 256; \
            if (MODE == 0) { \
                int r_ = cc_ >> 3, cg_ = cc_ & 7; \
                cpa16(base_ + AT_OFF_B + SWZ((uint32_t)r_ * 128u + (uint32_t)cg_ * 16u), \
                      B + (size_t)r_ * ldb + koff_ + cg_ * 8); \
            } else { \
                int r_ = cc_ >> 4, sub_ = (cc_ >> 3) & 1, cg_ = cc_ & 7; \
                cpa16(base_ + AT_OFF_B + (uint32_t)sub_ * 8192u + \
                          SWZ((uint32_t)r_ * 128u + (uint32_t)cg_ * 16u), \
                      B + (size_t)(koff_ + r_) * DMODEL + sub_ * 64 + cg_ * 8); \
            } \
        } \
        CPA_COMMIT(); \
    } while (0)

    AT_LOAD(0, 0);
    if (NC > 1) AT_LOAD(1, 1);

    for (int c = 0; c < NC; c++) {
        if (c + 1 < NC) asm volatile("cp.async.wait_group 1;" ::: "memory");
        else            asm volatile("cp.async.wait_group 0;" ::: "memory");
        __syncthreads();
        const uint32_t base = sb + (uint32_t)(((uint32_t)c) % 3u) * AT_STAGE;
#pragma unroll
        for (int ks = 0; ks < 4; ks++) {
            const uint32_t kb = ks * 32 + lc16;
            uint32_t ah[2][4], bh[4][2];
#pragma unroll
            for (int mb = 0; mb < 2; mb++) {
                uint32_t ro = (uint32_t)(wm * 32 + mb * 16 + lr) * 128u + kb;
                ldm_x4(ah[mb], base + SWZ(ro));
            }
#pragma unroll
            for (int n2 = 0; n2 < 2; n2++) {
                uint32_t t[4];
                if (MODE == 0) {
                    uint32_t ro = (uint32_t)(wn * 32 + n2 * 16 + lr) * 128u + kb;
                    ldm_x4(t, base + AT_OFF_B + SWZ(ro));
                    bh[n2 * 2][0] = t[0]; bh[n2 * 2][1] = t[2];
                    bh[n2 * 2 + 1][0] = t[1]; bh[n2 * 2 + 1][1] = t[3];
                } else {
                    int d_loc = wn * 32 + n2 * 16 + ((lane >> 4) << 3);
                    uint32_t row = (uint32_t)(ks * 16 + (lane & 15));
                    uint32_t addr = base + AT_OFF_B + ((uint32_t)(d_loc >> 6)) * 8192u +
                                    SWZ(row * 128u + (uint32_t)(d_loc & 63) * 2u);
                    ldm_x4t(t, addr);
                    bh[n2 * 2][0] = t[0]; bh[n2 * 2][1] = t[1];
                    bh[n2 * 2 + 1][0] = t[2]; bh[n2 * 2 + 1][1] = t[3];
                }
            }
#pragma unroll
            for (int mb = 0; mb < 2; mb++)
#pragma unroll
                for (int nb = 0; nb < 4; nb++)
                    mma16816h(acc[mb][nb], ah[mb], bh[nb]);
        }
        if (c + 2 < NC) AT_LOAD(((uint32_t)(c + 2)) % 3u, c + 2);
    }
#undef AT_LOAD

    const int g = lane >> 2, t4 = lane & 3;
    if (MODE == 0) Sout += sC * bz;
    else           Hout += sC * bz;
#pragma unroll
    for (int mb = 0; mb < 2; mb++) {
        const int mbase = bm * 64 + wm * 32 + mb * 16 + g;
#pragma unroll
        for (int nb = 0; nb < 4; nb++) {
            const int n0 = bn * 128 + wn * 32 + nb * 8 + t4 * 2;
#pragma unroll
            for (int rr = 0; rr < 2; rr++) {
                const int m = mbase + rr * 8;
                float v0 = acc[mb][nb][rr * 2], v1 = acc[mb][nb][rr * 2 + 1];
                if (MODE == 0) {
                    v0 = (n0 <= m) ? v0 * scale : 0.f;
                    v1 = (n0 + 1 <= m) ? v1 * scale : 0.f;
                    *(__half2*)(Sout + (size_t)m * SEQ + n0) = __floats2half2_rn(v0, v1);
                } else {
                    *(float2*)(Hout + (size_t)m * DMODEL + n0) = make_float2(v0, v1);
                }
            }
        }
    }
}

// ---------------- elementwise / small kernels ----------------
__global__ __launch_bounds__(256) void gather_split(const int* __restrict__ seq,
                                                    const float* __restrict__ feats,
                                                    const float* __restrict__ emb) {
    int i = blockIdx.x * 256 + threadIdx.x;
    int row = i >> 7, d = (i & 127) << 2;
    float4 val;
    if (d < EMB_DIM) val = *(const float4*)(emb + (size_t)seq[row] * EMB_DIM + d);
    else val = *(const float4*)(feats + (size_t)row * FEAT_DIM + (d - EMB_DIM));
    uint2 h, l;
    split4h(val, h, l);
    *(uint2*)(g_xh + ((size_t)row << 9) + d) = h;
    *(uint2*)(g_xl + ((size_t)row << 9) + d) = l;
}

__global__ __launch_bounds__(256) void convw_all(const float* __restrict__ Wq,
                                                 const float* __restrict__ Wk,
                                                 const float* __restrict__ Wv,
                                                 const float* __restrict__ W1,
                                                 const float* __restrict__ W2) {
    int midx = blockIdx.y;
    const float* src;
    switch (midx) {
        case 0: src = Wq; break;
        case 1: src = Wk; break;
        case 2: src = Wv; break;
        case 3: src = W1; break;
        case 4: src = W2; break;
        case 5: src = Wq + WMAT; break;
        case 6: src = Wk + WMAT; break;
        default: src = Wv + WMAT; break;
    }
    int i = (blockIdx.x * 256 + threadIdx.x) << 2;
    float4 f = *(const float4*)(src + i);
    uint2 h, l;
    split4h(f, h, l);
    *(uint2*)(g_wfh + (size_t)midx * WMAT + i) = h;
    *(uint2*)(g_wfl + (size_t)midx * WMAT + i) = l;
}

// fused stats + normalize. LAST=1: only emit last row into g_last
template <int LAST>
__global__ void norm_fused(const float* __restrict__ H) {
    const int b = blockIdx.x, tx = threadIdx.x, ty = threadIdx.y;
    const int d = blockIdx.y * 32 + tx;
    float sum = 0.f, sq = 0.f;
    for (int s = ty; s < SEQ; s += 8) {
        float v = H[(size_t)(b * SEQ + s) * DMODEL + d];
        sum += v; sq += v * v;
    }
    __shared__ float ss[8][32], s2[8][32], smean[32], srstd[32];
    ss[ty][tx] = sum; s2[ty][tx] = sq;
    __syncthreads();
    if (ty == 0) {
#pragma unroll
        for (int r = 1; r < 8; r++) { sum += ss[r][tx]; sq += s2[r][tx]; }
        float mean = sum * (1.0f / SEQ);
        float var = fmaxf((sq - sum * mean) * (1.0f / (SEQ - 1)), 0.0f);
        smean[tx] = mean;
        srstd[tx] = 1.0f / (sqrtf(var) + 2e-5f);
    }
    __syncthreads();
    const float mean = smean[tx], rstd = srstd[tx];
    if (LAST) {
        if (ty == 7) {
            float v = H[(size_t)(b * SEQ + SEQ - 1) * DMODEL + d];
            g_last[b * DMODEL + d] = (v - mean) * rstd;
        }
    } else {
        for (int s = ty; s < SEQ; s += 8) {
            float v = (H[(size_t)(b * SEQ + s) * DMODEL + d] - mean) * rstd;
            __half h = __float2half(v);
            __half l = __float2half(v - __half2float(h));
            g_hnh[(size_t)(b * SEQ + s) * DMODEL + d] = h;
            g_hnl[(size_t)(b * SEQ + s) * DMODEL + d] = l;
        }
    }
}

template <bool RELU>
__global__ void small_gemm(const float* __restrict__ A, const float* __restrict__ W,
                           const float* __restrict__ bias, float* __restrict__ C) {
    int i = blockIdx.x * 256 + threadIdx.x;  // 4096
    int m = i >> 9, n = i & 511;
    const float* a = A + (size_t)m * DMODEL;
    const float* w = W + (size_t)n * DMODEL;
    float s = 0.f;
#pragma unroll 8
    for (int k2 = 0; k2 < DMODEL; k2 += 4) {
        float4 av = *(const float4*)(a + k2), wv = *(const float4*)(w + k2);
        s += av.x * wv.x + av.y * wv.y + av.z * wv.z + av.w * wv.w;
    }
    s += bias[n];
    if (RELU) s = fmaxf(s, 0.0f);
    C[i] = s;
}

extern "C" void kernel_launch(void* const* d_in, const int* in_sizes, int n_in,
                              void* d_out, int out_size) {
    const int* seq = (const int*)d_in[0];
    const float* feats = (const float*)d_in[1];
    const float* emb = (const float*)d_in[2];
    const float* Wq = (const float*)d_in[3];  const float* bq = (const float*)d_in[4];
    const float* Wk = (const float*)d_in[5];  const float* bk = (const float*)d_in[6];
    const float* Wv = (const float*)d_in[7];  const float* bv = (const float*)d_in[8];
    const float* W1 = (const float*)d_in[9];  const float* b1 = (const float*)d_in[10];
    const float* W2 = (const float*)d_in[11]; const float* b2 = (const float*)d_in[12];
    float* out = (float*)d_out;

    cudaFuncSetAttribute(mma_gemm<0, 3>, cudaFuncAttributeMaxDynamicSharedMemorySize, SMEM_TC);
    cudaFuncSetAttribute(mma_gemm<1, 3>, cudaFuncAttributeMaxDynamicSharedMemorySize, SMEM_TC);
    cudaFuncSetAttribute(mma_gemm<4, 3>, cudaFuncAttributeMaxDynamicSharedMemorySize, SMEM_TC);
    cudaFuncSetAttribute(mma_gemm<4, 2>, cudaFuncAttributeMaxDynamicSharedMemorySize, SMEM_TC);
    cudaFuncSetAttribute(mma_attn<0>, cudaFuncAttributeMaxDynamicSharedMemorySize, SMEM_AT);
    cudaFuncSetAttribute(mma_attn<1>, cudaFuncAttributeMaxDynamicSharedMemorySize, SMEM_AT);

    void *pxh, *pxl, *phnh, *phnl, *pth, *ptl, *pwfh, *pwfl;
    void *pqf, *pkf, *pvf, *psf, *ph, *plast, *plt;
    cudaGetSymbolAddress(&pxh, g_xh);   cudaGetSymbolAddress(&pxl, g_xl);
    cudaGetSymbolAddress(&phnh, g_hnh); cudaGetSymbolAddress(&phnl, g_hnl);
    cudaGetSymbolAddress(&pth, g_th);   cudaGetSymbolAddress(&ptl, g_tl);
    cudaGetSymbolAddress(&pwfh, g_wfh); cudaGetSymbolAddress(&pwfl, g_wfl);
    cudaGetSymbolAddress(&pqf, g_qf);   cudaGetSymbolAddress(&pkf, g_kf);
    cudaGetSymbolAddress(&pvf, g_vf);   cudaGetSymbolAddress(&psf, g_sf);
    cudaGetSymbolAddress(&ph, g_h);
    cudaGetSymbolAddress(&plast, g_last); cudaGetSymbolAddress(&plt, g_lt);
    __half* xh = (__half*)pxh;   __half* xl = (__half*)pxl;
    __half* hnh = (__half*)phnh; __half* hnl = (__half*)phnl;
    __half* th = (__half*)pth;   __half* tl = (__half*)ptl;
    __half* wfh = (__half*)pwfh; __half* wfl = (__half*)pwfl;
    __half* qf = (__half*)pqf;   __half* kf = (__half*)pkf;
    __half* vf = (__half*)pvf;   __half* sf = (__half*)psf;
    float* h = (float*)ph;
    float* last = (float*)plast; float* lt = (float*)plt;

    const float scale = 0.044194173824159216f;  // 1/sqrt(512)

    gather_split<<<MTOT * 128 / 256, 256>>>(seq, feats, emb);
    convw_all<<<dim3(WMAT / 4 / 256, 8), 256>>>(Wq, Wk, Wv, W1, W2);

    const dim3 gqkv(MTOT / 128, 1536 / 128);        // 128 x 12
    const dim3 gw(MTOT / 128, DMODEL / 128);        // 128 x 4
    const dim3 gs(SEQ / 64, SEQ / 128, NBATCH);     // 32 x 16 x 8
    const dim3 ga(SEQ / 64, DMODEL / 128, NBATCH);  // 32 x 4 x 8

    for (int l = 0; l < 2; l++) {
        const int bo = l * DMODEL;
        const size_t mqkv = (size_t)(l ? 5 : 0) * WMAT;

        if (l == 0)
            mma_gemm<4, 3><<<gqkv, 512, SMEM_TC>>>(xh, xl, wfh + mqkv, wfl + mqkv,
                                                   bq + bo, bk + bo, bv + bo,
                                                   qf, nullptr, kf, vf);
        else
            mma_gemm<4, 2><<<gqkv, 512, SMEM_TC>>>(xh, xl, wfh + mqkv, wfl + mqkv,
                                                   bq + bo, bk + bo, bv + bo,
                                                   qf, nullptr, kf, vf);

        mma_attn<0><<<gs, 256, SMEM_AT>>>(qf, kf, sf, nullptr, DMODEL, DMODEL,
                                          (size_t)SEQ * DMODEL, (size_t)SEQ * DMODEL,
                                          (size_t)SEQ * SEQ, scale);
        mma_attn<1><<<ga, 256, SMEM_AT>>>(sf, vf, nullptr, h, SEQ, DMODEL,
                                          (size_t)SEQ * SEQ, (size_t)SEQ * DMODEL,
                                          (size_t)SEQ * DMODEL, 0.f);

        if (l == 0) {
            norm_fused<0><<<dim3(NBATCH, DMODEL / 32), dim3(32, 8)>>>(h);
            const size_t m1 = 3 * (size_t)WMAT, m2 = 4 * (size_t)WMAT;
            mma_gemm<1, 3><<<gw, 512, SMEM_TC>>>(hnh, hnl, wfh + m1, wfl + m1,
                                                 b1 + bo, nullptr, nullptr,
                                                 th, tl, nullptr, nullptr);
            mma_gemm<0, 3><<<gw, 512, SMEM_TC>>>(th, tl, wfh + m2, wfl + m2,
                                                 b2 + bo, nullptr, nullptr,
                                                 xh, xl, nullptr, nullptr);
        } else {
            norm_fused<1><<<dim3(NBATCH, DMODEL / 32), dim3(32, 8)>>>(h);
            small_gemm<true><<<16, 256>>>(last, W1 + (size_t)WMAT, b1 + bo, lt);
            small_gemm<false><<<16, 256>>>(lt, W2 + (size_t)WMAT, b2 + bo, out);
        }
    }
}

// round 15
// speedup vs baseline: 5.0342x; 1.0173x over previous
#include <cuda_runtime.h>
#include <cuda_fp16.h>
#include <math.h>
#include <stdint.h>

#define EMB_DIM 448
#define FEAT_DIM 64
#define DMODEL 512
#define NBATCH 8
#define SEQ 2048
#define MTOT (NBATCH * SEQ)
#define WMAT (DMODEL * DMODEL)

// -------- scratch (device globals) --------
static __device__ __half g_xh[MTOT * DMODEL], g_xl[MTOT * DMODEL];
static __device__ __half g_hnh[MTOT * DMODEL], g_hnl[MTOT * DMODEL];
static __device__ __half g_th[MTOT * DMODEL], g_tl[MTOT * DMODEL];
static __device__ __half g_wfh[8 * WMAT], g_wfl[8 * WMAT];  // fp16 hi/lo weights
static __device__ __half g_qf[MTOT * DMODEL], g_kf[MTOT * DMODEL];
static __device__ __half g_vf[MTOT * DMODEL];
static __device__ __half g_sf[(size_t)NBATCH * SEQ * SEQ];
static __device__ float g_h[MTOT * DMODEL];
static __device__ float g_last[NBATCH * DMODEL], g_lt[NBATCH * DMODEL];

__device__ __forceinline__ uint32_t smem_u32(const void* p) {
    uint32_t a;
    asm("{ .reg .u64 t; cvta.to.shared.u64 t, %1; cvt.u32.u64 %0, t; }" : "=r"(a) : "l"(p));
    return a;
}
#define SWZ(o) ((o) ^ ((((uint32_t)(o)) >> 3) & 0x70))
// projection GEMM stage: Ahi 16K | Alo 16K | Bhi 16K | Blo 16K
#define OFF_ALO 16384u
#define OFF_BHI 32768u
#define OFF_BLO 49152u
#define STAGE_B 65536u
#define SMEM_TC 196608
// attention stages (64x128 CTA): A 8K + B 16K = 24K/stage, 3 stages -> 72K (3 CTA/SM)
#define AT_OFF_B 8192u
#define AT_STAGE 24576u
#define SMEM_AT 73728

__device__ __forceinline__ void ldm_x4(uint32_t* r, uint32_t addr) {
    asm volatile("ldmatrix.sync.aligned.m8n8.x4.shared.b16 {%0,%1,%2,%3}, [%4];"
                 : "=r"(r[0]), "=r"(r[1]), "=r"(r[2]), "=r"(r[3]) : "r"(addr));
}
__device__ __forceinline__ void ldm_x4t(uint32_t* r, uint32_t addr) {
    asm volatile("ldmatrix.sync.aligned.m8n8.x4.trans.shared.b16 {%0,%1,%2,%3}, [%4];"
                 : "=r"(r[0]), "=r"(r[1]), "=r"(r[2]), "=r"(r[3]) : "r"(addr));
}
__device__ __forceinline__ void mma16816h(float* c, const uint32_t* a, const uint32_t* b) {
    asm volatile(
        "mma.sync.aligned.m16n8k16.row.col.f32.f16.f16.f32 "
        "{%0,%1,%2,%3}, {%4,%5,%6,%7}, {%8,%9}, {%0,%1,%2,%3};"
        : "+f"(c[0]), "+f"(c[1]), "+f"(c[2]), "+f"(c[3])
        : "r"(a[0]), "r"(a[1]), "r"(a[2]), "r"(a[3]), "r"(b[0]), "r"(b[1]));
}
__device__ __forceinline__ void cpa16(uint32_t dst, const void* src) {
    asm volatile("cp.async.cg.shared.global [%0], [%1], 16;" :: "r"(dst), "l"(src));
}
#define CPA_COMMIT() asm volatile("cp.async.commit_group;" ::: "memory")

__device__ __forceinline__ void split4h(float4 f, uint2& h, uint2& l) {
    __half2 h0 = __floats2half2_rn(f.x, f.y);
    __half2 h1 = __floats2half2_rn(f.z, f.w);
    __half2 l0 = __floats2half2_rn(f.x - __half2float(h0.x), f.y - __half2float(h0.y));
    __half2 l1 = __floats2half2_rn(f.z - __half2float(h1.x), f.w - __half2float(h1.y));
    h.x = *(uint32_t*)&h0; h.y = *(uint32_t*)&h1;
    l.x = *(uint32_t*)&l0; l.y = *(uint32_t*)&l1;
}

// ============ fp16 split projection/MLP GEMM (512 thr, CTA 128x128) ============
// MODE: 0=bias->hi/lo, 1=bias+relu->hi/lo, 4=fused QKV (Q,K,V all fp16)
// PASSES==3 with MODE==4: V region (bn>=8) runs only 2 passes (drops Ah*Wl).
template <int MODE, int PASSES>
__global__ void __launch_bounds__(512) mma_gemm(const __half* __restrict__ Ah, const __half* __restrict__ Al,
                                                const __half* __restrict__ Bh, const __half* __restrict__ Bl,
                                                const float* __restrict__ bias, const float* __restrict__ bias2,
                                                const float* __restrict__ bias3,
                                                __half* __restrict__ Ch, __half* __restrict__ Cl,
                                                __half* __restrict__ C2h, __half* __restrict__ C3h) {
    extern __shared__ char smem[];
    const int tid = threadIdx.x, wid = tid >> 5, lane = tid & 31;
    const int bm = blockIdx.x, bn = blockIdx.y;
    const bool third = (PASSES == 3) && !(MODE == 4 && bn >= 8);  // V region: 2-pass
    Ah += (size_t)bm * 128 * DMODEL;
    Al += (size_t)bm * 128 * DMODEL;
    Bh += (size_t)bn * 128 * DMODEL;
    Bl += (size_t)bn * 128 * DMODEL;
    const int NC = DMODEL >> 6;  // 8
    const uint32_t sb = smem_u32(smem);
    const int wm = wid >> 2, wn = wid & 3;  // warp grid 4x4, warp tile 32x32
    const int lr = lane & 15, lc16 = (lane >> 4) * 16;

    float acc[2][4][4];
#pragma unroll
    for (int i = 0; i < 2; i++)
#pragma unroll
        for (int j = 0; j < 4; j++)
#pragma unroll
            for (int r = 0; r < 4; r++) acc[i][j][r] = 0.f;

#define STAGE_LOAD(S, CIDX) do { \
        uint32_t base_ = sb + (uint32_t)(S) * STAGE_B; \
        int koff_ = (CIDX) * 64; \
        _Pragma("unroll") \
        for (int j_ = 0; j_ < 2; j_++) { \
            int cc_ = tid + j_ * 512; \
            int r_ = cc_ >> 3, cg_ = cc_ & 7; \
            uint32_t so_ = SWZ((uint32_t)r_ * 128u + (uint32_t)cg_ * 16u); \
            size_t g_ = (size_t)r_ * DMODEL + koff_ + cg_ * 8; \
            cpa16(base_ + so_, Ah + g_); \
            cpa16(base_ + OFF_ALO + so_, Al + g_); \
            cpa16(base_ + OFF_BHI + so_, Bh + g_); \
            if (PASSES == 3) { if (third) cpa16(base_ + OFF_BLO + so_, Bl + g_); } \
        } \
        CPA_COMMIT(); \
    } while (0)

    uint32_t ah[2][2][4], al[2][2][4], bhf[2][4][2], blf[2][4][2];
#define LDFRAG(BUF, KS) do { \
        const uint32_t kb_ = (KS) * 32 + lc16; \
        _Pragma("unroll") \
        for (int mb_ = 0; mb_ < 2; mb_++) { \
            uint32_t ro_ = (uint32_t)(wm * 32 + mb_ * 16 + lr) * 128u + kb_; \
            ldm_x4(ah[BUF][mb_], base + SWZ(ro_)); \
            ldm_x4(al[BUF][mb_], base + OFF_ALO + SWZ(ro_)); \
        } \
        _Pragma("unroll") \
        for (int n2_ = 0; n2_ < 2; n2_++) { \
            uint32_t ro_ = (uint32_t)(wn * 32 + n2_ * 16 + lr) * 128u + kb_; \
            uint32_t t_[4]; \
            ldm_x4(t_, base + OFF_BHI + SWZ(ro_)); \
            bhf[BUF][n2_ * 2][0] = t_[0]; bhf[BUF][n2_ * 2][1] = t_[2]; \
            bhf[BUF][n2_ * 2 + 1][0] = t_[1]; bhf[BUF][n2_ * 2 + 1][1] = t_[3]; \
            if (PASSES == 3) { if (third) { \
                ldm_x4(t_, base + OFF_BLO + SWZ(ro_)); \
                blf[BUF][n2_ * 2][0] = t_[0]; blf[BUF][n2_ * 2][1] = t_[2]; \
                blf[BUF][n2_ * 2 + 1][0] = t_[1]; blf[BUF][n2_ * 2 + 1][1] = t_[3]; \
            } } \
        } \
    } while (0)

    STAGE_LOAD(0, 0);
    STAGE_LOAD(1, 1);

    for (int c = 0; c < NC; c++) {
        if (c + 1 < NC) asm volatile("cp.async.wait_group 1;" ::: "memory");
        else            asm volatile("cp.async.wait_group 0;" ::: "memory");
        __syncthreads();
        const uint32_t base = sb + (uint32_t)(((uint32_t)c) % 3u) * STAGE_B;
        LDFRAG(0, 0);
#pragma unroll
        for (int ks = 0; ks < 4; ks++) {
            const int cur = ks & 1;
            if (ks < 3) LDFRAG(!(ks & 1), ks + 1);
#pragma unroll
            for (int mb = 0; mb < 2; mb++)
#pragma unroll
                for (int nb = 0; nb < 4; nb++)
                    mma16816h(acc[mb][nb], ah[cur][mb], bhf[cur][nb]);
#pragma unroll
            for (int mb = 0; mb < 2; mb++)
#pragma unroll
                for (int nb = 0; nb < 4; nb++)
                    mma16816h(acc[mb][nb], al[cur][mb], bhf[cur][nb]);
            if (PASSES == 3) {
                if (third) {
#pragma unroll
                    for (int mb = 0; mb < 2; mb++)
#pragma unroll
                        for (int nb = 0; nb < 4; nb++)
                            mma16816h(acc[mb][nb], ah[cur][mb], blf[cur][nb]);
                }
            }
        }
        if (c + 2 < NC) STAGE_LOAD(((uint32_t)(c + 2)) % 3u, c + 2);
    }
#undef STAGE_LOAD
#undef LDFRAG

    const int g = lane >> 2, t4 = lane & 3;
    const int region = (MODE == 4) ? (bn >> 2) : 0;
#pragma unroll
    for (int mb = 0; mb < 2; mb++) {
        const int mbase = bm * 128 + wm * 32 + mb * 16 + g;
#pragma unroll
        for (int nb = 0; nb < 4; nb++) {
            const int n0 = bn * 128 + wn * 32 + nb * 8 + t4 * 2;
#pragma unroll
            for (int rr = 0; rr < 2; rr++) {
                const int m = mbase + rr * 8;
                float v0 = acc[mb][nb][rr * 2], v1 = acc[mb][nb][rr * 2 + 1];
                if (MODE == 0) { v0 += bias[n0]; v1 += bias[n0 + 1]; }
                if (MODE == 1) { v0 = fmaxf(v0 + bias[n0], 0.f); v1 = fmaxf(v1 + bias[n0 + 1], 0.f); }
                if (MODE == 0 || MODE == 1) {
                    __half2 hv = __floats2half2_rn(v0, v1);
                    __half2 lv = __floats2half2_rn(v0 - __half2float(hv.x), v1 - __half2float(hv.y));
                    *(__half2*)(Ch + (size_t)m * DMODEL + n0) = hv;
                    *(__half2*)(Cl + (size_t)m * DMODEL + n0) = lv;
                } else {  // MODE 4: region 0=Q, 1=K, 2=V — all fp16
                    const int nl = n0 - (region << 9);
                    if (region == 0) {
                        *(__half2*)(Ch + (size_t)m * DMODEL + nl) =
                            __floats2half2_rn(v0 + bias[nl], v1 + bias[nl + 1]);
                    } else if (region == 1) {
                        *(__half2*)(C2h + (size_t)m * DMODEL + nl) =
                            __floats2half2_rn(v0 + bias2[nl], v1 + bias2[nl + 1]);
                    } else {
                        *(__half2*)(C3h + (size_t)m * DMODEL + nl) =
                            __floats2half2_rn(v0 + bias3[nl], v1 + bias3[nl + 1]);
                    }
                }
            }
        }
    }
}

// ============ fp16 attention GEMM (CTA 64x128, 256 thr, 3 CTA/SM) ============
// MODE 0: scores = tril(QK^T)*scale -> fp16 ; B = K rows (K-major)
// MODE 1: h = S @ V -> fp32, causal K bound; B = V [s][d] via ldmatrix.trans
template <int MODE>
__global__ void __launch_bounds__(256, 3) mma_attn(const __half* __restrict__ A, const __half* __restrict__ B,
                                                   __half* __restrict__ Sout, float* __restrict__ Hout,
                                                   int lda, int ldb,
                                                   size_t sA, size_t sB, size_t sC, float scale) {
    extern __shared__ char smem[];
    const int tid = threadIdx.x, wid = tid >> 5, lane = tid & 31;
    const int bm = gridDim.x - 1 - blockIdx.x;  // heavy tiles dispatched first
    const int bn = blockIdx.y, bz = blockIdx.z;
    if (MODE == 0 && 2 * bn > bm) return;  // fully-masked 64x128 tile
    A += sA * bz + (size_t)bm * 64 * lda;
    if (MODE == 0) B += sB * bz + (size_t)bn * 128 * ldb;
    else           B += sB * bz + (size_t)bn * 128;
    const int NC = (MODE == 1) ? (bm + 1) : 8;
    const uint32_t sb = smem_u32(smem);
    const int wm = wid >> 2, wn = wid & 3;  // 2m x 4n
    const int lr = lane & 15, lc16 = (lane >> 4) * 16;

    float acc[2][4][4];
#pragma unroll
    for (int i = 0; i < 2; i++)
#pragma unroll
        for (int j = 0; j < 4; j++)
#pragma unroll
            for (int r = 0; r < 4; r++) acc[i][j][r] = 0.f;

#define AT_LOAD(S, CIDX) do { \
        uint32_t base_ = sb + (uint32_t)(S) * AT_STAGE; \
        int koff_ = (CIDX) * 64; \
        _Pragma("unroll") \
        for (int j_ = 0; j_ < 2; j_++) { \
            int cc_ = tid + j_ * 256; \
            int r_ = cc_ >> 3, cg_ = cc_ & 7; \
            cpa16(base_ + SWZ((uint32_t)r_ * 128u + (uint32_t)cg_ * 16u), \
                  A + (size_t)r_ * lda + koff_ + cg_ * 8); \
        } \
        _Pragma("unroll") \
        for (int j_ = 0; j_ < 4; j_++) { \
            int cc_ = tid + j_ * 256; \
            if (MODE == 0) { \
                int r_ = cc_ >> 3, cg_ = cc_ & 7; \
                cpa16(base_ + AT_OFF_B + SWZ((uint32_t)r_ * 128u + (uint32_t)cg_ * 16u), \
                      B + (size_t)r_ * ldb + koff_ + cg_ * 8); \
            } else { \
                int r_ = cc_ >> 4, sub_ = (cc_ >> 3) & 1, cg_ = cc_ & 7; \
                cpa16(base_ + AT_OFF_B + (uint32_t)sub_ * 8192u + \
                          SWZ((uint32_t)r_ * 128u + (uint32_t)cg_ * 16u), \
                      B + (size_t)(koff_ + r_) * DMODEL + sub_ * 64 + cg_ * 8); \
            } \
        } \
        CPA_COMMIT(); \
    } while (0)

    AT_LOAD(0, 0);
    if (NC > 1) AT_LOAD(1, 1);

    for (int c = 0; c < NC; c++) {
        if (c + 1 < NC) asm volatile("cp.async.wait_group 1;" ::: "memory");
        else            asm volatile("cp.async.wait_group 0;" ::: "memory");
        __syncthreads();
        const uint32_t base = sb + (uint32_t)(((uint32_t)c) % 3u) * AT_STAGE;
#pragma unroll
        for (int ks = 0; ks < 4; ks++) {
            const uint32_t kb = ks * 32 + lc16;
            uint32_t ah[2][4], bh[4][2];
#pragma unroll
            for (int mb = 0; mb < 2; mb++) {
                uint32_t ro = (uint32_t)(wm * 32 + mb * 16 + lr) * 128u + kb;
                ldm_x4(ah[mb], base + SWZ(ro));
            }
#pragma unroll
            for (int n2 = 0; n2 < 2; n2++) {
                uint32_t t[4];
                if (MODE == 0) {
                    uint32_t ro = (uint32_t)(wn * 32 + n2 * 16 + lr) * 128u + kb;
                    ldm_x4(t, base + AT_OFF_B + SWZ(ro));
                    bh[n2 * 2][0] = t[0]; bh[n2 * 2][1] = t[2];
                    bh[n2 * 2 + 1][0] = t[1]; bh[n2 * 2 + 1][1] = t[3];
                } else {
                    int d_loc = wn * 32 + n2 * 16 + ((lane >> 4) << 3);
                    uint32_t row = (uint32_t)(ks * 16 + (lane & 15));
                    uint32_t addr = base + AT_OFF_B + ((uint32_t)(d_loc >> 6)) * 8192u +
                                    SWZ(row * 128u + (uint32_t)(d_loc & 63) * 2u);
                    ldm_x4t(t, addr);
                    bh[n2 * 2][0] = t[0]; bh[n2 * 2][1] = t[1];
                    bh[n2 * 2 + 1][0] = t[2]; bh[n2 * 2 + 1][1] = t[3];
                }
            }
#pragma unroll
            for (int mb = 0; mb < 2; mb++)
#pragma unroll
                for (int nb = 0; nb < 4; nb++)
                    mma16816h(acc[mb][nb], ah[mb], bh[nb]);
        }
        if (c + 2 < NC) AT_LOAD(((uint32_t)(c + 2)) % 3u, c + 2);
    }
#undef AT_LOAD

    const int g = lane >> 2, t4 = lane & 3;
    if (MODE == 0) Sout += sC * bz;
    else           Hout += sC * bz;
#pragma unroll
    for (int mb = 0; mb < 2; mb++) {
        const int mbase = bm * 64 + wm * 32 + mb * 16 + g;
#pragma unroll
        for (int nb = 0; nb < 4; nb++) {
            const int n0 = bn * 128 + wn * 32 + nb * 8 + t4 * 2;
#pragma unroll
            for (int rr = 0; rr < 2; rr++) {
                const int m = mbase + rr * 8;
                float v0 = acc[mb][nb][rr * 2], v1 = acc[mb][nb][rr * 2 + 1];
                if (MODE == 0) {
                    v0 = (n0 <= m) ? v0 * scale : 0.f;
                    v1 = (n0 + 1 <= m) ? v1 * scale : 0.f;
                    *(__half2*)(Sout + (size_t)m * SEQ + n0) = __floats2half2_rn(v0, v1);
                } else {
                    *(float2*)(Hout + (size_t)m * DMODEL + n0) = make_float2(v0, v1);
                }
            }
        }
    }
}

// ---------------- fused gather + weight split (one launch) ----------------
__global__ __launch_bounds__(256) void prep_all(const int* __restrict__ seq,
                                                const float* __restrict__ feats,
                                                const float* __restrict__ emb,
                                                const float* __restrict__ Wq,
                                                const float* __restrict__ Wk,
                                                const float* __restrict__ Wv,
                                                const float* __restrict__ W1,
                                                const float* __restrict__ W2) {
    int bx = blockIdx.x;
    if (bx < MTOT * 128 / 256) {  // gather+split x
        int i = bx * 256 + threadIdx.x;
        int row = i >> 7, d = (i & 127) << 2;
        float4 val;
        if (d < EMB_DIM) val = *(const float4*)(emb + (size_t)seq[row] * EMB_DIM + d);
        else val = *(const float4*)(feats + (size_t)row * FEAT_DIM + (d - EMB_DIM));
        uint2 h, l;
        split4h(val, h, l);
        *(uint2*)(g_xh + ((size_t)row << 9) + d) = h;
        *(uint2*)(g_xl + ((size_t)row << 9) + d) = l;
    } else {  // weight split: 8 matrices x 256 blocks
        int wb = bx - MTOT * 128 / 256;
        int midx = wb >> 8;            // 0..7
        int blk = wb & 255;
        const float* src;
        switch (midx) {
            case 0: src = Wq; break;
            case 1: src = Wk; break;
            case 2: src = Wv; break;
            case 3: src = W1; break;
            case 4: src = W2; break;
            case 5: src = Wq + WMAT; break;
            case 6: src = Wk + WMAT; break;
            default: src = Wv + WMAT; break;
        }
        int i = (blk * 256 + threadIdx.x) << 2;
        float4 f = *(const float4*)(src + i);
        uint2 h, l;
        split4h(f, h, l);
        *(uint2*)(g_wfh + (size_t)midx * WMAT + i) = h;
        *(uint2*)(g_wfl + (size_t)midx * WMAT + i) = l;
    }
}

// fused stats + normalize. LAST=1: only emit last row into g_last
template <int LAST>
__global__ void norm_fused(const float* __restrict__ H) {
    const int b = blockIdx.x, tx = threadIdx.x, ty = threadIdx.y;
    const int d = blockIdx.y * 32 + tx;
    float sum = 0.f, sq = 0.f;
    for (int s = ty; s < SEQ; s += 8) {
        float v = H[(size_t)(b * SEQ + s) * DMODEL + d];
        sum += v; sq += v * v;
    }
    __shared__ float ss[8][32], s2[8][32], smean[32], srstd[32];
    ss[ty][tx] = sum; s2[ty][tx] = sq;
    __syncthreads();
    if (ty == 0) {
#pragma unroll
        for (int r = 1; r < 8; r++) { sum += ss[r][tx]; sq += s2[r][tx]; }
        float mean = sum * (1.0f / SEQ);
        float var = fmaxf((sq - sum * mean) * (1.0f / (SEQ - 1)), 0.0f);
        smean[tx] = mean;
        srstd[tx] = 1.0f / (sqrtf(var) + 2e-5f);
    }
    __syncthreads();
    const float mean = smean[tx], rstd = srstd[tx];
    if (LAST) {
        if (ty == 7) {
            float v = H[(size_t)(b * SEQ + SEQ - 1) * DMODEL + d];
            g_last[b * DMODEL + d] = (v - mean) * rstd;
        }
    } else {
        for (int s = ty; s < SEQ; s += 8) {
            float v = (H[(size_t)(b * SEQ + s) * DMODEL + d] - mean) * rstd;
            __half h = __float2half(v);
            __half l = __float2half(v - __half2float(h));
            g_hnh[(size_t)(b * SEQ + s) * DMODEL + d] = h;
            g_hnl[(size_t)(b * SEQ + s) * DMODEL + d] = l;
        }
    }
}

template <bool RELU>
__global__ void small_gemm(const float* __restrict__ A, const float* __restrict__ W,
                           const float* __restrict__ bias, float* __restrict__ C) {
    int i = blockIdx.x * 256 + threadIdx.x;  // 4096
    int m = i >> 9, n = i & 511;
    const float* a = A + (size_t)m * DMODEL;
    const float* w = W + (size_t)n * DMODEL;
    float s = 0.f;
#pragma unroll 8
    for (int k2 = 0; k2 < DMODEL; k2 += 4) {
        float4 av = *(const float4*)(a + k2), wv = *(const float4*)(w + k2);
        s += av.x * wv.x + av.y * wv.y + av.z * wv.z + av.w * wv.w;
    }
    s += bias[n];
    if (RELU) s = fmaxf(s, 0.0f);
    C[i] = s;
}

extern "C" void kernel_launch(void* const* d_in, const int* in_sizes, int n_in,
                              void* d_out, int out_size) {
    const int* seq = (const int*)d_in[0];
    const float* feats = (const float*)d_in[1];
    const float* emb = (const float*)d_in[2];
    const float* Wq = (const float*)d_in[3];  const float* bq = (const float*)d_in[4];
    const float* Wk = (const float*)d_in[5];  const float* bk = (const float*)d_in[6];
    const float* Wv = (const float*)d_in[7];  const float* bv = (const float*)d_in[8];
    const float* W1 = (const float*)d_in[9];  const float* b1 = (const float*)d_in[10];
    const float* W2 = (const float*)d_in[11]; const float* b2 = (const float*)d_in[12];
    float* out = (float*)d_out;

    cudaFuncSetAttribute(mma_gemm<0, 3>, cudaFuncAttributeMaxDynamicSharedMemorySize, SMEM_TC);
    cudaFuncSetAttribute(mma_gemm<1, 3>, cudaFuncAttributeMaxDynamicSharedMemorySize, SMEM_TC);
    cudaFuncSetAttribute(mma_gemm<4, 3>, cudaFuncAttributeMaxDynamicSharedMemorySize, SMEM_TC);
    cudaFuncSetAttribute(mma_gemm<4, 2>, cudaFuncAttributeMaxDynamicSharedMemorySize, SMEM_TC);
    cudaFuncSetAttribute(mma_attn<0>, cudaFuncAttributeMaxDynamicSharedMemorySize, SMEM_AT);
    cudaFuncSetAttribute(mma_attn<1>, cudaFuncAttributeMaxDynamicSharedMemorySize, SMEM_AT);

    void *pxh, *pxl, *phnh, *phnl, *pth, *ptl, *pwfh, *pwfl;
    void *pqf, *pkf, *pvf, *psf, *ph, *plast, *plt;
    cudaGetSymbolAddress(&pxh, g_xh);   cudaGetSymbolAddress(&pxl, g_xl);
    cudaGetSymbolAddress(&phnh, g_hnh); cudaGetSymbolAddress(&phnl, g_hnl);
    cudaGetSymbolAddress(&pth, g_th);   cudaGetSymbolAddress(&ptl, g_tl);
    cudaGetSymbolAddress(&pwfh, g_wfh); cudaGetSymbolAddress(&pwfl, g_wfl);
    cudaGetSymbolAddress(&pqf, g_qf);   cudaGetSymbolAddress(&pkf, g_kf);
    cudaGetSymbolAddress(&pvf, g_vf);   cudaGetSymbolAddress(&psf, g_sf);
    cudaGetSymbolAddress(&ph, g_h);
    cudaGetSymbolAddress(&plast, g_last); cudaGetSymbolAddress(&plt, g_lt);
    __half* xh = (__half*)pxh;   __half* xl = (__half*)pxl;
    __half* hnh = (__half*)phnh; __half* hnl = (__half*)phnl;
    __half* th = (__half*)pth;   __half* tl = (__half*)ptl;
    __half* wfh = (__half*)pwfh; __half* wfl = (__half*)pwfl;
    __half* qf = (__half*)pqf;   __half* kf = (__half*)pkf;
    __half* vf = (__half*)pvf;   __half* sf = (__half*)psf;
    float* h = (float*)ph;
    float* last = (float*)plast; float* lt = (float*)plt;

    const float scale = 0.044194173824159216f;  // 1/sqrt(512)

    prep_all<<<MTOT * 128 / 256 + 8 * 256, 256>>>(seq, feats, emb, Wq, Wk, Wv, W1, W2);

    const dim3 gqkv(MTOT / 128, 1536 / 128);        // 128 x 12
    const dim3 gw(MTOT / 128, DMODEL / 128);        // 128 x 4
    const dim3 gs(SEQ / 64, SEQ / 128, NBATCH);     // 32 x 16 x 8
    const dim3 ga(SEQ / 64, DMODEL / 128, NBATCH);  // 32 x 4 x 8

    for (int l = 0; l < 2; l++) {
        const int bo = l * DMODEL;
        const size_t mqkv = (size_t)(l ? 5 : 0) * WMAT;

        if (l == 0)
            mma_gemm<4, 3><<<gqkv, 512, SMEM_TC>>>(xh, xl, wfh + mqkv, wfl + mqkv,
                                                   bq + bo, bk + bo, bv + bo,
                                                   qf, nullptr, kf, vf);
        else
            mma_gemm<4, 2><<<gqkv, 512, SMEM_TC>>>(xh, xl, wfh + mqkv, wfl + mqkv,
                                                   bq + bo, bk + bo, bv + bo,
                                                   qf, nullptr, kf, vf);

        mma_attn<0><<<gs, 256, SMEM_AT>>>(qf, kf, sf, nullptr, DMODEL, DMODEL,
                                          (size_t)SEQ * DMODEL, (size_t)SEQ * DMODEL,
                                          (size_t)SEQ * SEQ, scale);
        mma_attn<1><<<ga, 256, SMEM_AT>>>(sf, vf, nullptr, h, SEQ, DMODEL,
                                          (size_t)SEQ * SEQ, (size_t)SEQ * DMODEL,
                                          (size_t)SEQ * DMODEL, 0.f);

        if (l == 0) {
            norm_fused<0><<<dim3(NBATCH, DMODEL / 32), dim3(32, 8)>>>(h);
            const size_t m1 = 3 * (size_t)WMAT, m2 = 4 * (size_t)WMAT;
            mma_gemm<1, 3><<<gw, 512, SMEM_TC>>>(hnh, hnl, wfh + m1, wfl + m1,
                                                 b1 + bo, nullptr, nullptr,
                                                 th, tl, nullptr, nullptr);
            mma_gemm<0, 3><<<gw, 512, SMEM_TC>>>(th, tl, wfh + m2, wfl + m2,
                                                 b2 + bo, nullptr, nullptr,
                                                 xh, xl, nullptr, nullptr);
        } else {
            norm_fused<1><<<dim3(NBATCH, DMODEL / 32), dim3(32, 8)>>>(h);
            small_gemm<true><<<16, 256>>>(last, W1 + (size_t)WMAT, b1 + bo, lt);
            small_gemm<false><<<16, 256>>>(lt, W2 + (size_t)WMAT, b2 + bo, out);
        }
    }
}